// round 12
// baseline (speedup 1.0000x reference)
#include <cuda_runtime.h>
#include <cuda_bf16.h>
#include <math.h>
#include <stdint.h>

// ---------------- problem constants ----------------
#define BB   8
#define CC   256
#define LL   512
#define NG   32
#define CPG  8
#define NH   8
#define DH   32
#define EE   1024
#define HIDD 32
#define CAPP 4
#define NTOK 256
#define DTOK 512
#define QKVSZ (BB*NH*LL*DH)   // 1048576

// ---------------- scratch (device globals; allocation-free) ----------------
__device__ float g_x1[BB*CC*LL];
__device__ float g_r [BB*CC*LL];
__device__ float g_xa[BB*CC*LL];
__device__ float g_qkv[3*QKVSZ];
__device__ float g_xb[BB*CC*LL];
__device__ float g_xm[BB*CC*LL];
__device__ float g_logits[BB*NTOK*EE];
__device__ float g_raw  [BB*NTOK*EE];
__device__ float g_gate1[BB*NTOK];
__device__ float g_gate2[BB*NTOK];
__device__ int   g_i1[BB*NTOK];
__device__ int   g_i2[BB*NTOK];
__device__ float g_rawsum[BB*EE];
__device__ float g_cnt1 [BB*EE];
__device__ int   g_slot_tok [BB*EE*CAPP];
__device__ float g_slot_gate[BB*EE*CAPP];
__device__ float g_moeout[BB*CC*LL];
__device__ float g_yfull[(size_t)BB*2*CC*LL];
// bf16 hi/lo operand buffers
#define WSZ 196608
#define OFF_WQKVT (6*WSZ)
#define OFF_W2T   (OFF_WQKVT + 196608)
#define OFF_WGT   (OFF_W2T + 65536)
#define WTOT      (OFF_WGT + 524288)
__device__ unsigned short g_whi[WTOT];
__device__ unsigned short g_wlo[WTOT];
__device__ unsigned short g_hhi[BB*CC*LL];
__device__ unsigned short g_hlo[BB*CC*LL];
__device__ unsigned short g_xmh[BB*CC*LL];   // conv2 bf16 hi output (no aliasing!)
__device__ unsigned short g_xml[BB*CC*LL];   // conv2 bf16 lo output

__device__ __forceinline__ float gelu_exact(float v) {
    return 0.5f * v * (1.0f + erff(v * 0.7071067811865476f));
}
__device__ __forceinline__ void split_bf16(float v, unsigned short& h, unsigned short& l) {
    __nv_bfloat16 hb = __float2bfloat16(v);
    __nv_bfloat16 lb = __float2bfloat16(v - __bfloat162float(hb));
    h = *(unsigned short*)&hb;
    l = *(unsigned short*)&lb;
}

// ---------------- float -> bf16 hi/lo conversion ----------------
__global__ void cvt_hilo_kernel(const float* __restrict__ src, unsigned short* __restrict__ hi,
                                unsigned short* __restrict__ lo, int n) {
    int i = blockIdx.x * 256 + threadIdx.x;
    if (i < n) {
        unsigned short h, l;
        split_bf16(src[i], h, l);
        hi[i] = h; lo[i] = l;
    }
}

// ---------------- transposed weight cvt: W[K][N] -> Bt[N][K] bf16 hi/lo ----------------
__global__ void cvtT_w_kernel(const float* __restrict__ W, unsigned short* __restrict__ bhi,
                              unsigned short* __restrict__ blo, int K, int N) {
    __shared__ float tile[32][33];
    int k0 = blockIdx.x * 32, n0 = blockIdx.y * 32;
    int x = threadIdx.x, y = threadIdx.y;
#pragma unroll
    for (int i = 0; i < 32; i += 8)
        tile[y + i][x] = W[(size_t)(k0 + y + i) * N + n0 + x];
    __syncthreads();
#pragma unroll
    for (int i = 0; i < 32; i += 8) {
        float v = tile[x][y + i];
        unsigned short h, l;
        split_bf16(v, h, l);
        size_t o = (size_t)(n0 + y + i) * K + k0 + x;
        bhi[o] = h; blo[o] = l;
    }
}

// ---------------- transposed activation cvt: xa(B,C,L) -> A[(b*L+l)][C] hi/lo ----------------
__global__ void cvtT_x_kernel(const float* __restrict__ X, unsigned short* __restrict__ ahi,
                              unsigned short* __restrict__ alo) {
    __shared__ float tile[32][33];
    int b = blockIdx.z;
    int l0 = blockIdx.x * 32, c0 = blockIdx.y * 32;
    int x = threadIdx.x, y = threadIdx.y;
#pragma unroll
    for (int i = 0; i < 32; i += 8)
        tile[y + i][x] = X[(((size_t)(b * CC + c0 + y + i)) << 9) + l0 + x];
    __syncthreads();
#pragma unroll
    for (int i = 0; i < 32; i += 8) {
        float v = tile[x][y + i];
        unsigned short h, l;
        split_bf16(v, h, l);
        size_t o = (size_t)(b * LL + l0 + y + i) * CC + c0 + x;
        ahi[o] = h; alo[o] = l;
    }
}

// ================= warp-level bf16 MMA (m16n8k16, f32 accum) =================
__device__ __forceinline__ void mma16816(float* c, const uint32_t* a, const uint32_t* b) {
    asm volatile("mma.sync.aligned.m16n8k16.row.col.f32.bf16.bf16.f32 "
        "{%0,%1,%2,%3}, {%4,%5,%6,%7}, {%8,%9}, {%0,%1,%2,%3};"
        : "+f"(c[0]), "+f"(c[1]), "+f"(c[2]), "+f"(c[3])
        : "r"(a[0]), "r"(a[1]), "r"(a[2]), "r"(a[3]), "r"(b[0]), "r"(b[1]));
}

#define CPITCH 72
#define OFF_AHI 0
#define OFF_ALO (64*CPITCH)
#define OFF_BHI (2*64*CPITCH)
#define OFF_BLO (2*64*CPITCH + 128*CPITCH)
#define MMA_SMEM ((2*64*CPITCH + 2*128*CPITCH) * 2)   // 55296 bytes

// ================= tensor-core conv1d(k=3,pad=1), optional bf16 hi/lo out =================
__global__ void __launch_bounds__(256, 2)
conv_mma_kernel(const unsigned short* __restrict__ Whi, const unsigned short* __restrict__ Wlo,
                const unsigned short* __restrict__ Xhi, const unsigned short* __restrict__ Xlo,
                const float* __restrict__ bias, const float* __restrict__ res,
                float* __restrict__ Y, unsigned short* __restrict__ Yhi,
                unsigned short* __restrict__ Ylo, int M) {
    extern __shared__ unsigned short sm[];
    int tid = threadIdx.x;
    int wid = tid >> 5, lane = tid & 31;
    int g = lane >> 2, tg = lane & 3;
    int warp_m = wid & 1, warp_n = wid >> 1;
    int n0 = blockIdx.x * 128, m0 = blockIdx.y * 64;
    int bI = n0 >> 9, l0 = n0 & 511;

    const unsigned short* Wh = Whi + (size_t)m0 * 768;
    const unsigned short* Wl = Wlo + (size_t)m0 * 768;
    const unsigned short* Xh = Xhi + (((size_t)bI * CC) << 9);
    const unsigned short* Xl = Xlo + (((size_t)bI * CC) << 9);

    float acc[2][4][4];
#pragma unroll
    for (int mi = 0; mi < 2; mi++)
#pragma unroll
        for (int ni = 0; ni < 4; ni++)
#pragma unroll
            for (int r = 0; r < 4; r++) acc[mi][ni][r] = 0.f;

    int fa_m = tid >> 2, fa_k = (tid & 3) * 16;
    int fb_n = tid >> 1, fb_h = (tid & 1) * 32;

    for (int c = 0; c < 12; c++) {
        int c64 = c * 64;
        {
            const unsigned short* ph = Wh + (size_t)fa_m * 768 + c64 + fa_k;
            const unsigned short* pl = Wl + (size_t)fa_m * 768 + c64 + fa_k;
            *(uint4*)&sm[OFF_AHI + fa_m * CPITCH + fa_k]     = *(const uint4*)ph;
            *(uint4*)&sm[OFF_AHI + fa_m * CPITCH + fa_k + 8] = *(const uint4*)(ph + 8);
            *(uint4*)&sm[OFF_ALO + fa_m * CPITCH + fa_k]     = *(const uint4*)pl;
            *(uint4*)&sm[OFF_ALO + fa_m * CPITCH + fa_k + 8] = *(const uint4*)(pl + 8);
        }
        {
            int kg = c64 + fb_h;
            int ic = kg / 3, t = kg - 3 * ic;
            int l = l0 + fb_n;
            unsigned short* dh = &sm[OFF_BHI + fb_n * CPITCH + fb_h];
            unsigned short* dl = &sm[OFF_BLO + fb_n * CPITCH + fb_h];
#pragma unroll 8
            for (int i = 0; i < 32; i++) {
                int ll = l + t - 1;
                bool ok = ((unsigned)ll < 512u);
                int src = (ic << 9) + ll;
                dh[i] = ok ? Xh[src] : (unsigned short)0;
                dl[i] = ok ? Xl[src] : (unsigned short)0;
                if (++t == 3) { t = 0; ++ic; }
            }
        }
        __syncthreads();
#pragma unroll
        for (int ks = 0; ks < 4; ks++) {
            int k0 = ks * 16;
            uint32_t ahi[2][4], alo[2][4], bhi[4][2], blo[4][2];
#pragma unroll
            for (int mi = 0; mi < 2; mi++) {
                int r0 = warp_m * 32 + mi * 16 + g;
                const unsigned short* p0 = &sm[OFF_AHI + r0 * CPITCH + k0 + tg * 2];
                const unsigned short* p1 = p0 + 8 * CPITCH;
                ahi[mi][0] = *(const uint32_t*)p0;
                ahi[mi][1] = *(const uint32_t*)p1;
                ahi[mi][2] = *(const uint32_t*)(p0 + 8);
                ahi[mi][3] = *(const uint32_t*)(p1 + 8);
                const unsigned short* q0 = &sm[OFF_ALO + r0 * CPITCH + k0 + tg * 2];
                const unsigned short* q1 = q0 + 8 * CPITCH;
                alo[mi][0] = *(const uint32_t*)q0;
                alo[mi][1] = *(const uint32_t*)q1;
                alo[mi][2] = *(const uint32_t*)(q0 + 8);
                alo[mi][3] = *(const uint32_t*)(q1 + 8);
            }
#pragma unroll
            for (int ni = 0; ni < 4; ni++) {
                int nr = warp_n * 32 + ni * 8 + g;
                const unsigned short* p = &sm[OFF_BHI + nr * CPITCH + k0 + tg * 2];
                bhi[ni][0] = *(const uint32_t*)p;
                bhi[ni][1] = *(const uint32_t*)(p + 8);
                const unsigned short* q = &sm[OFF_BLO + nr * CPITCH + k0 + tg * 2];
                blo[ni][0] = *(const uint32_t*)q;
                blo[ni][1] = *(const uint32_t*)(q + 8);
            }
#pragma unroll
            for (int mi = 0; mi < 2; mi++)
#pragma unroll
                for (int ni = 0; ni < 4; ni++) {
                    mma16816(acc[mi][ni], ahi[mi], bhi[ni]);
                    mma16816(acc[mi][ni], ahi[mi], blo[ni]);
                    mma16816(acc[mi][ni], alo[mi], bhi[ni]);
                }
        }
        __syncthreads();
    }

#pragma unroll
    for (int mi = 0; mi < 2; mi++) {
        int m = m0 + warp_m * 32 + mi * 16 + g;
        float bs0 = bias[m], bs1 = bias[m + 8];
        size_t row0 = (((size_t)bI * M + m) << 9) + l0;
        size_t row1 = (((size_t)bI * M + m + 8) << 9) + l0;
#pragma unroll
        for (int ni = 0; ni < 4; ni++) {
            int ncol = warp_n * 32 + ni * 8 + tg * 2;
            float2 v0 = make_float2(acc[mi][ni][0] + bs0, acc[mi][ni][1] + bs0);
            float2 v1 = make_float2(acc[mi][ni][2] + bs1, acc[mi][ni][3] + bs1);
            if (res) {
                float2 r0 = *(const float2*)&res[row0 + ncol];
                float2 r1 = *(const float2*)&res[row1 + ncol];
                v0.x += r0.x; v0.y += r0.y; v1.x += r1.x; v1.y += r1.y;
            }
            *(float2*)&Y[row0 + ncol] = v0;
            *(float2*)&Y[row1 + ncol] = v1;
            if (Yhi) {
                unsigned short h, l;
                split_bf16(v0.x, h, l); Yhi[row0 + ncol]     = h; Ylo[row0 + ncol]     = l;
                split_bf16(v0.y, h, l); Yhi[row0 + ncol + 1] = h; Ylo[row0 + ncol + 1] = l;
                split_bf16(v1.x, h, l); Yhi[row1 + ncol]     = h; Ylo[row1 + ncol]     = l;
                split_bf16(v1.y, h, l); Yhi[row1 + ncol + 1] = h; Ylo[row1 + ncol + 1] = l;
            }
        }
    }
}

// ================= generic tensor-core GEMM: C[M,N] = A[M,K] @ Bt[N,K]^T =================
// CM: 0 = row-major C; 2 = CTRANS; 3 = QKV epilogue (writes Q/K/V at C, C+QKVSZ, C+2*QKVSZ)
template<int CM, int NT>
__global__ void __launch_bounds__(256, 2)
gemm_mma(const unsigned short* __restrict__ Ahi, const unsigned short* __restrict__ Alo,
         const unsigned short* __restrict__ Bthi, const unsigned short* __restrict__ Btlo,
         const float* __restrict__ bias, float* __restrict__ C, int M, int N, int K) {
    extern __shared__ unsigned short sm[];
    int tid = threadIdx.x;
    int wid = tid >> 5, lane = tid & 31;
    int g = lane >> 2, tg = lane & 3;
    int warp_m = wid & 1, warp_n = wid >> 1;
    int n0 = blockIdx.x * 128, m0 = blockIdx.y * 64;

    const unsigned short* Ah = Ahi + (size_t)m0 * K;
    const unsigned short* Al = Alo + (size_t)m0 * K;
    const unsigned short* Bh = Bthi + (size_t)n0 * K;
    const unsigned short* Bl = Btlo + (size_t)n0 * K;

    float acc[2][4][4];
#pragma unroll
    for (int mi = 0; mi < 2; mi++)
#pragma unroll
        for (int ni = 0; ni < 4; ni++)
#pragma unroll
            for (int r = 0; r < 4; r++) acc[mi][ni][r] = 0.f;

    int fa_m = tid >> 2, fa_k = (tid & 3) * 16;
    int fb_n = tid >> 1, fb_h = (tid & 1) * 32;
    int nchunks = K >> 6;

    for (int c = 0; c < nchunks; c++) {
        int c64 = c << 6;
        {
            const unsigned short* ph = Ah + (size_t)fa_m * K + c64 + fa_k;
            const unsigned short* pl = Al + (size_t)fa_m * K + c64 + fa_k;
            *(uint4*)&sm[OFF_AHI + fa_m * CPITCH + fa_k]     = *(const uint4*)ph;
            *(uint4*)&sm[OFF_AHI + fa_m * CPITCH + fa_k + 8] = *(const uint4*)(ph + 8);
            *(uint4*)&sm[OFF_ALO + fa_m * CPITCH + fa_k]     = *(const uint4*)pl;
            *(uint4*)&sm[OFF_ALO + fa_m * CPITCH + fa_k + 8] = *(const uint4*)(pl + 8);
        }
        {
            const unsigned short* ph = Bh + (size_t)fb_n * K + c64 + fb_h;
            const unsigned short* pl = Bl + (size_t)fb_n * K + c64 + fb_h;
            unsigned short* dh = &sm[OFF_BHI + fb_n * CPITCH + fb_h];
            unsigned short* dl = &sm[OFF_BLO + fb_n * CPITCH + fb_h];
#pragma unroll
            for (int i = 0; i < 4; i++) {
                *(uint4*)(dh + i * 8) = *(const uint4*)(ph + i * 8);
                *(uint4*)(dl + i * 8) = *(const uint4*)(pl + i * 8);
            }
        }
        __syncthreads();
#pragma unroll
        for (int ks = 0; ks < 4; ks++) {
            int k0 = ks * 16;
            uint32_t ahi[2][4], alo[2][4], bhi[4][2], blo[4][2];
#pragma unroll
            for (int mi = 0; mi < 2; mi++) {
                int r0 = warp_m * 32 + mi * 16 + g;
                const unsigned short* p0 = &sm[OFF_AHI + r0 * CPITCH + k0 + tg * 2];
                const unsigned short* p1 = p0 + 8 * CPITCH;
                ahi[mi][0] = *(const uint32_t*)p0;
                ahi[mi][1] = *(const uint32_t*)p1;
                ahi[mi][2] = *(const uint32_t*)(p0 + 8);
                ahi[mi][3] = *(const uint32_t*)(p1 + 8);
                const unsigned short* q0 = &sm[OFF_ALO + r0 * CPITCH + k0 + tg * 2];
                const unsigned short* q1 = q0 + 8 * CPITCH;
                alo[mi][0] = *(const uint32_t*)q0;
                alo[mi][1] = *(const uint32_t*)q1;
                alo[mi][2] = *(const uint32_t*)(q0 + 8);
                alo[mi][3] = *(const uint32_t*)(q1 + 8);
            }
#pragma unroll
            for (int ni = 0; ni < 4; ni++) {
                int nr = warp_n * 32 + ni * 8 + g;
                const unsigned short* p = &sm[OFF_BHI + nr * CPITCH + k0 + tg * 2];
                bhi[ni][0] = *(const uint32_t*)p;
                bhi[ni][1] = *(const uint32_t*)(p + 8);
                const unsigned short* q = &sm[OFF_BLO + nr * CPITCH + k0 + tg * 2];
                blo[ni][0] = *(const uint32_t*)q;
                blo[ni][1] = *(const uint32_t*)(q + 8);
            }
#pragma unroll
            for (int mi = 0; mi < 2; mi++)
#pragma unroll
                for (int ni = 0; ni < 4; ni++) {
                    mma16816(acc[mi][ni], ahi[mi], bhi[ni]);
                    mma16816(acc[mi][ni], ahi[mi], blo[ni]);
                    mma16816(acc[mi][ni], alo[mi], bhi[ni]);
                    if (NT == 4) mma16816(acc[mi][ni], alo[mi], blo[ni]);
                }
        }
        __syncthreads();
    }

    if (CM == 0) {
#pragma unroll
        for (int mi = 0; mi < 2; mi++) {
            int m = m0 + warp_m * 32 + mi * 16 + g;
#pragma unroll
            for (int ni = 0; ni < 4; ni++) {
                int n = n0 + warp_n * 32 + ni * 8 + tg * 2;
                float b0 = bias ? bias[n] : 0.f;
                float b1 = bias ? bias[n + 1] : 0.f;
                *(float2*)&C[(size_t)m * N + n] =
                    make_float2(acc[mi][ni][0] + b0, acc[mi][ni][1] + b1);
                *(float2*)&C[(size_t)(m + 8) * N + n] =
                    make_float2(acc[mi][ni][2] + b0, acc[mi][ni][3] + b1);
            }
        }
    } else if (CM == 2) {
#pragma unroll
        for (int mi = 0; mi < 2; mi++) {
            int m = m0 + warp_m * 32 + mi * 16 + g;
            int bI = m >> 9, l = m & 511;
#pragma unroll
            for (int ni = 0; ni < 4; ni++) {
                int n = n0 + warp_n * 32 + ni * 8 + tg * 2;
                float b0 = bias ? bias[n] : 0.f;
                float b1 = bias ? bias[n + 1] : 0.f;
                C[(((size_t)(bI * N + n)) << 9) + l]           = acc[mi][ni][0] + b0;
                C[(((size_t)(bI * N + n + 1)) << 9) + l]       = acc[mi][ni][1] + b1;
                C[(((size_t)(bI * N + n)) << 9) + l + 8]       = acc[mi][ni][2] + b0;
                C[(((size_t)(bI * N + n + 1)) << 9) + l + 8]   = acc[mi][ni][3] + b1;
            }
        }
    } else {
        // QKV epilogue: row m = b*512+l; col n -> d = n/24, h = (n%24)/3, kq = n%3
#pragma unroll
        for (int mi = 0; mi < 2; mi++) {
            int m = m0 + warp_m * 32 + mi * 16 + g;
            int bI = m >> 9, l = m & 511;
#pragma unroll
            for (int ni = 0; ni < 4; ni++) {
                int n = n0 + warp_n * 32 + ni * 8 + tg * 2;
#pragma unroll
                for (int jj = 0; jj < 2; jj++) {
                    int nn = n + jj;
                    int d = nn / 24;
                    int r = nn - 24 * d;
                    int h = r / 3;
                    int kq = r - 3 * h;
                    float bs = bias[nn];
                    size_t base0 = (size_t)kq * QKVSZ + (((size_t)(bI * 8 + h) * 512 + l) << 5) + d;
                    C[base0]                    = acc[mi][ni][jj] + bs;
                    C[base0 + ((size_t)8 << 5)] = acc[mi][ni][2 + jj] + bs;
                }
            }
        }
    }
}

// ---------------- GroupNorm (+optional emb add) + GELU, fused; bf16 hi/lo output ----------------
__global__ void gn_gelu_kernel(const float* __restrict__ xin, const float* __restrict__ emb,
                               const float* __restrict__ scale, const float* __restrict__ bias,
                               float* __restrict__ x1_out,
                               unsigned short* __restrict__ hhi, unsigned short* __restrict__ hlo) {
    int b = blockIdx.x >> 5;
    int g = blockIdx.x & 31;
    size_t base = ((size_t)b * CC + g * CPG) * LL;
    __shared__ float vals[CPG * LL];
    __shared__ float red[256];
    int tid = threadIdx.x;
    float s = 0.f, s2 = 0.f;
#pragma unroll
    for (int i = 0; i < 16; i++) {
        int j = tid + i * 256;
        float v = xin[base + j];
        if (emb) v += emb[base + j];
        vals[j] = v;
        s += v;
        s2 = fmaf(v, v, s2);
    }
    red[tid] = s; __syncthreads();
    for (int o = 128; o > 0; o >>= 1) { if (tid < o) red[tid] += red[tid + o]; __syncthreads(); }
    float mean = red[0] * (1.f / 4096.f);
    __syncthreads();
    red[tid] = s2; __syncthreads();
    for (int o = 128; o > 0; o >>= 1) { if (tid < o) red[tid] += red[tid + o]; __syncthreads(); }
    float var = red[0] * (1.f / 4096.f) - mean * mean;
    float rsig = rsqrtf(var + 1e-5f);
#pragma unroll
    for (int i = 0; i < 16; i++) {
        int j = tid + i * 256;
        int c = g * CPG + (j >> 9);
        float v = vals[j];
        if (x1_out) x1_out[base + j] = v;
        float nn = (v - mean) * rsig * scale[c] + bias[c];
        float hv = gelu_exact(nn);
        unsigned short hu, lu;
        split_bf16(hv, hu, lu);
        hhi[base + j] = hu;
        hlo[base + j] = lu;
    }
}

// ---------------- fused flash attention; bf16 hi/lo output ----------------
__global__ void fused_attn_kernel(const float* __restrict__ Q, const float* __restrict__ K,
                                  const float* __restrict__ V,
                                  unsigned short* __restrict__ Ohi, unsigned short* __restrict__ Olo) {
    int bh = blockIdx.y;
    int q0 = blockIdx.x * 64;
    int b = bh >> 3, h = bh & 7;
    __shared__ float Qs[64][33];
    __shared__ float Ks[64][33];
    __shared__ float Vs[64][33];
    __shared__ float Ps[64][65];
    __shared__ float rowm[64], rowl[64], rowscale[64];
    int tid = threadIdx.x;
    int d = tid & 31, qg = tid >> 5;
    int tx = tid & 15, ty = tid >> 4;
    const float sc = 0.17677669529663687f;

#pragma unroll
    for (int i = 0; i < 8; i++) {
        int idx = tid + i * 256;
        int r = idx >> 5, dd = idx & 31;
        Qs[r][dd] = Q[((size_t)(bh << 9) + q0 + r) * 32 + dd];
    }
    if (tid < 64) { rowm[tid] = -3.4e38f; rowl[tid] = 0.f; }
    float acc[8];
#pragma unroll
    for (int j = 0; j < 8; j++) acc[j] = 0.f;

    for (int k0 = 0; k0 < 512; k0 += 64) {
        __syncthreads();
#pragma unroll
        for (int i = 0; i < 8; i++) {
            int idx = tid + i * 256;
            int r = idx >> 5, dd = idx & 31;
            size_t gsrc = ((size_t)(bh << 9) + k0 + r) * 32 + dd;
            Ks[r][dd] = K[gsrc];
            Vs[r][dd] = V[gsrc];
        }
        __syncthreads();
        {
            float sacc[4][4] = {};
#pragma unroll
            for (int kk = 0; kk < 32; kk++) {
                float a[4], bq[4];
#pragma unroll
                for (int i = 0; i < 4; i++) a[i] = Qs[ty * 4 + i][kk];
#pragma unroll
                for (int j = 0; j < 4; j++) bq[j] = Ks[tx * 4 + j][kk];
#pragma unroll
                for (int i = 0; i < 4; i++)
#pragma unroll
                    for (int j = 0; j < 4; j++) sacc[i][j] = fmaf(a[i], bq[j], sacc[i][j]);
            }
#pragma unroll
            for (int i = 0; i < 4; i++)
#pragma unroll
                for (int j = 0; j < 4; j++)
                    Ps[ty * 4 + i][tx * 4 + j] = sacc[i][j] * sc;
        }
        __syncthreads();
        {
            int r = tid >> 2, sub = tid & 3;
            float mloc = -3.4e38f;
#pragma unroll
            for (int c = 0; c < 16; c++) mloc = fmaxf(mloc, Ps[r][sub * 16 + c]);
            mloc = fmaxf(mloc, __shfl_xor_sync(0xffffffff, mloc, 1));
            mloc = fmaxf(mloc, __shfl_xor_sync(0xffffffff, mloc, 2));
            float mold = rowm[r];
            float mnew = fmaxf(mold, mloc);
            float ssum = 0.f;
#pragma unroll
            for (int c = 0; c < 16; c++) {
                float e = expf(Ps[r][sub * 16 + c] - mnew);
                Ps[r][sub * 16 + c] = e;
                ssum += e;
            }
            ssum += __shfl_xor_sync(0xffffffff, ssum, 1);
            ssum += __shfl_xor_sync(0xffffffff, ssum, 2);
            if (sub == 0) {
                float scl = expf(mold - mnew);
                rowscale[r] = scl;
                rowl[r] = rowl[r] * scl + ssum;
                rowm[r] = mnew;
            }
        }
        __syncthreads();
#pragma unroll
        for (int j = 0; j < 8; j++) acc[j] *= rowscale[qg + j * 8];
#pragma unroll
        for (int kk = 0; kk < 64; kk++) {
            float vv = Vs[kk][d];
#pragma unroll
            for (int j = 0; j < 8; j++) acc[j] = fmaf(Ps[qg + j * 8][kk], vv, acc[j]);
        }
    }
#pragma unroll
    for (int j = 0; j < 8; j++) {
        int q = q0 + qg + j * 8;
        float v = acc[j] / rowl[qg + j * 8];
        unsigned short hu, lu;
        split_bf16(v, hu, lu);
        size_t o = ((size_t)(b << 9) + q) * 256 + d * NH + h;
        Ohi[o] = hu;
        Olo[o] = lu;
    }
}

// ---------------- MoE gating ----------------
__global__ void gating_kernel(const float* __restrict__ logits, float* __restrict__ raw,
                              float* __restrict__ g1, int* __restrict__ i1,
                              float* __restrict__ g2, int* __restrict__ i2) {
    int row = blockIdx.x;
    int tid = threadIdx.x;
    const float* p = logits + (size_t)row * EE;
    float lv[4];
#pragma unroll
    for (int j = 0; j < 4; j++) lv[j] = p[tid * 4 + j];
    __shared__ float sv[256];
    __shared__ int si[256];
    float bv = lv[0]; int bi = tid * 4;
#pragma unroll
    for (int j = 1; j < 4; j++) if (lv[j] > bv) { bv = lv[j]; bi = tid * 4 + j; }
    sv[tid] = bv; si[tid] = bi; __syncthreads();
    for (int o = 128; o > 0; o >>= 1) {
        if (tid < o) {
            if (sv[tid + o] > sv[tid] || (sv[tid + o] == sv[tid] && si[tid + o] < si[tid])) {
                sv[tid] = sv[tid + o]; si[tid] = si[tid + o];
            }
        }
        __syncthreads();
    }
    float maxv = sv[0]; int maxi = si[0];
    __syncthreads();
    float s = 0.f;
#pragma unroll
    for (int j = 0; j < 4; j++) s += expf(lv[j] - maxv);
    sv[tid] = s; __syncthreads();
    for (int o = 128; o > 0; o >>= 1) { if (tid < o) sv[tid] += sv[tid + o]; __syncthreads(); }
    float inv = 1.f / sv[0];
#pragma unroll
    for (int j = 0; j < 4; j++)
        raw[(size_t)row * EE + tid * 4 + j] = expf(lv[j] - maxv) * inv;
    __syncthreads();
    bv = -3.4e38f; bi = 0;
#pragma unroll
    for (int j = 0; j < 4; j++) {
        int e = tid * 4 + j;
        if (e != maxi && lv[j] > bv) { bv = lv[j]; bi = e; }
    }
    sv[tid] = bv; si[tid] = bi; __syncthreads();
    for (int o = 128; o > 0; o >>= 1) {
        if (tid < o) {
            if (sv[tid + o] > sv[tid] || (sv[tid + o] == sv[tid] && si[tid + o] < si[tid])) {
                sv[tid] = sv[tid + o]; si[tid] = si[tid + o];
            }
        }
        __syncthreads();
    }
    if (tid == 0) {
        float gate1v = inv;
        float gate2v = expf(sv[0] - maxv) * inv;
        float denom = gate1v + gate2v + 1e-9f;
        g1[row] = gate1v / denom;
        i1[row] = maxi;
        g2[row] = gate2v / denom;
        i2[row] = si[0];
    }
}

// ---------------- per-(b,e) sum of raw over tokens ----------------
__global__ void rawsum_kernel(const float* __restrict__ raw, float* __restrict__ rawsum) {
    int b = blockIdx.x >> 2;
    int chunk = blockIdx.x & 3;
    int e = chunk * 256 + threadIdx.x;
    const float* p = raw + (size_t)b * NTOK * EE + e;
    float s = 0.f;
    for (int n = 0; n < NTOK; n++) s += p[(size_t)n * EE];
    rawsum[b * EE + e] = s;
}

// ---------------- routing with capacity ----------------
__global__ void routing_kernel(const int* __restrict__ idx1, const float* __restrict__ gate1,
                               const int* __restrict__ idx2, const float* __restrict__ gate2,
                               int* __restrict__ slot_tok, float* __restrict__ slot_gate,
                               float* __restrict__ cnt1_out) {
    int b = blockIdx.x;
    int tid = threadIdx.x;
    __shared__ int cnt[EE];
    __shared__ int mcnt[EE];
    for (int e = tid; e < EE; e += 256) cnt[e] = 0;
    for (int i = tid; i < EE * CAPP; i += 256) {
        slot_tok[b * EE * CAPP + i] = -1;
        slot_gate[b * EE * CAPP + i] = 0.f;
    }
    __syncthreads();
    if (tid == 0) {
        for (int n = 0; n < NTOK; n++) {
            int e = idx1[b * NTOK + n];
            int pcur = cnt[e]++;
            if (pcur < CAPP) {
                slot_tok[(b * EE + e) * CAPP + pcur] = n;
                slot_gate[(b * EE + e) * CAPP + pcur] = gate1[b * NTOK + n];
            }
        }
    }
    __syncthreads();
    for (int e = tid; e < EE; e += 256) {
        cnt1_out[b * EE + e] = (float)cnt[e];
        mcnt[e] = cnt[e] < CAPP ? cnt[e] : CAPP;
        cnt[e] = 0;
    }
    __syncthreads();
    if (tid == 0) {
        for (int n = 0; n < NTOK; n++) {
            int e = idx2[b * NTOK + n];
            int pcur = mcnt[e] + cnt[e];
            cnt[e]++;
            if (pcur < CAPP) {
                slot_tok[(b * EE + e) * CAPP + pcur] = n;
                slot_gate[(b * EE + e) * CAPP + pcur] = gate2[b * NTOK + n];
            }
        }
    }
}

// ---------------- expert FFN (float4 weight staging) ----------------
__global__ void expert_kernel(const float* __restrict__ xm, const float* __restrict__ w1,
                              const float* __restrict__ w2,
                              const int* __restrict__ slot_tok, const float* __restrict__ slot_gate,
                              float* __restrict__ out) {
    int e = blockIdx.x;
    int tid = threadIdx.x;
    extern __shared__ float sw[];
    __shared__ float hsh[32][33];
    __shared__ int stok[32];
    __shared__ float sgate[32];
    __shared__ int s_any;
    if (tid < 32) {
        int b = tid >> 2, c = tid & 3;
        stok[tid]  = slot_tok [(b * EE + e) * CAPP + c];
        sgate[tid] = slot_gate[(b * EE + e) * CAPP + c];
    }
    if (tid == 0) s_any = 0;
    __syncthreads();
    if (tid == 0) {
        int a = 0;
        for (int i = 0; i < 32; i++) a |= (stok[i] >= 0);
        s_any = a;
    }
    __syncthreads();
    if (!s_any) return;
    {
        const float4* w1v = (const float4*)(w1 + (size_t)e * DTOK * HIDD);
        float4* swv = (float4*)sw;
#pragma unroll
        for (int i = 0; i < 16; i++) swv[tid + i * 256] = w1v[tid + i * 256];
    }
    __syncthreads();
    int hid = tid & 31;
#pragma unroll
    for (int pass = 0; pass < 4; pass++) {
        int sidx = pass * 8 + (tid >> 5);
        int tok = stok[sidx];
        float acc = 0.f;
        if (tok >= 0) {
            const float* xr = xm + ((size_t)((sidx >> 2) * NTOK + tok)) * DTOK;
            for (int dd = 0; dd < DTOK; dd++) acc = fmaf(xr[dd], sw[dd * HIDD + hid], acc);
        }
        hsh[sidx][hid] = gelu_exact(acc);
    }
    __syncthreads();
    {
        const float4* w2v = (const float4*)(w2 + (size_t)e * HIDD * DTOK);
        float4* swv = (float4*)sw;
#pragma unroll
        for (int i = 0; i < 16; i++) swv[tid + i * 256] = w2v[tid + i * 256];
    }
    __syncthreads();
#pragma unroll
    for (int i = 0; i < 64; i++) {
        int idx = tid + i * 256;
        int sidx = idx >> 9;
        int dd = idx & 511;
        int tok = stok[sidx];
        float g = sgate[sidx];
        if (tok >= 0 && g != 0.f) {
            float acc = 0.f;
#pragma unroll
            for (int h2 = 0; h2 < HIDD; h2++) acc = fmaf(hsh[sidx][h2], sw[h2 * DTOK + dd], acc);
            atomicAdd(&out[((size_t)((sidx >> 2) * NTOK + tok)) * DTOK + dd], g * acc);
        }
    }
}

// ---------------- aux loss ----------------
__global__ void loss_kernel(const float* __restrict__ rawsum, const float* __restrict__ cnt1,
                            float* __restrict__ out_scalar) {
    __shared__ float red[256];
    int tid = threadIdx.x;
    float s = 0.f;
    for (int i = tid; i < BB * EE; i += 256) s += rawsum[i] * cnt1[i];
    red[tid] = s; __syncthreads();
    for (int o = 128; o > 0; o >>= 1) { if (tid < o) red[tid] += red[tid + o]; __syncthreads(); }
    if (tid == 0) out_scalar[0] = red[0] * 1.953125e-05f;
}

// ---------------- maxpool k=3 s=2 pad=1 ----------------
__global__ void maxpool_kernel(const float* __restrict__ yf, float* __restrict__ out) {
    int idx = blockIdx.x * 256 + threadIdx.x;
    int j = idx & 255;
    int o = (idx >> 8) & 511;
    int b = idx >> 17;
    const float* row = yf + ((size_t)(b * 512 + o)) * 512;
    int l = 2 * j;
    float m = row[l];
    if (l > 0) m = fmaxf(m, row[l - 1]);
    m = fmaxf(m, row[l + 1]);
    out[idx] = m;
}

// ---------------- host orchestration ----------------
extern "C" void kernel_launch(void* const* d_in, const int* in_sizes, int n_in,
                              void* d_out, int out_size) {
    const float* x        = (const float*)d_in[0];
    const float* emb      = (const float*)d_in[1];
    const float* rb1_g1s  = (const float*)d_in[2];
    const float* rb1_g1b  = (const float*)d_in[3];
    const float* rb1_c1w  = (const float*)d_in[4];
    const float* rb1_c1b  = (const float*)d_in[5];
    const float* rb1_g2s  = (const float*)d_in[6];
    const float* rb1_g2b  = (const float*)d_in[7];
    const float* rb1_c2w  = (const float*)d_in[8];
    const float* rb1_c2b  = (const float*)d_in[9];
    const float* rb2_g1s  = (const float*)d_in[10];
    const float* rb2_g1b  = (const float*)d_in[11];
    const float* rb2_c1w  = (const float*)d_in[12];
    const float* rb2_c1b  = (const float*)d_in[13];
    const float* rb2_g2s  = (const float*)d_in[14];
    const float* rb2_g2b  = (const float*)d_in[15];
    const float* rb2_c2w  = (const float*)d_in[16];
    const float* rb2_c2b  = (const float*)d_in[17];
    const float* attn_w1  = (const float*)d_in[18];
    const float* attn_b1  = (const float*)d_in[19];
    const float* attn_w2  = (const float*)d_in[20];
    const float* attn_b2  = (const float*)d_in[21];
    const float* moe_wg   = (const float*)d_in[22];
    const float* moe_w1   = (const float*)d_in[23];
    const float* moe_w2   = (const float*)d_in[24];
    const float* out_w    = (const float*)d_in[25];
    const float* out_b    = (const float*)d_in[26];
    float* out = (float*)d_out;

    float *px1, *pr, *pxa, *pqkv, *pxb, *pxm;
    float *plog, *praw, *pg1, *pg2, *prs, *pc1, *psg, *pmo, *pyf;
    int *pi1, *pi2, *pst;
    unsigned short *pwhi, *pwlo, *phhi, *phlo, *pxmh, *pxml;
    cudaGetSymbolAddress((void**)&px1, g_x1);
    cudaGetSymbolAddress((void**)&pr,  g_r);
    cudaGetSymbolAddress((void**)&pxa, g_xa);
    cudaGetSymbolAddress((void**)&pqkv, g_qkv);
    cudaGetSymbolAddress((void**)&pxb, g_xb);
    cudaGetSymbolAddress((void**)&pxm, g_xm);
    cudaGetSymbolAddress((void**)&plog, g_logits);
    cudaGetSymbolAddress((void**)&praw, g_raw);
    cudaGetSymbolAddress((void**)&pg1, g_gate1);
    cudaGetSymbolAddress((void**)&pg2, g_gate2);
    cudaGetSymbolAddress((void**)&pi1, g_i1);
    cudaGetSymbolAddress((void**)&pi2, g_i2);
    cudaGetSymbolAddress((void**)&prs, g_rawsum);
    cudaGetSymbolAddress((void**)&pc1, g_cnt1);
    cudaGetSymbolAddress((void**)&pst, g_slot_tok);
    cudaGetSymbolAddress((void**)&psg, g_slot_gate);
    cudaGetSymbolAddress((void**)&pmo, g_moeout);
    cudaGetSymbolAddress((void**)&pyf, g_yfull);
    cudaGetSymbolAddress((void**)&pwhi, g_whi);
    cudaGetSymbolAddress((void**)&pwlo, g_wlo);
    cudaGetSymbolAddress((void**)&phhi, g_hhi);
    cudaGetSymbolAddress((void**)&phlo, g_hlo);
    cudaGetSymbolAddress((void**)&pxmh, g_xmh);
    cudaGetSymbolAddress((void**)&pxml, g_xml);

    cudaFuncSetAttribute(expert_kernel, cudaFuncAttributeMaxDynamicSharedMemorySize, 65536);
    cudaFuncSetAttribute(conv_mma_kernel, cudaFuncAttributeMaxDynamicSharedMemorySize, MMA_SMEM);
    cudaFuncSetAttribute(gemm_mma<3,3>, cudaFuncAttributeMaxDynamicSharedMemorySize, MMA_SMEM);
    cudaFuncSetAttribute(gemm_mma<2,3>, cudaFuncAttributeMaxDynamicSharedMemorySize, MMA_SMEM);
    cudaFuncSetAttribute(gemm_mma<0,4>, cudaFuncAttributeMaxDynamicSharedMemorySize, MMA_SMEM);

    const int WSZc = WSZ;
    // ---- pre-convert weights ----
    cvt_hilo_kernel<<<768, 256>>>(rb1_c1w, pwhi,          pwlo,          WSZc);
    cvt_hilo_kernel<<<768, 256>>>(rb1_c2w, pwhi + WSZc,   pwlo + WSZc,   WSZc);
    cvt_hilo_kernel<<<768, 256>>>(rb2_c1w, pwhi + 2*WSZc, pwlo + 2*WSZc, WSZc);
    cvt_hilo_kernel<<<768, 256>>>(rb2_c2w, pwhi + 3*WSZc, pwlo + 3*WSZc, WSZc);
    cvt_hilo_kernel<<<1536, 256>>>(out_w,  pwhi + 4*WSZc, pwlo + 4*WSZc, 2*WSZc);
    cvtT_w_kernel<<<dim3(8, 24), dim3(32, 8)>>>(attn_w1, pwhi + OFF_WQKVT, pwlo + OFF_WQKVT, 256, 768);
    cvtT_w_kernel<<<dim3(8, 8),  dim3(32, 8)>>>(attn_w2, pwhi + OFF_W2T,   pwlo + OFF_W2T,   256, 256);
    cvtT_w_kernel<<<dim3(16, 32), dim3(32, 8)>>>(moe_wg, pwhi + OFF_WGT,   pwlo + OFF_WGT,   512, 1024);

    // ---- res block 1 ----
    gn_gelu_kernel<<<BB * NG, 256>>>(x, emb, rb1_g1s, rb1_g1b, px1, phhi, phlo);
    conv_mma_kernel<<<dim3(32, 4), 256, MMA_SMEM>>>(pwhi, pwlo, phhi, phlo, rb1_c1b, nullptr, pr, nullptr, nullptr, 256);
    gn_gelu_kernel<<<BB * NG, 256>>>(pr, nullptr, rb1_g2s, rb1_g2b, nullptr, phhi, phlo);
    conv_mma_kernel<<<dim3(32, 4), 256, MMA_SMEM>>>(pwhi + WSZc, pwlo + WSZc, phhi, phlo, rb1_c2b, px1, pxa, nullptr, nullptr, 256);

    // ---- attention (qkv split fused into GEMM epilogue) ----
    cvtT_x_kernel<<<dim3(16, 8, 8), dim3(32, 8)>>>(pxa, phhi, phlo);
    gemm_mma<3,3><<<dim3(6, 64), 256, MMA_SMEM>>>(phhi, phlo, pwhi + OFF_WQKVT, pwlo + OFF_WQKVT,
                                                  attn_b1, pqkv, 4096, 768, 256);
    fused_attn_kernel<<<dim3(8, 64), 256>>>(pqkv, pqkv + QKVSZ, pqkv + 2*QKVSZ, phhi, phlo);
    gemm_mma<2,3><<<dim3(2, 64), 256, MMA_SMEM>>>(phhi, phlo, pwhi + OFF_W2T, pwlo + OFF_W2T,
                                                  attn_b2, pxb, 4096, 256, 256);

    // ---- res block 2 (conv2 emits bf16 hi/lo into SEPARATE buffers for logits GEMM) ----
    gn_gelu_kernel<<<BB * NG, 256>>>(pxb, emb, rb2_g1s, rb2_g1b, px1, phhi, phlo);
    conv_mma_kernel<<<dim3(32, 4), 256, MMA_SMEM>>>(pwhi + 2*WSZc, pwlo + 2*WSZc, phhi, phlo, rb2_c1b, nullptr, pr, nullptr, nullptr, 256);
    gn_gelu_kernel<<<BB * NG, 256>>>(pr, nullptr, rb2_g2s, rb2_g2b, nullptr, phhi, phlo);
    conv_mma_kernel<<<dim3(32, 4), 256, MMA_SMEM>>>(pwhi + 3*WSZc, pwlo + 3*WSZc, phhi, phlo, rb2_c2b, px1, pxm, pxmh, pxml, 256);

    // ---- MoE ----
    gemm_mma<0,4><<<dim3(8, 32), 256, MMA_SMEM>>>(pxmh, pxml, pwhi + OFF_WGT, pwlo + OFF_WGT,
                                                  nullptr, plog, 2048, 1024, 512);
    gating_kernel<<<2048, 256>>>(plog, praw, pg1, pi1, pg2, pi2);
    rawsum_kernel<<<32, 256>>>(praw, prs);
    routing_kernel<<<BB, 256>>>(pi1, pg1, pi2, pg2, pst, psg, pc1);
    cudaMemsetAsync(pmo, 0, sizeof(float) * BB * CC * LL);
    expert_kernel<<<EE, 256, 65536>>>(pxm, moe_w1, moe_w2, pst, psg, pmo);
    loss_kernel<<<1, 256>>>(prs, pc1, out + 2097152);

    // ---- output conv + maxpool ----
    cvt_hilo_kernel<<<4096, 256>>>(pmo, phhi, phlo, BB * CC * LL);
    conv_mma_kernel<<<dim3(32, 8), 256, MMA_SMEM>>>(pwhi + 4*WSZc, pwlo + 4*WSZc, phhi, phlo, out_b, nullptr, pyf, nullptr, nullptr, 512);
    maxpool_kernel<<<4096, 256>>>(pyf, out);

    // second output: moe result x (B,C,L)
    cudaMemcpyAsync(out + 1048576, pmo, sizeof(float) * BB * CC * LL, cudaMemcpyDeviceToDevice);
}

// round 13
// speedup vs baseline: 1.0086x; 1.0086x over previous
#include <cuda_runtime.h>
#include <cuda_bf16.h>
#include <math.h>
#include <stdint.h>

// ---------------- problem constants ----------------
#define BB   8
#define CC   256
#define LL   512
#define NG   32
#define CPG  8
#define NH   8
#define DH   32
#define EE   1024
#define HIDD 32
#define CAPP 4
#define NTOK 256
#define DTOK 512

// ---------------- scratch (device globals; allocation-free) ----------------
__device__ float g_x1[BB*CC*LL];
__device__ float g_r [BB*CC*LL];
__device__ float g_xa[BB*CC*LL];
__device__ float g_t [BB*LL*3*CC];
__device__ float g_q [BB*NH*LL*DH];
__device__ float g_k [BB*NH*LL*DH];
__device__ float g_v [BB*NH*LL*DH];
__device__ float g_oc[BB*LL*CC];
__device__ float g_xb[BB*CC*LL];
__device__ float g_xm[BB*CC*LL];
__device__ float g_logits[BB*NTOK*EE];
__device__ float g_raw  [BB*NTOK*EE];
__device__ float g_gate1[BB*NTOK];
__device__ float g_gate2[BB*NTOK];
__device__ int   g_i1[BB*NTOK];
__device__ int   g_i2[BB*NTOK];
__device__ float g_rawsum[BB*EE];
__device__ float g_cnt1 [BB*EE];
__device__ int   g_slot_tok [BB*EE*CAPP];
__device__ float g_slot_gate[BB*EE*CAPP];
__device__ float g_moeout[BB*CC*LL];
__device__ float g_yfull[(size_t)BB*2*CC*LL];
// bf16 hi/lo operand buffers
#define WSZ 196608
#define OFF_WQKVT (6*WSZ)
#define OFF_W2T   (OFF_WQKVT + 196608)
#define OFF_WGT   (OFF_W2T + 65536)
#define WTOT      (OFF_WGT + 524288)
__device__ unsigned short g_whi[WTOT];
__device__ unsigned short g_wlo[WTOT];
__device__ unsigned short g_hhi[BB*CC*LL];
__device__ unsigned short g_hlo[BB*CC*LL];

__device__ __forceinline__ float gelu_exact(float v) {
    return 0.5f * v * (1.0f + erff(v * 0.7071067811865476f));
}
__device__ __forceinline__ void split_bf16(float v, unsigned short& h, unsigned short& l) {
    __nv_bfloat16 hb = __float2bfloat16(v);
    __nv_bfloat16 lb = __float2bfloat16(v - __bfloat162float(hb));
    h = *(unsigned short*)&hb;
    l = *(unsigned short*)&lb;
}

// ---------------- float -> bf16 hi/lo conversion ----------------
__global__ void cvt_hilo_kernel(const float* __restrict__ src, unsigned short* __restrict__ hi,
                                unsigned short* __restrict__ lo, int n) {
    int i = blockIdx.x * 256 + threadIdx.x;
    if (i < n) {
        unsigned short h, l;
        split_bf16(src[i], h, l);
        hi[i] = h; lo[i] = l;
    }
}

// ---------------- transposed weight cvt: W[K][N] -> Bt[N][K] bf16 hi/lo ----------------
__global__ void cvtT_w_kernel(const float* __restrict__ W, unsigned short* __restrict__ bhi,
                              unsigned short* __restrict__ blo, int K, int N) {
    __shared__ float tile[32][33];
    int k0 = blockIdx.x * 32, n0 = blockIdx.y * 32;
    int x = threadIdx.x, y = threadIdx.y;
#pragma unroll
    for (int i = 0; i < 32; i += 8)
        tile[y + i][x] = W[(size_t)(k0 + y + i) * N + n0 + x];
    __syncthreads();
#pragma unroll
    for (int i = 0; i < 32; i += 8) {
        float v = tile[x][y + i];
        unsigned short h, l;
        split_bf16(v, h, l);
        size_t o = (size_t)(n0 + y + i) * K + k0 + x;
        bhi[o] = h; blo[o] = l;
    }
}

// ---------------- transposed activation cvt: xa(B,C,L) -> A[(b*L+l)][C] hi/lo ----------------
__global__ void cvtT_x_kernel(const float* __restrict__ X, unsigned short* __restrict__ ahi,
                              unsigned short* __restrict__ alo) {
    __shared__ float tile[32][33];
    int b = blockIdx.z;
    int l0 = blockIdx.x * 32, c0 = blockIdx.y * 32;
    int x = threadIdx.x, y = threadIdx.y;
#pragma unroll
    for (int i = 0; i < 32; i += 8)
        tile[y + i][x] = X[(((size_t)(b * CC + c0 + y + i)) << 9) + l0 + x];
    __syncthreads();
#pragma unroll
    for (int i = 0; i < 32; i += 8) {
        float v = tile[x][y + i];
        unsigned short h, l;
        split_bf16(v, h, l);
        size_t o = (size_t)(b * LL + l0 + y + i) * CC + c0 + x;
        ahi[o] = h; alo[o] = l;
    }
}

// ================= warp-level bf16 MMA (m16n8k16, f32 accum) =================
__device__ __forceinline__ void mma16816(float* c, const uint32_t* a, const uint32_t* b) {
    asm volatile("mma.sync.aligned.m16n8k16.row.col.f32.bf16.bf16.f32 "
        "{%0,%1,%2,%3}, {%4,%5,%6,%7}, {%8,%9}, {%0,%1,%2,%3};"
        : "+f"(c[0]), "+f"(c[1]), "+f"(c[2]), "+f"(c[3])
        : "r"(a[0]), "r"(a[1]), "r"(a[2]), "r"(a[3]), "r"(b[0]), "r"(b[1]));
}

#define CPITCH 72
#define OFF_AHI 0
#define OFF_ALO (64*CPITCH)
#define OFF_BHI (2*64*CPITCH)
#define OFF_BLO (2*64*CPITCH + 128*CPITCH)
#define MMA_SMEM ((2*64*CPITCH + 2*128*CPITCH) * 2)   // 55296 bytes

// ================= tensor-core conv1d(k=3,pad=1) =================
__global__ void __launch_bounds__(256, 2)
conv_mma_kernel(const unsigned short* __restrict__ Whi, const unsigned short* __restrict__ Wlo,
                const unsigned short* __restrict__ Xhi, const unsigned short* __restrict__ Xlo,
                const float* __restrict__ bias, const float* __restrict__ res,
                float* __restrict__ Y, int M) {
    extern __shared__ unsigned short sm[];
    int tid = threadIdx.x;
    int wid = tid >> 5, lane = tid & 31;
    int g = lane >> 2, tg = lane & 3;
    int warp_m = wid & 1, warp_n = wid >> 1;
    int n0 = blockIdx.x * 128, m0 = blockIdx.y * 64;
    int bI = n0 >> 9, l0 = n0 & 511;

    const unsigned short* Wh = Whi + (size_t)m0 * 768;
    const unsigned short* Wl = Wlo + (size_t)m0 * 768;
    const unsigned short* Xh = Xhi + (((size_t)bI * CC) << 9);
    const unsigned short* Xl = Xlo + (((size_t)bI * CC) << 9);

    float acc[2][4][4];
#pragma unroll
    for (int mi = 0; mi < 2; mi++)
#pragma unroll
        for (int ni = 0; ni < 4; ni++)
#pragma unroll
            for (int r = 0; r < 4; r++) acc[mi][ni][r] = 0.f;

    int fa_m = tid >> 2, fa_k = (tid & 3) * 16;
    int fb_n = tid >> 1, fb_h = (tid & 1) * 32;

    for (int c = 0; c < 12; c++) {
        int c64 = c * 64;
        {
            const unsigned short* ph = Wh + (size_t)fa_m * 768 + c64 + fa_k;
            const unsigned short* pl = Wl + (size_t)fa_m * 768 + c64 + fa_k;
            *(uint4*)&sm[OFF_AHI + fa_m * CPITCH + fa_k]     = *(const uint4*)ph;
            *(uint4*)&sm[OFF_AHI + fa_m * CPITCH + fa_k + 8] = *(const uint4*)(ph + 8);
            *(uint4*)&sm[OFF_ALO + fa_m * CPITCH + fa_k]     = *(const uint4*)pl;
            *(uint4*)&sm[OFF_ALO + fa_m * CPITCH + fa_k + 8] = *(const uint4*)(pl + 8);
        }
        {
            int kg = c64 + fb_h;
            int ic = kg / 3, t = kg - 3 * ic;
            int l = l0 + fb_n;
            unsigned short* dh = &sm[OFF_BHI + fb_n * CPITCH + fb_h];
            unsigned short* dl = &sm[OFF_BLO + fb_n * CPITCH + fb_h];
#pragma unroll 8
            for (int i = 0; i < 32; i++) {
                int ll = l + t - 1;
                bool ok = ((unsigned)ll < 512u);
                int src = (ic << 9) + ll;
                dh[i] = ok ? Xh[src] : (unsigned short)0;
                dl[i] = ok ? Xl[src] : (unsigned short)0;
                if (++t == 3) { t = 0; ++ic; }
            }
        }
        __syncthreads();
#pragma unroll
        for (int ks = 0; ks < 4; ks++) {
            int k0 = ks * 16;
            uint32_t ahi[2][4], alo[2][4], bhi[4][2], blo[4][2];
#pragma unroll
            for (int mi = 0; mi < 2; mi++) {
                int r0 = warp_m * 32 + mi * 16 + g;
                const unsigned short* p0 = &sm[OFF_AHI + r0 * CPITCH + k0 + tg * 2];
                const unsigned short* p1 = p0 + 8 * CPITCH;
                ahi[mi][0] = *(const uint32_t*)p0;
                ahi[mi][1] = *(const uint32_t*)p1;
                ahi[mi][2] = *(const uint32_t*)(p0 + 8);
                ahi[mi][3] = *(const uint32_t*)(p1 + 8);
                const unsigned short* q0 = &sm[OFF_ALO + r0 * CPITCH + k0 + tg * 2];
                const unsigned short* q1 = q0 + 8 * CPITCH;
                alo[mi][0] = *(const uint32_t*)q0;
                alo[mi][1] = *(const uint32_t*)q1;
                alo[mi][2] = *(const uint32_t*)(q0 + 8);
                alo[mi][3] = *(const uint32_t*)(q1 + 8);
            }
#pragma unroll
            for (int ni = 0; ni < 4; ni++) {
                int nr = warp_n * 32 + ni * 8 + g;
                const unsigned short* p = &sm[OFF_BHI + nr * CPITCH + k0 + tg * 2];
                bhi[ni][0] = *(const uint32_t*)p;
                bhi[ni][1] = *(const uint32_t*)(p + 8);
                const unsigned short* q = &sm[OFF_BLO + nr * CPITCH + k0 + tg * 2];
                blo[ni][0] = *(const uint32_t*)q;
                blo[ni][1] = *(const uint32_t*)(q + 8);
            }
#pragma unroll
            for (int mi = 0; mi < 2; mi++)
#pragma unroll
                for (int ni = 0; ni < 4; ni++) {
                    mma16816(acc[mi][ni], ahi[mi], bhi[ni]);
                    mma16816(acc[mi][ni], ahi[mi], blo[ni]);
                    mma16816(acc[mi][ni], alo[mi], bhi[ni]);
                }
        }
        __syncthreads();
    }

#pragma unroll
    for (int mi = 0; mi < 2; mi++) {
        int m = m0 + warp_m * 32 + mi * 16 + g;
        float bs0 = bias[m], bs1 = bias[m + 8];
        size_t row0 = (((size_t)bI * M + m) << 9) + l0;
        size_t row1 = (((size_t)bI * M + m + 8) << 9) + l0;
#pragma unroll
        for (int ni = 0; ni < 4; ni++) {
            int ncol = warp_n * 32 + ni * 8 + tg * 2;
            float2 v0 = make_float2(acc[mi][ni][0] + bs0, acc[mi][ni][1] + bs0);
            float2 v1 = make_float2(acc[mi][ni][2] + bs1, acc[mi][ni][3] + bs1);
            if (res) {
                float2 r0 = *(const float2*)&res[row0 + ncol];
                float2 r1 = *(const float2*)&res[row1 + ncol];
                v0.x += r0.x; v0.y += r0.y; v1.x += r1.x; v1.y += r1.y;
            }
            *(float2*)&Y[row0 + ncol] = v0;
            *(float2*)&Y[row1 + ncol] = v1;
        }
    }
}

// ================= generic tensor-core GEMM: C[M,N] = A[M,K] @ Bt[N,K]^T =================
template<int CM, int NT>
__global__ void __launch_bounds__(256, 2)
gemm_mma(const unsigned short* __restrict__ Ahi, const unsigned short* __restrict__ Alo,
         const unsigned short* __restrict__ Bthi, const unsigned short* __restrict__ Btlo,
         const float* __restrict__ bias, float* __restrict__ C, int M, int N, int K) {
    extern __shared__ unsigned short sm[];
    int tid = threadIdx.x;
    int wid = tid >> 5, lane = tid & 31;
    int g = lane >> 2, tg = lane & 3;
    int warp_m = wid & 1, warp_n = wid >> 1;
    int n0 = blockIdx.x * 128, m0 = blockIdx.y * 64;

    const unsigned short* Ah = Ahi + (size_t)m0 * K;
    const unsigned short* Al = Alo + (size_t)m0 * K;
    const unsigned short* Bh = Bthi + (size_t)n0 * K;
    const unsigned short* Bl = Btlo + (size_t)n0 * K;

    float acc[2][4][4];
#pragma unroll
    for (int mi = 0; mi < 2; mi++)
#pragma unroll
        for (int ni = 0; ni < 4; ni++)
#pragma unroll
            for (int r = 0; r < 4; r++) acc[mi][ni][r] = 0.f;

    int fa_m = tid >> 2, fa_k = (tid & 3) * 16;
    int fb_n = tid >> 1, fb_h = (tid & 1) * 32;
    int nchunks = K >> 6;

    for (int c = 0; c < nchunks; c++) {
        int c64 = c << 6;
        {
            const unsigned short* ph = Ah + (size_t)fa_m * K + c64 + fa_k;
            const unsigned short* pl = Al + (size_t)fa_m * K + c64 + fa_k;
            *(uint4*)&sm[OFF_AHI + fa_m * CPITCH + fa_k]     = *(const uint4*)ph;
            *(uint4*)&sm[OFF_AHI + fa_m * CPITCH + fa_k + 8] = *(const uint4*)(ph + 8);
            *(uint4*)&sm[OFF_ALO + fa_m * CPITCH + fa_k]     = *(const uint4*)pl;
            *(uint4*)&sm[OFF_ALO + fa_m * CPITCH + fa_k + 8] = *(const uint4*)(pl + 8);
        }
        {
            const unsigned short* ph = Bh + (size_t)fb_n * K + c64 + fb_h;
            const unsigned short* pl = Bl + (size_t)fb_n * K + c64 + fb_h;
            unsigned short* dh = &sm[OFF_BHI + fb_n * CPITCH + fb_h];
            unsigned short* dl = &sm[OFF_BLO + fb_n * CPITCH + fb_h];
#pragma unroll
            for (int i = 0; i < 4; i++) {
                *(uint4*)(dh + i * 8) = *(const uint4*)(ph + i * 8);
                *(uint4*)(dl + i * 8) = *(const uint4*)(pl + i * 8);
            }
        }
        __syncthreads();
#pragma unroll
        for (int ks = 0; ks < 4; ks++) {
            int k0 = ks * 16;
            uint32_t ahi[2][4], alo[2][4], bhi[4][2], blo[4][2];
#pragma unroll
            for (int mi = 0; mi < 2; mi++) {
                int r0 = warp_m * 32 + mi * 16 + g;
                const unsigned short* p0 = &sm[OFF_AHI + r0 * CPITCH + k0 + tg * 2];
                const unsigned short* p1 = p0 + 8 * CPITCH;
                ahi[mi][0] = *(const uint32_t*)p0;
                ahi[mi][1] = *(const uint32_t*)p1;
                ahi[mi][2] = *(const uint32_t*)(p0 + 8);
                ahi[mi][3] = *(const uint32_t*)(p1 + 8);
                const unsigned short* q0 = &sm[OFF_ALO + r0 * CPITCH + k0 + tg * 2];
                const unsigned short* q1 = q0 + 8 * CPITCH;
                alo[mi][0] = *(const uint32_t*)q0;
                alo[mi][1] = *(const uint32_t*)q1;
                alo[mi][2] = *(const uint32_t*)(q0 + 8);
                alo[mi][3] = *(const uint32_t*)(q1 + 8);
            }
#pragma unroll
            for (int ni = 0; ni < 4; ni++) {
                int nr = warp_n * 32 + ni * 8 + g;
                const unsigned short* p = &sm[OFF_BHI + nr * CPITCH + k0 + tg * 2];
                bhi[ni][0] = *(const uint32_t*)p;
                bhi[ni][1] = *(const uint32_t*)(p + 8);
                const unsigned short* q = &sm[OFF_BLO + nr * CPITCH + k0 + tg * 2];
                blo[ni][0] = *(const uint32_t*)q;
                blo[ni][1] = *(const uint32_t*)(q + 8);
            }
#pragma unroll
            for (int mi = 0; mi < 2; mi++)
#pragma unroll
                for (int ni = 0; ni < 4; ni++) {
                    mma16816(acc[mi][ni], ahi[mi], bhi[ni]);
                    mma16816(acc[mi][ni], ahi[mi], blo[ni]);
                    mma16816(acc[mi][ni], alo[mi], bhi[ni]);
                    if (NT == 4) mma16816(acc[mi][ni], alo[mi], blo[ni]);
                }
        }
        __syncthreads();
    }

    if (CM == 0) {
#pragma unroll
        for (int mi = 0; mi < 2; mi++) {
            int m = m0 + warp_m * 32 + mi * 16 + g;
#pragma unroll
            for (int ni = 0; ni < 4; ni++) {
                int n = n0 + warp_n * 32 + ni * 8 + tg * 2;
                float b0 = bias ? bias[n] : 0.f;
                float b1 = bias ? bias[n + 1] : 0.f;
                *(float2*)&C[(size_t)m * N + n] =
                    make_float2(acc[mi][ni][0] + b0, acc[mi][ni][1] + b1);
                *(float2*)&C[(size_t)(m + 8) * N + n] =
                    make_float2(acc[mi][ni][2] + b0, acc[mi][ni][3] + b1);
            }
        }
    } else {  // CTRANS
#pragma unroll
        for (int mi = 0; mi < 2; mi++) {
            int m = m0 + warp_m * 32 + mi * 16 + g;
            int bI = m >> 9, l = m & 511;
#pragma unroll
            for (int ni = 0; ni < 4; ni++) {
                int n = n0 + warp_n * 32 + ni * 8 + tg * 2;
                float b0 = bias ? bias[n] : 0.f;
                float b1 = bias ? bias[n + 1] : 0.f;
                C[(((size_t)(bI * N + n)) << 9) + l]           = acc[mi][ni][0] + b0;
                C[(((size_t)(bI * N + n + 1)) << 9) + l]       = acc[mi][ni][1] + b1;
                C[(((size_t)(bI * N + n)) << 9) + l + 8]       = acc[mi][ni][2] + b0;
                C[(((size_t)(bI * N + n + 1)) << 9) + l + 8]   = acc[mi][ni][3] + b1;
            }
        }
    }
}

// ---------------- GroupNorm (+optional emb add) + GELU, fused; bf16 hi/lo output ----------------
__global__ void gn_gelu_kernel(const float* __restrict__ xin, const float* __restrict__ emb,
                               const float* __restrict__ scale, const float* __restrict__ bias,
                               float* __restrict__ x1_out,
                               unsigned short* __restrict__ hhi, unsigned short* __restrict__ hlo) {
    int b = blockIdx.x >> 5;
    int g = blockIdx.x & 31;
    size_t base = ((size_t)b * CC + g * CPG) * LL;
    __shared__ float vals[CPG * LL];
    __shared__ float red[256];
    int tid = threadIdx.x;
    float s = 0.f, s2 = 0.f;
#pragma unroll
    for (int i = 0; i < 16; i++) {
        int j = tid + i * 256;
        float v = xin[base + j];
        if (emb) v += emb[base + j];
        vals[j] = v;
        s += v;
        s2 = fmaf(v, v, s2);
    }
    red[tid] = s; __syncthreads();
    for (int o = 128; o > 0; o >>= 1) { if (tid < o) red[tid] += red[tid + o]; __syncthreads(); }
    float mean = red[0] * (1.f / 4096.f);
    __syncthreads();
    red[tid] = s2; __syncthreads();
    for (int o = 128; o > 0; o >>= 1) { if (tid < o) red[tid] += red[tid + o]; __syncthreads(); }
    float var = red[0] * (1.f / 4096.f) - mean * mean;
    float rsig = rsqrtf(var + 1e-5f);
#pragma unroll
    for (int i = 0; i < 16; i++) {
        int j = tid + i * 256;
        int c = g * CPG + (j >> 9);
        float v = vals[j];
        if (x1_out) x1_out[base + j] = v;
        float nn = (v - mean) * rsig * scale[c] + bias[c];
        float hv = gelu_exact(nn);
        unsigned short hu, lu;
        split_bf16(hv, hu, lu);
        hhi[base + j] = hu;
        hlo[base + j] = lu;
    }
}

// ---------------- qkv split ----------------
__global__ void qkv_split_kernel(const float* __restrict__ t, float* __restrict__ Q,
                                 float* __restrict__ K, float* __restrict__ V) {
    int idx = blockIdx.x * 256 + threadIdx.x;
    int d = idx & 31;
    int l = (idx >> 5) & 511;
    int h = (idx >> 14) & 7;
    int b = idx >> 17;
    size_t base = ((size_t)(b * LL + l)) * 768 + (size_t)(d * NH + h) * 3;
    int o = ((b * NH + h) * LL + l) * DH + d;
    Q[o] = t[base];
    K[o] = t[base + 1];
    V[o] = t[base + 2];
}

// ---------------- fused flash attention ----------------
__global__ void fused_attn_kernel(const float* __restrict__ Q, const float* __restrict__ K,
                                  const float* __restrict__ V, float* __restrict__ OCb) {
    int bh = blockIdx.y;
    int q0 = blockIdx.x * 64;
    int b = bh >> 3, h = bh & 7;
    __shared__ float Qs[64][33];
    __shared__ float Ks[64][33];
    __shared__ float Vs[64][33];
    __shared__ float Ps[64][65];
    __shared__ float rowm[64], rowl[64], rowscale[64];
    int tid = threadIdx.x;
    int d = tid & 31, qg = tid >> 5;
    int tx = tid & 15, ty = tid >> 4;
    const float sc = 0.17677669529663687f;

#pragma unroll
    for (int i = 0; i < 8; i++) {
        int idx = tid + i * 256;
        int r = idx >> 5, dd = idx & 31;
        Qs[r][dd] = Q[((size_t)(bh << 9) + q0 + r) * 32 + dd];
    }
    if (tid < 64) { rowm[tid] = -3.4e38f; rowl[tid] = 0.f; }
    float acc[8];
#pragma unroll
    for (int j = 0; j < 8; j++) acc[j] = 0.f;

    for (int k0 = 0; k0 < 512; k0 += 64) {
        __syncthreads();
#pragma unroll
        for (int i = 0; i < 8; i++) {
            int idx = tid + i * 256;
            int r = idx >> 5, dd = idx & 31;
            size_t gsrc = ((size_t)(bh << 9) + k0 + r) * 32 + dd;
            Ks[r][dd] = K[gsrc];
            Vs[r][dd] = V[gsrc];
        }
        __syncthreads();
        {
            float sacc[4][4] = {};
#pragma unroll
            for (int kk = 0; kk < 32; kk++) {
                float a[4], bq[4];
#pragma unroll
                for (int i = 0; i < 4; i++) a[i] = Qs[ty * 4 + i][kk];
#pragma unroll
                for (int j = 0; j < 4; j++) bq[j] = Ks[tx * 4 + j][kk];
#pragma unroll
                for (int i = 0; i < 4; i++)
#pragma unroll
                    for (int j = 0; j < 4; j++) sacc[i][j] = fmaf(a[i], bq[j], sacc[i][j]);
            }
#pragma unroll
            for (int i = 0; i < 4; i++)
#pragma unroll
                for (int j = 0; j < 4; j++)
                    Ps[ty * 4 + i][tx * 4 + j] = sacc[i][j] * sc;
        }
        __syncthreads();
        {
            int r = tid >> 2, sub = tid & 3;
            float mloc = -3.4e38f;
#pragma unroll
            for (int c = 0; c < 16; c++) mloc = fmaxf(mloc, Ps[r][sub * 16 + c]);
            mloc = fmaxf(mloc, __shfl_xor_sync(0xffffffff, mloc, 1));
            mloc = fmaxf(mloc, __shfl_xor_sync(0xffffffff, mloc, 2));
            float mold = rowm[r];
            float mnew = fmaxf(mold, mloc);
            float ssum = 0.f;
#pragma unroll
            for (int c = 0; c < 16; c++) {
                float e = expf(Ps[r][sub * 16 + c] - mnew);
                Ps[r][sub * 16 + c] = e;
                ssum += e;
            }
            ssum += __shfl_xor_sync(0xffffffff, ssum, 1);
            ssum += __shfl_xor_sync(0xffffffff, ssum, 2);
            if (sub == 0) {
                float scl = expf(mold - mnew);
                rowscale[r] = scl;
                rowl[r] = rowl[r] * scl + ssum;
                rowm[r] = mnew;
            }
        }
        __syncthreads();
#pragma unroll
        for (int j = 0; j < 8; j++) acc[j] *= rowscale[qg + j * 8];
#pragma unroll
        for (int kk = 0; kk < 64; kk++) {
            float vv = Vs[kk][d];
#pragma unroll
            for (int j = 0; j < 8; j++) acc[j] = fmaf(Ps[qg + j * 8][kk], vv, acc[j]);
        }
    }
#pragma unroll
    for (int j = 0; j < 8; j++) {
        int q = q0 + qg + j * 8;
        OCb[((size_t)(b << 9) + q) * 256 + d * NH + h] = acc[j] / rowl[qg + j * 8];
    }
}

// ---------------- MoE gating: warp-per-row, shuffle reductions only ----------------
// grid 256 blocks x 256 threads = 2048 warps? no: 8 warps/block * 256 blocks = 2048 rows.
__global__ void gating_kernel(const float* __restrict__ logits, float* __restrict__ raw,
                              float* __restrict__ g1, int* __restrict__ i1,
                              float* __restrict__ g2, int* __restrict__ i2) {
    int warp = (blockIdx.x << 3) + (threadIdx.x >> 5);   // row 0..2047
    int lane = threadIdx.x & 31;
    const float* p = logits + (size_t)warp * EE;
    float lv[32];
#pragma unroll
    for (int i = 0; i < 32; i++) lv[i] = p[i * 32 + lane];

    // ---- argmax (first-index tie-break) ----
    float bv = lv[0]; int bi = lane;
#pragma unroll
    for (int i = 1; i < 32; i++)
        if (lv[i] > bv) { bv = lv[i]; bi = i * 32 + lane; }
#pragma unroll
    for (int o = 16; o > 0; o >>= 1) {
        float ov = __shfl_xor_sync(0xffffffff, bv, o);
        int oi = __shfl_xor_sync(0xffffffff, bi, o);
        if (ov > bv || (ov == bv && oi < bi)) { bv = ov; bi = oi; }
    }
    float maxv = bv; int maxi = bi;

    // ---- softmax sum + raw write ----
    float s = 0.f;
#pragma unroll
    for (int i = 0; i < 32; i++) s += expf(lv[i] - maxv);
#pragma unroll
    for (int o = 16; o > 0; o >>= 1) s += __shfl_xor_sync(0xffffffff, s, o);
    float inv = 1.f / s;
    float* rp = raw + (size_t)warp * EE;
#pragma unroll
    for (int i = 0; i < 32; i++) rp[i * 32 + lane] = expf(lv[i] - maxv) * inv;

    // ---- second max excluding maxi ----
    float b2 = -3.4e38f; int b2i = 0;
#pragma unroll
    for (int i = 0; i < 32; i++) {
        int e = i * 32 + lane;
        if (e != maxi && lv[i] > b2) { b2 = lv[i]; b2i = e; }
    }
#pragma unroll
    for (int o = 16; o > 0; o >>= 1) {
        float ov = __shfl_xor_sync(0xffffffff, b2, o);
        int oi = __shfl_xor_sync(0xffffffff, b2i, o);
        if (ov > b2 || (ov == b2 && oi < b2i)) { b2 = ov; b2i = oi; }
    }

    if (lane == 0) {
        float gate1v = inv;
        float gate2v = expf(b2 - maxv) * inv;
        float denom = gate1v + gate2v + 1e-9f;
        g1[warp] = gate1v / denom;
        i1[warp] = maxi;
        g2[warp] = gate2v / denom;
        i2[warp] = b2i;
    }
}

// ---------------- per-(b,e) sum of raw over tokens ----------------
__global__ void rawsum_kernel(const float* __restrict__ raw, float* __restrict__ rawsum) {
    int b = blockIdx.x >> 2;
    int chunk = blockIdx.x & 3;
    int e = chunk * 256 + threadIdx.x;
    const float* p = raw + (size_t)b * NTOK * EE + e;
    float s = 0.f;
    for (int n = 0; n < NTOK; n++) s += p[(size_t)n * EE];
    rawsum[b * EE + e] = s;
}

// ---------------- routing with capacity ----------------
__global__ void routing_kernel(const int* __restrict__ idx1, const float* __restrict__ gate1,
                               const int* __restrict__ idx2, const float* __restrict__ gate2,
                               int* __restrict__ slot_tok, float* __restrict__ slot_gate,
                               float* __restrict__ cnt1_out) {
    int b = blockIdx.x;
    int tid = threadIdx.x;
    __shared__ int cnt[EE];
    __shared__ int mcnt[EE];
    for (int e = tid; e < EE; e += 256) cnt[e] = 0;
    for (int i = tid; i < EE * CAPP; i += 256) {
        slot_tok[b * EE * CAPP + i] = -1;
        slot_gate[b * EE * CAPP + i] = 0.f;
    }
    __syncthreads();
    if (tid == 0) {
        for (int n = 0; n < NTOK; n++) {
            int e = idx1[b * NTOK + n];
            int pcur = cnt[e]++;
            if (pcur < CAPP) {
                slot_tok[(b * EE + e) * CAPP + pcur] = n;
                slot_gate[(b * EE + e) * CAPP + pcur] = gate1[b * NTOK + n];
            }
        }
    }
    __syncthreads();
    for (int e = tid; e < EE; e += 256) {
        cnt1_out[b * EE + e] = (float)cnt[e];
        mcnt[e] = cnt[e] < CAPP ? cnt[e] : CAPP;
        cnt[e] = 0;
    }
    __syncthreads();
    if (tid == 0) {
        for (int n = 0; n < NTOK; n++) {
            int e = idx2[b * NTOK + n];
            int pcur = mcnt[e] + cnt[e];
            cnt[e]++;
            if (pcur < CAPP) {
                slot_tok[(b * EE + e) * CAPP + pcur] = n;
                slot_gate[(b * EE + e) * CAPP + pcur] = gate2[b * NTOK + n];
            }
        }
    }
}

// ---------------- expert FFN (float4 weight staging) ----------------
__global__ void expert_kernel(const float* __restrict__ xm, const float* __restrict__ w1,
                              const float* __restrict__ w2,
                              const int* __restrict__ slot_tok, const float* __restrict__ slot_gate,
                              float* __restrict__ out) {
    int e = blockIdx.x;
    int tid = threadIdx.x;
    extern __shared__ float sw[];
    __shared__ float hsh[32][33];
    __shared__ int stok[32];
    __shared__ float sgate[32];
    __shared__ int s_any;
    if (tid < 32) {
        int b = tid >> 2, c = tid & 3;
        stok[tid]  = slot_tok [(b * EE + e) * CAPP + c];
        sgate[tid] = slot_gate[(b * EE + e) * CAPP + c];
    }
    if (tid == 0) s_any = 0;
    __syncthreads();
    if (tid == 0) {
        int a = 0;
        for (int i = 0; i < 32; i++) a |= (stok[i] >= 0);
        s_any = a;
    }
    __syncthreads();
    if (!s_any) return;
    {
        const float4* w1v = (const float4*)(w1 + (size_t)e * DTOK * HIDD);
        float4* swv = (float4*)sw;
#pragma unroll
        for (int i = 0; i < 16; i++) swv[tid + i * 256] = w1v[tid + i * 256];
    }
    __syncthreads();
    int hid = tid & 31;
#pragma unroll
    for (int pass = 0; pass < 4; pass++) {
        int sidx = pass * 8 + (tid >> 5);
        int tok = stok[sidx];
        float acc = 0.f;
        if (tok >= 0) {
            const float* xr = xm + ((size_t)((sidx >> 2) * NTOK + tok)) * DTOK;
            for (int dd = 0; dd < DTOK; dd++) acc = fmaf(xr[dd], sw[dd * HIDD + hid], acc);
        }
        hsh[sidx][hid] = gelu_exact(acc);
    }
    __syncthreads();
    {
        const float4* w2v = (const float4*)(w2 + (size_t)e * HIDD * DTOK);
        float4* swv = (float4*)sw;
#pragma unroll
        for (int i = 0; i < 16; i++) swv[tid + i * 256] = w2v[tid + i * 256];
    }
    __syncthreads();
#pragma unroll
    for (int i = 0; i < 64; i++) {
        int idx = tid + i * 256;
        int sidx = idx >> 9;
        int dd = idx & 511;
        int tok = stok[sidx];
        float g = sgate[sidx];
        if (tok >= 0 && g != 0.f) {
            float acc = 0.f;
#pragma unroll
            for (int h2 = 0; h2 < HIDD; h2++) acc = fmaf(hsh[sidx][h2], sw[h2 * DTOK + dd], acc);
            atomicAdd(&out[((size_t)((sidx >> 2) * NTOK + tok)) * DTOK + dd], g * acc);
        }
    }
}

// ---------------- aux loss ----------------
__global__ void loss_kernel(const float* __restrict__ rawsum, const float* __restrict__ cnt1,
                            float* __restrict__ out_scalar) {
    __shared__ float red[256];
    int tid = threadIdx.x;
    float s = 0.f;
    for (int i = tid; i < BB * EE; i += 256) s += rawsum[i] * cnt1[i];
    red[tid] = s; __syncthreads();
    for (int o = 128; o > 0; o >>= 1) { if (tid < o) red[tid] += red[tid + o]; __syncthreads(); }
    if (tid == 0) out_scalar[0] = red[0] * 1.953125e-05f;
}

// ---------------- maxpool k=3 s=2 pad=1 ----------------
__global__ void maxpool_kernel(const float* __restrict__ yf, float* __restrict__ out) {
    int idx = blockIdx.x * 256 + threadIdx.x;
    int j = idx & 255;
    int o = (idx >> 8) & 511;
    int b = idx >> 17;
    const float* row = yf + ((size_t)(b * 512 + o)) * 512;
    int l = 2 * j;
    float m = row[l];
    if (l > 0) m = fmaxf(m, row[l - 1]);
    m = fmaxf(m, row[l + 1]);
    out[idx] = m;
}

// ---------------- host orchestration ----------------
extern "C" void kernel_launch(void* const* d_in, const int* in_sizes, int n_in,
                              void* d_out, int out_size) {
    const float* x        = (const float*)d_in[0];
    const float* emb      = (const float*)d_in[1];
    const float* rb1_g1s  = (const float*)d_in[2];
    const float* rb1_g1b  = (const float*)d_in[3];
    const float* rb1_c1w  = (const float*)d_in[4];
    const float* rb1_c1b  = (const float*)d_in[5];
    const float* rb1_g2s  = (const float*)d_in[6];
    const float* rb1_g2b  = (const float*)d_in[7];
    const float* rb1_c2w  = (const float*)d_in[8];
    const float* rb1_c2b  = (const float*)d_in[9];
    const float* rb2_g1s  = (const float*)d_in[10];
    const float* rb2_g1b  = (const float*)d_in[11];
    const float* rb2_c1w  = (const float*)d_in[12];
    const float* rb2_c1b  = (const float*)d_in[13];
    const float* rb2_g2s  = (const float*)d_in[14];
    const float* rb2_g2b  = (const float*)d_in[15];
    const float* rb2_c2w  = (const float*)d_in[16];
    const float* rb2_c2b  = (const float*)d_in[17];
    const float* attn_w1  = (const float*)d_in[18];
    const float* attn_b1  = (const float*)d_in[19];
    const float* attn_w2  = (const float*)d_in[20];
    const float* attn_b2  = (const float*)d_in[21];
    const float* moe_wg   = (const float*)d_in[22];
    const float* moe_w1   = (const float*)d_in[23];
    const float* moe_w2   = (const float*)d_in[24];
    const float* out_w    = (const float*)d_in[25];
    const float* out_b    = (const float*)d_in[26];
    float* out = (float*)d_out;

    float *px1, *pr, *pxa, *pt, *pq, *pk, *pv, *poc, *pxb, *pxm;
    float *plog, *praw, *pg1, *pg2, *prs, *pc1, *psg, *pmo, *pyf;
    int *pi1, *pi2, *pst;
    unsigned short *pwhi, *pwlo, *phhi, *phlo;
    cudaGetSymbolAddress((void**)&px1, g_x1);
    cudaGetSymbolAddress((void**)&pr,  g_r);
    cudaGetSymbolAddress((void**)&pxa, g_xa);
    cudaGetSymbolAddress((void**)&pt,  g_t);
    cudaGetSymbolAddress((void**)&pq,  g_q);
    cudaGetSymbolAddress((void**)&pk,  g_k);
    cudaGetSymbolAddress((void**)&pv,  g_v);
    cudaGetSymbolAddress((void**)&poc, g_oc);
    cudaGetSymbolAddress((void**)&pxb, g_xb);
    cudaGetSymbolAddress((void**)&pxm, g_xm);
    cudaGetSymbolAddress((void**)&plog, g_logits);
    cudaGetSymbolAddress((void**)&praw, g_raw);
    cudaGetSymbolAddress((void**)&pg1, g_gate1);
    cudaGetSymbolAddress((void**)&pg2, g_gate2);
    cudaGetSymbolAddress((void**)&pi1, g_i1);
    cudaGetSymbolAddress((void**)&pi2, g_i2);
    cudaGetSymbolAddress((void**)&prs, g_rawsum);
    cudaGetSymbolAddress((void**)&pc1, g_cnt1);
    cudaGetSymbolAddress((void**)&pst, g_slot_tok);
    cudaGetSymbolAddress((void**)&psg, g_slot_gate);
    cudaGetSymbolAddress((void**)&pmo, g_moeout);
    cudaGetSymbolAddress((void**)&pyf, g_yfull);
    cudaGetSymbolAddress((void**)&pwhi, g_whi);
    cudaGetSymbolAddress((void**)&pwlo, g_wlo);
    cudaGetSymbolAddress((void**)&phhi, g_hhi);
    cudaGetSymbolAddress((void**)&phlo, g_hlo);

    cudaFuncSetAttribute(expert_kernel, cudaFuncAttributeMaxDynamicSharedMemorySize, 65536);
    cudaFuncSetAttribute(conv_mma_kernel, cudaFuncAttributeMaxDynamicSharedMemorySize, MMA_SMEM);
    cudaFuncSetAttribute(gemm_mma<0,3>, cudaFuncAttributeMaxDynamicSharedMemorySize, MMA_SMEM);
    cudaFuncSetAttribute(gemm_mma<2,3>, cudaFuncAttributeMaxDynamicSharedMemorySize, MMA_SMEM);
    cudaFuncSetAttribute(gemm_mma<0,4>, cudaFuncAttributeMaxDynamicSharedMemorySize, MMA_SMEM);

    const int WSZc = WSZ;
    // ---- pre-convert weights ----
    cvt_hilo_kernel<<<768, 256>>>(rb1_c1w, pwhi,          pwlo,          WSZc);
    cvt_hilo_kernel<<<768, 256>>>(rb1_c2w, pwhi + WSZc,   pwlo + WSZc,   WSZc);
    cvt_hilo_kernel<<<768, 256>>>(rb2_c1w, pwhi + 2*WSZc, pwlo + 2*WSZc, WSZc);
    cvt_hilo_kernel<<<768, 256>>>(rb2_c2w, pwhi + 3*WSZc, pwlo + 3*WSZc, WSZc);
    cvt_hilo_kernel<<<1536, 256>>>(out_w,  pwhi + 4*WSZc, pwlo + 4*WSZc, 2*WSZc);
    cvtT_w_kernel<<<dim3(8, 24), dim3(32, 8)>>>(attn_w1, pwhi + OFF_WQKVT, pwlo + OFF_WQKVT, 256, 768);
    cvtT_w_kernel<<<dim3(8, 8),  dim3(32, 8)>>>(attn_w2, pwhi + OFF_W2T,   pwlo + OFF_W2T,   256, 256);
    cvtT_w_kernel<<<dim3(16, 32), dim3(32, 8)>>>(moe_wg, pwhi + OFF_WGT,   pwlo + OFF_WGT,   512, 1024);

    // ---- res block 1 ----
    gn_gelu_kernel<<<BB * NG, 256>>>(x, emb, rb1_g1s, rb1_g1b, px1, phhi, phlo);
    conv_mma_kernel<<<dim3(32, 4), 256, MMA_SMEM>>>(pwhi, pwlo, phhi, phlo, rb1_c1b, nullptr, pr, 256);
    gn_gelu_kernel<<<BB * NG, 256>>>(pr, nullptr, rb1_g2s, rb1_g2b, nullptr, phhi, phlo);
    conv_mma_kernel<<<dim3(32, 4), 256, MMA_SMEM>>>(pwhi + WSZc, pwlo + WSZc, phhi, phlo, rb1_c2b, px1, pxa, 256);

    // ---- attention ----
    cvtT_x_kernel<<<dim3(16, 8, 8), dim3(32, 8)>>>(pxa, phhi, phlo);
    gemm_mma<0,3><<<dim3(6, 64), 256, MMA_SMEM>>>(phhi, phlo, pwhi + OFF_WQKVT, pwlo + OFF_WQKVT,
                                                  attn_b1, pt, 4096, 768, 256);
    qkv_split_kernel<<<4096, 256>>>(pt, pq, pk, pv);
    fused_attn_kernel<<<dim3(8, 64), 256>>>(pq, pk, pv, poc);
    cvt_hilo_kernel<<<4096, 256>>>(poc, phhi, phlo, BB * LL * CC);
    gemm_mma<2,3><<<dim3(2, 64), 256, MMA_SMEM>>>(phhi, phlo, pwhi + OFF_W2T, pwlo + OFF_W2T,
                                                  attn_b2, pxb, 4096, 256, 256);

    // ---- res block 2 ----
    gn_gelu_kernel<<<BB * NG, 256>>>(pxb, emb, rb2_g1s, rb2_g1b, px1, phhi, phlo);
    conv_mma_kernel<<<dim3(32, 4), 256, MMA_SMEM>>>(pwhi + 2*WSZc, pwlo + 2*WSZc, phhi, phlo, rb2_c1b, nullptr, pr, 256);
    gn_gelu_kernel<<<BB * NG, 256>>>(pr, nullptr, rb2_g2s, rb2_g2b, nullptr, phhi, phlo);
    conv_mma_kernel<<<dim3(32, 4), 256, MMA_SMEM>>>(pwhi + 3*WSZc, pwlo + 3*WSZc, phhi, phlo, rb2_c2b, px1, pxm, 256);

    // ---- MoE ----
    cvt_hilo_kernel<<<4096, 256>>>(pxm, phhi, phlo, BB * CC * LL);
    gemm_mma<0,4><<<dim3(8, 32), 256, MMA_SMEM>>>(phhi, phlo, pwhi + OFF_WGT, pwlo + OFF_WGT,
                                                  nullptr, plog, 2048, 1024, 512);
    gating_kernel<<<256, 256>>>(plog, praw, pg1, pi1, pg2, pi2);
    rawsum_kernel<<<32, 256>>>(praw, prs);
    routing_kernel<<<BB, 256>>>(pi1, pg1, pi2, pg2, pst, psg, pc1);
    cudaMemsetAsync(pmo, 0, sizeof(float) * BB * CC * LL);
    expert_kernel<<<EE, 256, 65536>>>(pxm, moe_w1, moe_w2, pst, psg, pmo);
    loss_kernel<<<1, 256>>>(prs, pc1, out + 2097152);

    // ---- output conv + maxpool ----
    cvt_hilo_kernel<<<4096, 256>>>(pmo, phhi, phlo, BB * CC * LL);
    conv_mma_kernel<<<dim3(32, 8), 256, MMA_SMEM>>>(pwhi + 4*WSZc, pwlo + 4*WSZc, phhi, phlo, out_b, nullptr, pyf, 512);
    maxpool_kernel<<<4096, 256>>>(pyf, out);

    // second output: moe result x (B,C,L)
    cudaMemcpyAsync(out + 1048576, pmo, sizeof(float) * BB * CC * LL, cudaMemcpyDeviceToDevice);
}

// round 14
// speedup vs baseline: 1.0452x; 1.0362x over previous
#include <cuda_runtime.h>
#include <cuda_bf16.h>
#include <math.h>
#include <stdint.h>

// ---------------- problem constants ----------------
#define BB   8
#define CC   256
#define LL   512
#define NG   32
#define CPG  8
#define NH   8
#define DH   32
#define EE   1024
#define HIDD 32
#define CAPP 4
#define NTOK 256
#define DTOK 512

// ---------------- scratch (device globals; allocation-free) ----------------
__device__ float g_x1[BB*CC*LL];
__device__ float g_r [BB*CC*LL];
__device__ float g_xa[BB*CC*LL];
__device__ float g_t [BB*LL*3*CC];
__device__ float g_q [BB*NH*LL*DH];
__device__ float g_k [BB*NH*LL*DH];
__device__ float g_v [BB*NH*LL*DH];
__device__ float g_oc[BB*LL*CC];
__device__ float g_xb[BB*CC*LL];
__device__ float g_xm[BB*CC*LL];
__device__ float g_logits[BB*NTOK*EE];
__device__ float g_raw  [BB*NTOK*EE];
__device__ float g_gate1[BB*NTOK];
__device__ float g_gate2[BB*NTOK];
__device__ int   g_i1[BB*NTOK];
__device__ int   g_i2[BB*NTOK];
__device__ float g_rawsum[BB*EE];
__device__ float g_cnt1 [BB*EE];
__device__ int   g_slot_tok [BB*EE*CAPP];
__device__ float g_slot_gate[BB*EE*CAPP];
__device__ float g_moeout[BB*CC*LL];
__device__ float g_yfull[(size_t)BB*2*CC*LL];
// bf16 operand buffers: weights separate hi/lo, activations packed (hi | lo<<16)
#define WSZ 196608
#define OFF_WQKVT (6*WSZ)
#define OFF_W2T   (OFF_WQKVT + 196608)
#define OFF_WGT   (OFF_W2T + 65536)
#define WTOT      (OFF_WGT + 524288)
__device__ unsigned short g_whi[WTOT];
__device__ unsigned short g_wlo[WTOT];
__device__ uint32_t g_hpk[BB*CC*LL];

__device__ __forceinline__ float gelu_exact(float v) {
    return 0.5f * v * (1.0f + erff(v * 0.7071067811865476f));
}
__device__ __forceinline__ void split_bf16(float v, unsigned short& h, unsigned short& l) {
    __nv_bfloat16 hb = __float2bfloat16(v);
    __nv_bfloat16 lb = __float2bfloat16(v - __bfloat162float(hb));
    h = *(unsigned short*)&hb;
    l = *(unsigned short*)&lb;
}
__device__ __forceinline__ uint32_t pack_bf16(float v) {
    unsigned short h, l;
    split_bf16(v, h, l);
    return (uint32_t)h | ((uint32_t)l << 16);
}

// ---------------- float -> packed bf16 hi/lo conversion ----------------
__global__ void cvt_pk_kernel(const float* __restrict__ src, uint32_t* __restrict__ pk, int n) {
    int i = blockIdx.x * 256 + threadIdx.x;
    if (i < n) pk[i] = pack_bf16(src[i]);
}

// ---------------- ONE fused weight conversion kernel (replaces 8 launches) ----------------
// blocks [0,4608): row-major hi/lo cvts (4x conv 768 blocks each, out_w 1536 blocks)
// blocks [4608,5376): 32x32 transpose tiles (attn_w1 192, attn_w2 64, moe_wg 512)
__global__ void cvt_weights_kernel(const float* __restrict__ w0, const float* __restrict__ w1,
                                   const float* __restrict__ w2, const float* __restrict__ w3,
                                   const float* __restrict__ w4,
                                   const float* __restrict__ tw0, const float* __restrict__ tw1,
                                   const float* __restrict__ tw2,
                                   unsigned short* __restrict__ whi, unsigned short* __restrict__ wlo) {
    __shared__ float tile[32][33];
    int b = blockIdx.x, tid = threadIdx.x;
    if (b < 4608) {
        const float* src;
        size_t off;
        int base;
        if (b < 3072) {
            int s = b / 768;
            src = (s == 0) ? w0 : (s == 1) ? w1 : (s == 2) ? w2 : w3;
            off = (size_t)s * WSZ;
            base = (b - s * 768) * 256;
        } else {
            src = w4; off = (size_t)4 * WSZ; base = (b - 3072) * 256;
        }
        int i = base + tid;
        unsigned short h, l;
        split_bf16(src[i], h, l);
        whi[off + i] = h; wlo[off + i] = l;
    } else {
        int t = b - 4608;
        const float* W; int K, N; size_t off; int tk, tn;
        if (t < 192)      { W = tw0; K = 256; N = 768;  off = OFF_WQKVT; tk = t & 7;  tn = t >> 3; }
        else if (t < 256) { t -= 192; W = tw1; K = 256; N = 256; off = OFF_W2T; tk = t & 7;  tn = t >> 3; }
        else              { t -= 256; W = tw2; K = 512; N = 1024; off = OFF_WGT; tk = t & 15; tn = t >> 4; }
        int x = tid & 31, y = tid >> 5;       // 32x8
        int k0 = tk * 32, n0 = tn * 32;
#pragma unroll
        for (int i = 0; i < 32; i += 8)
            tile[y + i][x] = W[(size_t)(k0 + y + i) * N + n0 + x];
        __syncthreads();
#pragma unroll
        for (int i = 0; i < 32; i += 8) {
            unsigned short h, l;
            split_bf16(tile[x][y + i], h, l);
            size_t o = off + (size_t)(n0 + y + i) * K + k0 + x;
            whi[o] = h; wlo[o] = l;
        }
    }
}

// ---------------- transposed activation cvt: xa(B,C,L) -> A[(b*L+l)][C] packed ----------------
__global__ void cvtT_x_kernel(const float* __restrict__ X, uint32_t* __restrict__ apk) {
    __shared__ float tile[32][33];
    int b = blockIdx.z;
    int l0 = blockIdx.x * 32, c0 = blockIdx.y * 32;
    int x = threadIdx.x, y = threadIdx.y;
#pragma unroll
    for (int i = 0; i < 32; i += 8)
        tile[y + i][x] = X[(((size_t)(b * CC + c0 + y + i)) << 9) + l0 + x];
    __syncthreads();
#pragma unroll
    for (int i = 0; i < 32; i += 8)
        apk[(size_t)(b * LL + l0 + y + i) * CC + c0 + x] = pack_bf16(tile[x][y + i]);
}

// ================= warp-level bf16 MMA (m16n8k16, f32 accum) =================
__device__ __forceinline__ void mma16816(float* c, const uint32_t* a, const uint32_t* b) {
    asm volatile("mma.sync.aligned.m16n8k16.row.col.f32.bf16.bf16.f32 "
        "{%0,%1,%2,%3}, {%4,%5,%6,%7}, {%8,%9}, {%0,%1,%2,%3};"
        : "+f"(c[0]), "+f"(c[1]), "+f"(c[2]), "+f"(c[3])
        : "r"(a[0]), "r"(a[1]), "r"(a[2]), "r"(a[3]), "r"(b[0]), "r"(b[1]));
}

#define CPITCH 72
#define OFF_AHI 0
#define OFF_ALO (64*CPITCH)
#define OFF_BHI (2*64*CPITCH)
#define OFF_BLO (2*64*CPITCH + 128*CPITCH)
#define MMA_SMEM ((2*64*CPITCH + 2*128*CPITCH) * 2)   // 55296 bytes

// ================= tensor-core conv1d(k=3,pad=1); X packed =================
__global__ void __launch_bounds__(256, 2)
conv_mma_kernel(const unsigned short* __restrict__ Whi, const unsigned short* __restrict__ Wlo,
                const uint32_t* __restrict__ Xpk,
                const float* __restrict__ bias, const float* __restrict__ res,
                float* __restrict__ Y, int M) {
    extern __shared__ unsigned short sm[];
    int tid = threadIdx.x;
    int wid = tid >> 5, lane = tid & 31;
    int g = lane >> 2, tg = lane & 3;
    int warp_m = wid & 1, warp_n = wid >> 1;
    int n0 = blockIdx.x * 128, m0 = blockIdx.y * 64;
    int bI = n0 >> 9, l0 = n0 & 511;

    const unsigned short* Wh = Whi + (size_t)m0 * 768;
    const unsigned short* Wl = Wlo + (size_t)m0 * 768;
    const uint32_t* Xp = Xpk + (((size_t)bI * CC) << 9);

    float acc[2][4][4];
#pragma unroll
    for (int mi = 0; mi < 2; mi++)
#pragma unroll
        for (int ni = 0; ni < 4; ni++)
#pragma unroll
            for (int r = 0; r < 4; r++) acc[mi][ni][r] = 0.f;

    int fa_m = tid >> 2, fa_k = (tid & 3) * 16;
    int fb_n = tid >> 1, fb_h = (tid & 1) * 32;

    for (int c = 0; c < 12; c++) {
        int c64 = c * 64;
        {
            const unsigned short* ph = Wh + (size_t)fa_m * 768 + c64 + fa_k;
            const unsigned short* pl = Wl + (size_t)fa_m * 768 + c64 + fa_k;
            *(uint4*)&sm[OFF_AHI + fa_m * CPITCH + fa_k]     = *(const uint4*)ph;
            *(uint4*)&sm[OFF_AHI + fa_m * CPITCH + fa_k + 8] = *(const uint4*)(ph + 8);
            *(uint4*)&sm[OFF_ALO + fa_m * CPITCH + fa_k]     = *(const uint4*)pl;
            *(uint4*)&sm[OFF_ALO + fa_m * CPITCH + fa_k + 8] = *(const uint4*)(pl + 8);
        }
        {
            int kg = c64 + fb_h;
            int ic = kg / 3, t = kg - 3 * ic;
            int l = l0 + fb_n;
            unsigned short* dh = &sm[OFF_BHI + fb_n * CPITCH + fb_h];
            unsigned short* dl = &sm[OFF_BLO + fb_n * CPITCH + fb_h];
#pragma unroll 8
            for (int i = 0; i < 32; i++) {
                int ll = l + t - 1;
                bool ok = ((unsigned)ll < 512u);
                uint32_t v = ok ? Xp[(ic << 9) + ll] : 0u;
                dh[i] = (unsigned short)v;
                dl[i] = (unsigned short)(v >> 16);
                if (++t == 3) { t = 0; ++ic; }
            }
        }
        __syncthreads();
#pragma unroll
        for (int ks = 0; ks < 4; ks++) {
            int k0 = ks * 16;
            uint32_t ahi[2][4], alo[2][4], bhi[4][2], blo[4][2];
#pragma unroll
            for (int mi = 0; mi < 2; mi++) {
                int r0 = warp_m * 32 + mi * 16 + g;
                const unsigned short* p0 = &sm[OFF_AHI + r0 * CPITCH + k0 + tg * 2];
                const unsigned short* p1 = p0 + 8 * CPITCH;
                ahi[mi][0] = *(const uint32_t*)p0;
                ahi[mi][1] = *(const uint32_t*)p1;
                ahi[mi][2] = *(const uint32_t*)(p0 + 8);
                ahi[mi][3] = *(const uint32_t*)(p1 + 8);
                const unsigned short* q0 = &sm[OFF_ALO + r0 * CPITCH + k0 + tg * 2];
                const unsigned short* q1 = q0 + 8 * CPITCH;
                alo[mi][0] = *(const uint32_t*)q0;
                alo[mi][1] = *(const uint32_t*)q1;
                alo[mi][2] = *(const uint32_t*)(q0 + 8);
                alo[mi][3] = *(const uint32_t*)(q1 + 8);
            }
#pragma unroll
            for (int ni = 0; ni < 4; ni++) {
                int nr = warp_n * 32 + ni * 8 + g;
                const unsigned short* p = &sm[OFF_BHI + nr * CPITCH + k0 + tg * 2];
                bhi[ni][0] = *(const uint32_t*)p;
                bhi[ni][1] = *(const uint32_t*)(p + 8);
                const unsigned short* q = &sm[OFF_BLO + nr * CPITCH + k0 + tg * 2];
                blo[ni][0] = *(const uint32_t*)q;
                blo[ni][1] = *(const uint32_t*)(q + 8);
            }
#pragma unroll
            for (int mi = 0; mi < 2; mi++)
#pragma unroll
                for (int ni = 0; ni < 4; ni++) {
                    mma16816(acc[mi][ni], ahi[mi], bhi[ni]);
                    mma16816(acc[mi][ni], ahi[mi], blo[ni]);
                    mma16816(acc[mi][ni], alo[mi], bhi[ni]);
                }
        }
        __syncthreads();
    }

#pragma unroll
    for (int mi = 0; mi < 2; mi++) {
        int m = m0 + warp_m * 32 + mi * 16 + g;
        float bs0 = bias[m], bs1 = bias[m + 8];
        size_t row0 = (((size_t)bI * M + m) << 9) + l0;
        size_t row1 = (((size_t)bI * M + m + 8) << 9) + l0;
#pragma unroll
        for (int ni = 0; ni < 4; ni++) {
            int ncol = warp_n * 32 + ni * 8 + tg * 2;
            float2 v0 = make_float2(acc[mi][ni][0] + bs0, acc[mi][ni][1] + bs0);
            float2 v1 = make_float2(acc[mi][ni][2] + bs1, acc[mi][ni][3] + bs1);
            if (res) {
                float2 r0 = *(const float2*)&res[row0 + ncol];
                float2 r1 = *(const float2*)&res[row1 + ncol];
                v0.x += r0.x; v0.y += r0.y; v1.x += r1.x; v1.y += r1.y;
            }
            *(float2*)&Y[row0 + ncol] = v0;
            *(float2*)&Y[row1 + ncol] = v1;
        }
    }
}

// ================= generic tensor-core GEMM: A packed, B hi/lo =================
template<int CM, int NT>
__global__ void __launch_bounds__(256, 2)
gemm_mma(const uint32_t* __restrict__ Apk,
         const unsigned short* __restrict__ Bthi, const unsigned short* __restrict__ Btlo,
         const float* __restrict__ bias, float* __restrict__ C, int M, int N, int K) {
    extern __shared__ unsigned short sm[];
    int tid = threadIdx.x;
    int wid = tid >> 5, lane = tid & 31;
    int g = lane >> 2, tg = lane & 3;
    int warp_m = wid & 1, warp_n = wid >> 1;
    int n0 = blockIdx.x * 128, m0 = blockIdx.y * 64;

    const uint32_t* Ap = Apk + (size_t)m0 * K;
    const unsigned short* Bh = Bthi + (size_t)n0 * K;
    const unsigned short* Bl = Btlo + (size_t)n0 * K;

    float acc[2][4][4];
#pragma unroll
    for (int mi = 0; mi < 2; mi++)
#pragma unroll
        for (int ni = 0; ni < 4; ni++)
#pragma unroll
            for (int r = 0; r < 4; r++) acc[mi][ni][r] = 0.f;

    int fa_m = tid >> 2, fa_k = (tid & 3) * 16;
    int fb_n = tid >> 1, fb_h = (tid & 1) * 32;
    int nchunks = K >> 6;

    for (int c = 0; c < nchunks; c++) {
        int c64 = c << 6;
        {
            const uint32_t* pa = Ap + (size_t)fa_m * K + c64 + fa_k;
            uint4 p0 = *(const uint4*)pa;
            uint4 p1 = *(const uint4*)(pa + 4);
            uint4 p2 = *(const uint4*)(pa + 8);
            uint4 p3 = *(const uint4*)(pa + 12);
            uint4 h0, h1, l0v, l1v;
            h0.x = __byte_perm(p0.x, p0.y, 0x5410); h0.y = __byte_perm(p0.z, p0.w, 0x5410);
            h0.z = __byte_perm(p1.x, p1.y, 0x5410); h0.w = __byte_perm(p1.z, p1.w, 0x5410);
            h1.x = __byte_perm(p2.x, p2.y, 0x5410); h1.y = __byte_perm(p2.z, p2.w, 0x5410);
            h1.z = __byte_perm(p3.x, p3.y, 0x5410); h1.w = __byte_perm(p3.z, p3.w, 0x5410);
            l0v.x = __byte_perm(p0.x, p0.y, 0x7632); l0v.y = __byte_perm(p0.z, p0.w, 0x7632);
            l0v.z = __byte_perm(p1.x, p1.y, 0x7632); l0v.w = __byte_perm(p1.z, p1.w, 0x7632);
            l1v.x = __byte_perm(p2.x, p2.y, 0x7632); l1v.y = __byte_perm(p2.z, p2.w, 0x7632);
            l1v.z = __byte_perm(p3.x, p3.y, 0x7632); l1v.w = __byte_perm(p3.z, p3.w, 0x7632);
            *(uint4*)&sm[OFF_AHI + fa_m * CPITCH + fa_k]     = h0;
            *(uint4*)&sm[OFF_AHI + fa_m * CPITCH + fa_k + 8] = h1;
            *(uint4*)&sm[OFF_ALO + fa_m * CPITCH + fa_k]     = l0v;
            *(uint4*)&sm[OFF_ALO + fa_m * CPITCH + fa_k + 8] = l1v;
        }
        {
            const unsigned short* ph = Bh + (size_t)fb_n * K + c64 + fb_h;
            const unsigned short* pl = Bl + (size_t)fb_n * K + c64 + fb_h;
            unsigned short* dh = &sm[OFF_BHI + fb_n * CPITCH + fb_h];
            unsigned short* dl = &sm[OFF_BLO + fb_n * CPITCH + fb_h];
#pragma unroll
            for (int i = 0; i < 4; i++) {
                *(uint4*)(dh + i * 8) = *(const uint4*)(ph + i * 8);
                *(uint4*)(dl + i * 8) = *(const uint4*)(pl + i * 8);
            }
        }
        __syncthreads();
#pragma unroll
        for (int ks = 0; ks < 4; ks++) {
            int k0 = ks * 16;
            uint32_t ahi[2][4], alo[2][4], bhi[4][2], blo[4][2];
#pragma unroll
            for (int mi = 0; mi < 2; mi++) {
                int r0 = warp_m * 32 + mi * 16 + g;
                const unsigned short* p0 = &sm[OFF_AHI + r0 * CPITCH + k0 + tg * 2];
                const unsigned short* p1 = p0 + 8 * CPITCH;
                ahi[mi][0] = *(const uint32_t*)p0;
                ahi[mi][1] = *(const uint32_t*)p1;
                ahi[mi][2] = *(const uint32_t*)(p0 + 8);
                ahi[mi][3] = *(const uint32_t*)(p1 + 8);
                const unsigned short* q0 = &sm[OFF_ALO + r0 * CPITCH + k0 + tg * 2];
                const unsigned short* q1 = q0 + 8 * CPITCH;
                alo[mi][0] = *(const uint32_t*)q0;
                alo[mi][1] = *(const uint32_t*)q1;
                alo[mi][2] = *(const uint32_t*)(q0 + 8);
                alo[mi][3] = *(const uint32_t*)(q1 + 8);
            }
#pragma unroll
            for (int ni = 0; ni < 4; ni++) {
                int nr = warp_n * 32 + ni * 8 + g;
                const unsigned short* p = &sm[OFF_BHI + nr * CPITCH + k0 + tg * 2];
                bhi[ni][0] = *(const uint32_t*)p;
                bhi[ni][1] = *(const uint32_t*)(p + 8);
                const unsigned short* q = &sm[OFF_BLO + nr * CPITCH + k0 + tg * 2];
                blo[ni][0] = *(const uint32_t*)q;
                blo[ni][1] = *(const uint32_t*)(q + 8);
            }
#pragma unroll
            for (int mi = 0; mi < 2; mi++)
#pragma unroll
                for (int ni = 0; ni < 4; ni++) {
                    mma16816(acc[mi][ni], ahi[mi], bhi[ni]);
                    mma16816(acc[mi][ni], ahi[mi], blo[ni]);
                    mma16816(acc[mi][ni], alo[mi], bhi[ni]);
                    if (NT == 4) mma16816(acc[mi][ni], alo[mi], blo[ni]);
                }
        }
        __syncthreads();
    }

    if (CM == 0) {
#pragma unroll
        for (int mi = 0; mi < 2; mi++) {
            int m = m0 + warp_m * 32 + mi * 16 + g;
#pragma unroll
            for (int ni = 0; ni < 4; ni++) {
                int n = n0 + warp_n * 32 + ni * 8 + tg * 2;
                float b0 = bias ? bias[n] : 0.f;
                float b1 = bias ? bias[n + 1] : 0.f;
                *(float2*)&C[(size_t)m * N + n] =
                    make_float2(acc[mi][ni][0] + b0, acc[mi][ni][1] + b1);
                *(float2*)&C[(size_t)(m + 8) * N + n] =
                    make_float2(acc[mi][ni][2] + b0, acc[mi][ni][3] + b1);
            }
        }
    } else {  // CTRANS
#pragma unroll
        for (int mi = 0; mi < 2; mi++) {
            int m = m0 + warp_m * 32 + mi * 16 + g;
            int bI = m >> 9, l = m & 511;
#pragma unroll
            for (int ni = 0; ni < 4; ni++) {
                int n = n0 + warp_n * 32 + ni * 8 + tg * 2;
                float b0 = bias ? bias[n] : 0.f;
                float b1 = bias ? bias[n + 1] : 0.f;
                C[(((size_t)(bI * N + n)) << 9) + l]           = acc[mi][ni][0] + b0;
                C[(((size_t)(bI * N + n + 1)) << 9) + l]       = acc[mi][ni][1] + b1;
                C[(((size_t)(bI * N + n)) << 9) + l + 8]       = acc[mi][ni][2] + b0;
                C[(((size_t)(bI * N + n + 1)) << 9) + l + 8]   = acc[mi][ni][3] + b1;
            }
        }
    }
}

// ---------------- GroupNorm (+optional emb add) + GELU, fused; packed bf16 output ----------------
__global__ void gn_gelu_kernel(const float* __restrict__ xin, const float* __restrict__ emb,
                               const float* __restrict__ scale, const float* __restrict__ bias,
                               float* __restrict__ x1_out, uint32_t* __restrict__ hpk) {
    int b = blockIdx.x >> 5;
    int g = blockIdx.x & 31;
    size_t base = ((size_t)b * CC + g * CPG) * LL;
    __shared__ float vals[CPG * LL];
    __shared__ float red[256];
    int tid = threadIdx.x;
    float s = 0.f, s2 = 0.f;
#pragma unroll
    for (int i = 0; i < 16; i++) {
        int j = tid + i * 256;
        float v = xin[base + j];
        if (emb) v += emb[base + j];
        vals[j] = v;
        s += v;
        s2 = fmaf(v, v, s2);
    }
    red[tid] = s; __syncthreads();
    for (int o = 128; o > 0; o >>= 1) { if (tid < o) red[tid] += red[tid + o]; __syncthreads(); }
    float mean = red[0] * (1.f / 4096.f);
    __syncthreads();
    red[tid] = s2; __syncthreads();
    for (int o = 128; o > 0; o >>= 1) { if (tid < o) red[tid] += red[tid + o]; __syncthreads(); }
    float var = red[0] * (1.f / 4096.f) - mean * mean;
    float rsig = rsqrtf(var + 1e-5f);
#pragma unroll
    for (int i = 0; i < 16; i++) {
        int j = tid + i * 256;
        int c = g * CPG + (j >> 9);
        float v = vals[j];
        if (x1_out) x1_out[base + j] = v;
        float nn = (v - mean) * rsig * scale[c] + bias[c];
        hpk[base + j] = pack_bf16(gelu_exact(nn));
    }
}

// ---------------- qkv split ----------------
__global__ void qkv_split_kernel(const float* __restrict__ t, float* __restrict__ Q,
                                 float* __restrict__ K, float* __restrict__ V) {
    int idx = blockIdx.x * 256 + threadIdx.x;
    int d = idx & 31;
    int l = (idx >> 5) & 511;
    int h = (idx >> 14) & 7;
    int b = idx >> 17;
    size_t base = ((size_t)(b * LL + l)) * 768 + (size_t)(d * NH + h) * 3;
    int o = ((b * NH + h) * LL + l) * DH + d;
    Q[o] = t[base];
    K[o] = t[base + 1];
    V[o] = t[base + 2];
}

// ---------------- fused flash attention ----------------
__global__ void fused_attn_kernel(const float* __restrict__ Q, const float* __restrict__ K,
                                  const float* __restrict__ V, float* __restrict__ OCb) {
    int bh = blockIdx.y;
    int q0 = blockIdx.x * 64;
    int b = bh >> 3, h = bh & 7;
    __shared__ float Qs[64][33];
    __shared__ float Ks[64][33];
    __shared__ float Vs[64][33];
    __shared__ float Ps[64][65];
    __shared__ float rowm[64], rowl[64], rowscale[64];
    int tid = threadIdx.x;
    int d = tid & 31, qg = tid >> 5;
    int tx = tid & 15, ty = tid >> 4;
    const float sc = 0.17677669529663687f;

#pragma unroll
    for (int i = 0; i < 8; i++) {
        int idx = tid + i * 256;
        int r = idx >> 5, dd = idx & 31;
        Qs[r][dd] = Q[((size_t)(bh << 9) + q0 + r) * 32 + dd];
    }
    if (tid < 64) { rowm[tid] = -3.4e38f; rowl[tid] = 0.f; }
    float acc[8];
#pragma unroll
    for (int j = 0; j < 8; j++) acc[j] = 0.f;

    for (int k0 = 0; k0 < 512; k0 += 64) {
        __syncthreads();
#pragma unroll
        for (int i = 0; i < 8; i++) {
            int idx = tid + i * 256;
            int r = idx >> 5, dd = idx & 31;
            size_t gsrc = ((size_t)(bh << 9) + k0 + r) * 32 + dd;
            Ks[r][dd] = K[gsrc];
            Vs[r][dd] = V[gsrc];
        }
        __syncthreads();
        {
            float sacc[4][4] = {};
#pragma unroll
            for (int kk = 0; kk < 32; kk++) {
                float a[4], bq[4];
#pragma unroll
                for (int i = 0; i < 4; i++) a[i] = Qs[ty * 4 + i][kk];
#pragma unroll
                for (int j = 0; j < 4; j++) bq[j] = Ks[tx * 4 + j][kk];
#pragma unroll
                for (int i = 0; i < 4; i++)
#pragma unroll
                    for (int j = 0; j < 4; j++) sacc[i][j] = fmaf(a[i], bq[j], sacc[i][j]);
            }
#pragma unroll
            for (int i = 0; i < 4; i++)
#pragma unroll
                for (int j = 0; j < 4; j++)
                    Ps[ty * 4 + i][tx * 4 + j] = sacc[i][j] * sc;
        }
        __syncthreads();
        {
            int r = tid >> 2, sub = tid & 3;
            float mloc = -3.4e38f;
#pragma unroll
            for (int c = 0; c < 16; c++) mloc = fmaxf(mloc, Ps[r][sub * 16 + c]);
            mloc = fmaxf(mloc, __shfl_xor_sync(0xffffffff, mloc, 1));
            mloc = fmaxf(mloc, __shfl_xor_sync(0xffffffff, mloc, 2));
            float mold = rowm[r];
            float mnew = fmaxf(mold, mloc);
            float ssum = 0.f;
#pragma unroll
            for (int c = 0; c < 16; c++) {
                float e = expf(Ps[r][sub * 16 + c] - mnew);
                Ps[r][sub * 16 + c] = e;
                ssum += e;
            }
            ssum += __shfl_xor_sync(0xffffffff, ssum, 1);
            ssum += __shfl_xor_sync(0xffffffff, ssum, 2);
            if (sub == 0) {
                float scl = expf(mold - mnew);
                rowscale[r] = scl;
                rowl[r] = rowl[r] * scl + ssum;
                rowm[r] = mnew;
            }
        }
        __syncthreads();
#pragma unroll
        for (int j = 0; j < 8; j++) acc[j] *= rowscale[qg + j * 8];
#pragma unroll
        for (int kk = 0; kk < 64; kk++) {
            float vv = Vs[kk][d];
#pragma unroll
            for (int j = 0; j < 8; j++) acc[j] = fmaf(Ps[qg + j * 8][kk], vv, acc[j]);
        }
    }
#pragma unroll
    for (int j = 0; j < 8; j++) {
        int q = q0 + qg + j * 8;
        OCb[((size_t)(b << 9) + q) * 256 + d * NH + h] = acc[j] / rowl[qg + j * 8];
    }
}

// ---------------- MoE gating: warp-per-row ----------------
__global__ void gating_kernel(const float* __restrict__ logits, float* __restrict__ raw,
                              float* __restrict__ g1, int* __restrict__ i1,
                              float* __restrict__ g2, int* __restrict__ i2) {
    int warp = (blockIdx.x << 3) + (threadIdx.x >> 5);
    int lane = threadIdx.x & 31;
    const float* p = logits + (size_t)warp * EE;
    float lv[32];
#pragma unroll
    for (int i = 0; i < 32; i++) lv[i] = p[i * 32 + lane];

    float bv = lv[0]; int bi = lane;
#pragma unroll
    for (int i = 1; i < 32; i++)
        if (lv[i] > bv) { bv = lv[i]; bi = i * 32 + lane; }
#pragma unroll
    for (int o = 16; o > 0; o >>= 1) {
        float ov = __shfl_xor_sync(0xffffffff, bv, o);
        int oi = __shfl_xor_sync(0xffffffff, bi, o);
        if (ov > bv || (ov == bv && oi < bi)) { bv = ov; bi = oi; }
    }
    float maxv = bv; int maxi = bi;

    float s = 0.f;
#pragma unroll
    for (int i = 0; i < 32; i++) s += expf(lv[i] - maxv);
#pragma unroll
    for (int o = 16; o > 0; o >>= 1) s += __shfl_xor_sync(0xffffffff, s, o);
    float inv = 1.f / s;
    float* rp = raw + (size_t)warp * EE;
#pragma unroll
    for (int i = 0; i < 32; i++) rp[i * 32 + lane] = expf(lv[i] - maxv) * inv;

    float b2 = -3.4e38f; int b2i = 0;
#pragma unroll
    for (int i = 0; i < 32; i++) {
        int e = i * 32 + lane;
        if (e != maxi && lv[i] > b2) { b2 = lv[i]; b2i = e; }
    }
#pragma unroll
    for (int o = 16; o > 0; o >>= 1) {
        float ov = __shfl_xor_sync(0xffffffff, b2, o);
        int oi = __shfl_xor_sync(0xffffffff, b2i, o);
        if (ov > b2 || (ov == b2 && oi < b2i)) { b2 = ov; b2i = oi; }
    }

    if (lane == 0) {
        float gate1v = inv;
        float gate2v = expf(b2 - maxv) * inv;
        float denom = gate1v + gate2v + 1e-9f;
        g1[warp] = gate1v / denom;
        i1[warp] = maxi;
        g2[warp] = gate2v / denom;
        i2[warp] = b2i;
    }
}

// ---------------- per-(b,e) sum of raw over tokens ----------------
__global__ void rawsum_kernel(const float* __restrict__ raw, float* __restrict__ rawsum) {
    int b = blockIdx.x >> 2;
    int chunk = blockIdx.x & 3;
    int e = chunk * 256 + threadIdx.x;
    const float* p = raw + (size_t)b * NTOK * EE + e;
    float s = 0.f;
    for (int n = 0; n < NTOK; n++) s += p[(size_t)n * EE];
    rawsum[b * EE + e] = s;
}

// ---------------- routing with capacity ----------------
__global__ void routing_kernel(const int* __restrict__ idx1, const float* __restrict__ gate1,
                               const int* __restrict__ idx2, const float* __restrict__ gate2,
                               int* __restrict__ slot_tok, float* __restrict__ slot_gate,
                               float* __restrict__ cnt1_out) {
    int b = blockIdx.x;
    int tid = threadIdx.x;
    __shared__ int cnt[EE];
    __shared__ int mcnt[EE];
    for (int e = tid; e < EE; e += 256) cnt[e] = 0;
    for (int i = tid; i < EE * CAPP; i += 256) {
        slot_tok[b * EE * CAPP + i] = -1;
        slot_gate[b * EE * CAPP + i] = 0.f;
    }
    __syncthreads();
    if (tid == 0) {
        for (int n = 0; n < NTOK; n++) {
            int e = idx1[b * NTOK + n];
            int pcur = cnt[e]++;
            if (pcur < CAPP) {
                slot_tok[(b * EE + e) * CAPP + pcur] = n;
                slot_gate[(b * EE + e) * CAPP + pcur] = gate1[b * NTOK + n];
            }
        }
    }
    __syncthreads();
    for (int e = tid; e < EE; e += 256) {
        cnt1_out[b * EE + e] = (float)cnt[e];
        mcnt[e] = cnt[e] < CAPP ? cnt[e] : CAPP;
        cnt[e] = 0;
    }
    __syncthreads();
    if (tid == 0) {
        for (int n = 0; n < NTOK; n++) {
            int e = idx2[b * NTOK + n];
            int pcur = mcnt[e] + cnt[e];
            cnt[e]++;
            if (pcur < CAPP) {
                slot_tok[(b * EE + e) * CAPP + pcur] = n;
                slot_gate[(b * EE + e) * CAPP + pcur] = gate2[b * NTOK + n];
            }
        }
    }
}

// ---------------- expert FFN (float4 weight staging) ----------------
__global__ void expert_kernel(const float* __restrict__ xm, const float* __restrict__ w1,
                              const float* __restrict__ w2,
                              const int* __restrict__ slot_tok, const float* __restrict__ slot_gate,
                              float* __restrict__ out) {
    int e = blockIdx.x;
    int tid = threadIdx.x;
    extern __shared__ float sw[];
    __shared__ float hsh[32][33];
    __shared__ int stok[32];
    __shared__ float sgate[32];
    __shared__ int s_any;
    if (tid < 32) {
        int b = tid >> 2, c = tid & 3;
        stok[tid]  = slot_tok [(b * EE + e) * CAPP + c];
        sgate[tid] = slot_gate[(b * EE + e) * CAPP + c];
    }
    if (tid == 0) s_any = 0;
    __syncthreads();
    if (tid == 0) {
        int a = 0;
        for (int i = 0; i < 32; i++) a |= (stok[i] >= 0);
        s_any = a;
    }
    __syncthreads();
    if (!s_any) return;
    {
        const float4* w1v = (const float4*)(w1 + (size_t)e * DTOK * HIDD);
        float4* swv = (float4*)sw;
#pragma unroll
        for (int i = 0; i < 16; i++) swv[tid + i * 256] = w1v[tid + i * 256];
    }
    __syncthreads();
    int hid = tid & 31;
#pragma unroll
    for (int pass = 0; pass < 4; pass++) {
        int sidx = pass * 8 + (tid >> 5);
        int tok = stok[sidx];
        float acc = 0.f;
        if (tok >= 0) {
            const float* xr = xm + ((size_t)((sidx >> 2) * NTOK + tok)) * DTOK;
            for (int dd = 0; dd < DTOK; dd++) acc = fmaf(xr[dd], sw[dd * HIDD + hid], acc);
        }
        hsh[sidx][hid] = gelu_exact(acc);
    }
    __syncthreads();
    {
        const float4* w2v = (const float4*)(w2 + (size_t)e * HIDD * DTOK);
        float4* swv = (float4*)sw;
#pragma unroll
        for (int i = 0; i < 16; i++) swv[tid + i * 256] = w2v[tid + i * 256];
    }
    __syncthreads();
#pragma unroll
    for (int i = 0; i < 64; i++) {
        int idx = tid + i * 256;
        int sidx = idx >> 9;
        int dd = idx & 511;
        int tok = stok[sidx];
        float g = sgate[sidx];
        if (tok >= 0 && g != 0.f) {
            float acc = 0.f;
#pragma unroll
            for (int h2 = 0; h2 < HIDD; h2++) acc = fmaf(hsh[sidx][h2], sw[h2 * DTOK + dd], acc);
            atomicAdd(&out[((size_t)((sidx >> 2) * NTOK + tok)) * DTOK + dd], g * acc);
        }
    }
}

// ---------------- aux loss ----------------
__global__ void loss_kernel(const float* __restrict__ rawsum, const float* __restrict__ cnt1,
                            float* __restrict__ out_scalar) {
    __shared__ float red[256];
    int tid = threadIdx.x;
    float s = 0.f;
    for (int i = tid; i < BB * EE; i += 256) s += rawsum[i] * cnt1[i];
    red[tid] = s; __syncthreads();
    for (int o = 128; o > 0; o >>= 1) { if (tid < o) red[tid] += red[tid + o]; __syncthreads(); }
    if (tid == 0) out_scalar[0] = red[0] * 1.953125e-05f;
}

// ---------------- maxpool k=3 s=2 pad=1 ----------------
__global__ void maxpool_kernel(const float* __restrict__ yf, float* __restrict__ out) {
    int idx = blockIdx.x * 256 + threadIdx.x;
    int j = idx & 255;
    int o = (idx >> 8) & 511;
    int b = idx >> 17;
    const float* row = yf + ((size_t)(b * 512 + o)) * 512;
    int l = 2 * j;
    float m = row[l];
    if (l > 0) m = fmaxf(m, row[l - 1]);
    m = fmaxf(m, row[l + 1]);
    out[idx] = m;
}

// ---------------- host orchestration ----------------
extern "C" void kernel_launch(void* const* d_in, const int* in_sizes, int n_in,
                              void* d_out, int out_size) {
    const float* x        = (const float*)d_in[0];
    const float* emb      = (const float*)d_in[1];
    const float* rb1_g1s  = (const float*)d_in[2];
    const float* rb1_g1b  = (const float*)d_in[3];
    const float* rb1_c1w  = (const float*)d_in[4];
    const float* rb1_c1b  = (const float*)d_in[5];
    const float* rb1_g2s  = (const float*)d_in[6];
    const float* rb1_g2b  = (const float*)d_in[7];
    const float* rb1_c2w  = (const float*)d_in[8];
    const float* rb1_c2b  = (const float*)d_in[9];
    const float* rb2_g1s  = (const float*)d_in[10];
    const float* rb2_g1b  = (const float*)d_in[11];
    const float* rb2_c1w  = (const float*)d_in[12];
    const float* rb2_c1b  = (const float*)d_in[13];
    const float* rb2_g2s  = (const float*)d_in[14];
    const float* rb2_g2b  = (const float*)d_in[15];
    const float* rb2_c2w  = (const float*)d_in[16];
    const float* rb2_c2b  = (const float*)d_in[17];
    const float* attn_w1  = (const float*)d_in[18];
    const float* attn_b1  = (const float*)d_in[19];
    const float* attn_w2  = (const float*)d_in[20];
    const float* attn_b2  = (const float*)d_in[21];
    const float* moe_wg   = (const float*)d_in[22];
    const float* moe_w1   = (const float*)d_in[23];
    const float* moe_w2   = (const float*)d_in[24];
    const float* out_w    = (const float*)d_in[25];
    const float* out_b    = (const float*)d_in[26];
    float* out = (float*)d_out;

    float *px1, *pr, *pxa, *pt, *pq, *pk, *pv, *poc, *pxb, *pxm;
    float *plog, *praw, *pg1, *pg2, *prs, *pc1, *psg, *pmo, *pyf;
    int *pi1, *pi2, *pst;
    unsigned short *pwhi, *pwlo;
    uint32_t *phpk;
    cudaGetSymbolAddress((void**)&px1, g_x1);
    cudaGetSymbolAddress((void**)&pr,  g_r);
    cudaGetSymbolAddress((void**)&pxa, g_xa);
    cudaGetSymbolAddress((void**)&pt,  g_t);
    cudaGetSymbolAddress((void**)&pq,  g_q);
    cudaGetSymbolAddress((void**)&pk,  g_k);
    cudaGetSymbolAddress((void**)&pv,  g_v);
    cudaGetSymbolAddress((void**)&poc, g_oc);
    cudaGetSymbolAddress((void**)&pxb, g_xb);
    cudaGetSymbolAddress((void**)&pxm, g_xm);
    cudaGetSymbolAddress((void**)&plog, g_logits);
    cudaGetSymbolAddress((void**)&praw, g_raw);
    cudaGetSymbolAddress((void**)&pg1, g_gate1);
    cudaGetSymbolAddress((void**)&pg2, g_gate2);
    cudaGetSymbolAddress((void**)&pi1, g_i1);
    cudaGetSymbolAddress((void**)&pi2, g_i2);
    cudaGetSymbolAddress((void**)&prs, g_rawsum);
    cudaGetSymbolAddress((void**)&pc1, g_cnt1);
    cudaGetSymbolAddress((void**)&pst, g_slot_tok);
    cudaGetSymbolAddress((void**)&psg, g_slot_gate);
    cudaGetSymbolAddress((void**)&pmo, g_moeout);
    cudaGetSymbolAddress((void**)&pyf, g_yfull);
    cudaGetSymbolAddress((void**)&pwhi, g_whi);
    cudaGetSymbolAddress((void**)&pwlo, g_wlo);
    cudaGetSymbolAddress((void**)&phpk, g_hpk);

    cudaFuncSetAttribute(expert_kernel, cudaFuncAttributeMaxDynamicSharedMemorySize, 65536);
    cudaFuncSetAttribute(conv_mma_kernel, cudaFuncAttributeMaxDynamicSharedMemorySize, MMA_SMEM);
    cudaFuncSetAttribute(gemm_mma<0,3>, cudaFuncAttributeMaxDynamicSharedMemorySize, MMA_SMEM);
    cudaFuncSetAttribute(gemm_mma<2,3>, cudaFuncAttributeMaxDynamicSharedMemorySize, MMA_SMEM);
    cudaFuncSetAttribute(gemm_mma<0,4>, cudaFuncAttributeMaxDynamicSharedMemorySize, MMA_SMEM);

    const int WSZc = WSZ;
    // ---- ONE fused weight-conversion launch ----
    cvt_weights_kernel<<<5376, 256>>>(rb1_c1w, rb1_c2w, rb2_c1w, rb2_c2w, out_w,
                                      attn_w1, attn_w2, moe_wg, pwhi, pwlo);

    // ---- res block 1 ----
    gn_gelu_kernel<<<BB * NG, 256>>>(x, emb, rb1_g1s, rb1_g1b, px1, phpk);
    conv_mma_kernel<<<dim3(32, 4), 256, MMA_SMEM>>>(pwhi, pwlo, phpk, rb1_c1b, nullptr, pr, 256);
    gn_gelu_kernel<<<BB * NG, 256>>>(pr, nullptr, rb1_g2s, rb1_g2b, nullptr, phpk);
    conv_mma_kernel<<<dim3(32, 4), 256, MMA_SMEM>>>(pwhi + WSZc, pwlo + WSZc, phpk, rb1_c2b, px1, pxa, 256);

    // ---- attention ----
    cvtT_x_kernel<<<dim3(16, 8, 8), dim3(32, 8)>>>(pxa, phpk);
    gemm_mma<0,3><<<dim3(6, 64), 256, MMA_SMEM>>>(phpk, pwhi + OFF_WQKVT, pwlo + OFF_WQKVT,
                                                  attn_b1, pt, 4096, 768, 256);
    qkv_split_kernel<<<4096, 256>>>(pt, pq, pk, pv);
    fused_attn_kernel<<<dim3(8, 64), 256>>>(pq, pk, pv, poc);
    cvt_pk_kernel<<<4096, 256>>>(poc, phpk, BB * LL * CC);
    gemm_mma<2,3><<<dim3(2, 64), 256, MMA_SMEM>>>(phpk, pwhi + OFF_W2T, pwlo + OFF_W2T,
                                                  attn_b2, pxb, 4096, 256, 256);

    // ---- res block 2 ----
    gn_gelu_kernel<<<BB * NG, 256>>>(pxb, emb, rb2_g1s, rb2_g1b, px1, phpk);
    conv_mma_kernel<<<dim3(32, 4), 256, MMA_SMEM>>>(pwhi + 2*WSZc, pwlo + 2*WSZc, phpk, rb2_c1b, nullptr, pr, 256);
    gn_gelu_kernel<<<BB * NG, 256>>>(pr, nullptr, rb2_g2s, rb2_g2b, nullptr, phpk);
    conv_mma_kernel<<<dim3(32, 4), 256, MMA_SMEM>>>(pwhi + 3*WSZc, pwlo + 3*WSZc, phpk, rb2_c2b, px1, pxm, 256);

    // ---- MoE ----
    cvt_pk_kernel<<<4096, 256>>>(pxm, phpk, BB * CC * LL);
    gemm_mma<0,4><<<dim3(8, 32), 256, MMA_SMEM>>>(phpk, pwhi + OFF_WGT, pwlo + OFF_WGT,
                                                  nullptr, plog, 2048, 1024, 512);
    gating_kernel<<<256, 256>>>(plog, praw, pg1, pi1, pg2, pi2);
    rawsum_kernel<<<32, 256>>>(praw, prs);
    routing_kernel<<<BB, 256>>>(pi1, pg1, pi2, pg2, pst, psg, pc1);
    cudaMemsetAsync(pmo, 0, sizeof(float) * BB * CC * LL);
    expert_kernel<<<EE, 256, 65536>>>(pxm, moe_w1, moe_w2, pst, psg, pmo);
    loss_kernel<<<1, 256>>>(prs, pc1, out + 2097152);

    // ---- output conv + maxpool ----
    cvt_pk_kernel<<<4096, 256>>>(pmo, phpk, BB * CC * LL);
    conv_mma_kernel<<<dim3(32, 8), 256, MMA_SMEM>>>(pwhi + 4*WSZc, pwlo + 4*WSZc, phpk, out_b, nullptr, pyf, 512);
    maxpool_kernel<<<4096, 256>>>(pyf, out);

    // second output: moe result x (B,C,L)
    cudaMemcpyAsync(out + 1048576, pmo, sizeof(float) * BB * CC * LL, cudaMemcpyDeviceToDevice);
}

// round 15
// speedup vs baseline: 1.0488x; 1.0034x over previous
#include <cuda_runtime.h>
#include <cuda_bf16.h>
#include <math.h>
#include <stdint.h>

// ---------------- problem constants ----------------
#define BB   8
#define CC   256
#define LL   512
#define NG   32
#define CPG  8
#define NH   8
#define DH   32
#define EE   1024
#define HIDD 32
#define CAPP 4
#define NTOK 256
#define DTOK 512

// ---------------- scratch (device globals; allocation-free) ----------------
__device__ float g_x1[BB*CC*LL];
__device__ float g_r [BB*CC*LL];
__device__ float g_xa[BB*CC*LL];
__device__ float g_t [BB*LL*3*CC];
__device__ float g_q [BB*NH*LL*DH];
__device__ float g_k [BB*NH*LL*DH];
__device__ float g_v [BB*NH*LL*DH];
__device__ float g_oc[BB*LL*CC];
__device__ float g_xb[BB*CC*LL];
__device__ float g_xm[BB*CC*LL];
__device__ float g_logits[BB*NTOK*EE];
__device__ float g_raw  [BB*NTOK*EE];
__device__ float g_gate1[BB*NTOK];
__device__ float g_gate2[BB*NTOK];
__device__ int   g_i1[BB*NTOK];
__device__ int   g_i2[BB*NTOK];
__device__ float g_rawsum[BB*EE];
__device__ float g_cnt1 [BB*EE];
__device__ int   g_slot_tok [BB*EE*CAPP];
__device__ float g_slot_gate[BB*EE*CAPP];
__device__ float g_moeout[BB*CC*LL];
__device__ float g_yfull[(size_t)BB*2*CC*LL];
// bf16 operand buffers: weights separate hi/lo, activations packed (hi | lo<<16)
#define WSZ 196608
#define OFF_WQKVT (6*WSZ)
#define OFF_W2T   (OFF_WQKVT + 196608)
#define OFF_WGT   (OFF_W2T + 65536)
#define WTOT      (OFF_WGT + 524288)
__device__ unsigned short g_whi[WTOT];
__device__ unsigned short g_wlo[WTOT];
__device__ uint32_t g_hpk[BB*CC*LL];

__device__ __forceinline__ float gelu_exact(float v) {
    return 0.5f * v * (1.0f + erff(v * 0.7071067811865476f));
}
__device__ __forceinline__ void split_bf16(float v, unsigned short& h, unsigned short& l) {
    __nv_bfloat16 hb = __float2bfloat16(v);
    __nv_bfloat16 lb = __float2bfloat16(v - __bfloat162float(hb));
    h = *(unsigned short*)&hb;
    l = *(unsigned short*)&lb;
}
__device__ __forceinline__ uint32_t pack_bf16(float v) {
    unsigned short h, l;
    split_bf16(v, h, l);
    return (uint32_t)h | ((uint32_t)l << 16);
}

// ---------------- float -> packed bf16 hi/lo conversion ----------------
__global__ void cvt_pk_kernel(const float* __restrict__ src, uint32_t* __restrict__ pk, int n) {
    int i = blockIdx.x * 256 + threadIdx.x;
    if (i < n) pk[i] = pack_bf16(src[i]);
}

// ---------------- ONE fused weight conversion kernel ----------------
__global__ void cvt_weights_kernel(const float* __restrict__ w0, const float* __restrict__ w1,
                                   const float* __restrict__ w2, const float* __restrict__ w3,
                                   const float* __restrict__ w4,
                                   const float* __restrict__ tw0, const float* __restrict__ tw1,
                                   const float* __restrict__ tw2,
                                   unsigned short* __restrict__ whi, unsigned short* __restrict__ wlo) {
    __shared__ float tile[32][33];
    int b = blockIdx.x, tid = threadIdx.x;
    if (b < 4608) {
        const float* src;
        size_t off;
        int base;
        if (b < 3072) {
            int s = b / 768;
            src = (s == 0) ? w0 : (s == 1) ? w1 : (s == 2) ? w2 : w3;
            off = (size_t)s * WSZ;
            base = (b - s * 768) * 256;
        } else {
            src = w4; off = (size_t)4 * WSZ; base = (b - 3072) * 256;
        }
        int i = base + tid;
        unsigned short h, l;
        split_bf16(src[i], h, l);
        whi[off + i] = h; wlo[off + i] = l;
    } else {
        int t = b - 4608;
        const float* W; int K, N; size_t off; int tk, tn;
        if (t < 192)      { W = tw0; K = 256; N = 768;  off = OFF_WQKVT; tk = t & 7;  tn = t >> 3; }
        else if (t < 256) { t -= 192; W = tw1; K = 256; N = 256; off = OFF_W2T; tk = t & 7;  tn = t >> 3; }
        else              { t -= 256; W = tw2; K = 512; N = 1024; off = OFF_WGT; tk = t & 15; tn = t >> 4; }
        int x = tid & 31, y = tid >> 5;
        int k0 = tk * 32, n0 = tn * 32;
#pragma unroll
        for (int i = 0; i < 32; i += 8)
            tile[y + i][x] = W[(size_t)(k0 + y + i) * N + n0 + x];
        __syncthreads();
#pragma unroll
        for (int i = 0; i < 32; i += 8) {
            unsigned short h, l;
            split_bf16(tile[x][y + i], h, l);
            size_t o = off + (size_t)(n0 + y + i) * K + k0 + x;
            whi[o] = h; wlo[o] = l;
        }
    }
}

// ---------------- transposed activation cvt: xa(B,C,L) -> A[(b*L+l)][C] packed ----------------
__global__ void cvtT_x_kernel(const float* __restrict__ X, uint32_t* __restrict__ apk) {
    __shared__ float tile[32][33];
    int b = blockIdx.z;
    int l0 = blockIdx.x * 32, c0 = blockIdx.y * 32;
    int x = threadIdx.x, y = threadIdx.y;
#pragma unroll
    for (int i = 0; i < 32; i += 8)
        tile[y + i][x] = X[(((size_t)(b * CC + c0 + y + i)) << 9) + l0 + x];
    __syncthreads();
#pragma unroll
    for (int i = 0; i < 32; i += 8)
        apk[(size_t)(b * LL + l0 + y + i) * CC + c0 + x] = pack_bf16(tile[x][y + i]);
}

// ================= warp-level bf16 MMA (m16n8k16, f32 accum) =================
__device__ __forceinline__ void mma16816(float* c, const uint32_t* a, const uint32_t* b) {
    asm volatile("mma.sync.aligned.m16n8k16.row.col.f32.bf16.bf16.f32 "
        "{%0,%1,%2,%3}, {%4,%5,%6,%7}, {%8,%9}, {%0,%1,%2,%3};"
        : "+f"(c[0]), "+f"(c[1]), "+f"(c[2]), "+f"(c[3])
        : "r"(a[0]), "r"(a[1]), "r"(a[2]), "r"(a[3]), "r"(b[0]), "r"(b[1]));
}

#define CPITCH 72
#define OFF_AHI 0
#define OFF_ALO (64*CPITCH)
#define OFF_BHI (2*64*CPITCH)
#define OFF_BLO (2*64*CPITCH + 128*CPITCH)
#define MMA_SMEM ((2*64*CPITCH + 2*128*CPITCH) * 2)   // 55296 bytes

// ================= tensor-core conv1d(k=3,pad=1); X packed =================
__global__ void __launch_bounds__(256, 2)
conv_mma_kernel(const unsigned short* __restrict__ Whi, const unsigned short* __restrict__ Wlo,
                const uint32_t* __restrict__ Xpk,
                const float* __restrict__ bias, const float* __restrict__ res,
                float* __restrict__ Y, int M) {
    extern __shared__ unsigned short sm[];
    int tid = threadIdx.x;
    int wid = tid >> 5, lane = tid & 31;
    int g = lane >> 2, tg = lane & 3;
    int warp_m = wid & 1, warp_n = wid >> 1;
    int n0 = blockIdx.x * 128, m0 = blockIdx.y * 64;
    int bI = n0 >> 9, l0 = n0 & 511;

    const unsigned short* Wh = Whi + (size_t)m0 * 768;
    const unsigned short* Wl = Wlo + (size_t)m0 * 768;
    const uint32_t* Xp = Xpk + (((size_t)bI * CC) << 9);

    float acc[2][4][4];
#pragma unroll
    for (int mi = 0; mi < 2; mi++)
#pragma unroll
        for (int ni = 0; ni < 4; ni++)
#pragma unroll
            for (int r = 0; r < 4; r++) acc[mi][ni][r] = 0.f;

    int fa_m = tid >> 2, fa_k = (tid & 3) * 16;
    int fb_n = tid >> 1, fb_h = (tid & 1) * 32;

    for (int c = 0; c < 12; c++) {
        int c64 = c * 64;
        {
            const unsigned short* ph = Wh + (size_t)fa_m * 768 + c64 + fa_k;
            const unsigned short* pl = Wl + (size_t)fa_m * 768 + c64 + fa_k;
            *(uint4*)&sm[OFF_AHI + fa_m * CPITCH + fa_k]     = *(const uint4*)ph;
            *(uint4*)&sm[OFF_AHI + fa_m * CPITCH + fa_k + 8] = *(const uint4*)(ph + 8);
            *(uint4*)&sm[OFF_ALO + fa_m * CPITCH + fa_k]     = *(const uint4*)pl;
            *(uint4*)&sm[OFF_ALO + fa_m * CPITCH + fa_k + 8] = *(const uint4*)(pl + 8);
        }
        {
            int kg = c64 + fb_h;
            int ic = kg / 3, t = kg - 3 * ic;
            int l = l0 + fb_n;
            unsigned short* dh = &sm[OFF_BHI + fb_n * CPITCH + fb_h];
            unsigned short* dl = &sm[OFF_BLO + fb_n * CPITCH + fb_h];
#pragma unroll 8
            for (int i = 0; i < 32; i++) {
                int ll = l + t - 1;
                bool ok = ((unsigned)ll < 512u);
                uint32_t v = ok ? Xp[(ic << 9) + ll] : 0u;
                dh[i] = (unsigned short)v;
                dl[i] = (unsigned short)(v >> 16);
                if (++t == 3) { t = 0; ++ic; }
            }
        }
        __syncthreads();
#pragma unroll
        for (int ks = 0; ks < 4; ks++) {
            int k0 = ks * 16;
            uint32_t ahi[2][4], alo[2][4], bhi[4][2], blo[4][2];
#pragma unroll
            for (int mi = 0; mi < 2; mi++) {
                int r0 = warp_m * 32 + mi * 16 + g;
                const unsigned short* p0 = &sm[OFF_AHI + r0 * CPITCH + k0 + tg * 2];
                const unsigned short* p1 = p0 + 8 * CPITCH;
                ahi[mi][0] = *(const uint32_t*)p0;
                ahi[mi][1] = *(const uint32_t*)p1;
                ahi[mi][2] = *(const uint32_t*)(p0 + 8);
                ahi[mi][3] = *(const uint32_t*)(p1 + 8);
                const unsigned short* q0 = &sm[OFF_ALO + r0 * CPITCH + k0 + tg * 2];
                const unsigned short* q1 = q0 + 8 * CPITCH;
                alo[mi][0] = *(const uint32_t*)q0;
                alo[mi][1] = *(const uint32_t*)q1;
                alo[mi][2] = *(const uint32_t*)(q0 + 8);
                alo[mi][3] = *(const uint32_t*)(q1 + 8);
            }
#pragma unroll
            for (int ni = 0; ni < 4; ni++) {
                int nr = warp_n * 32 + ni * 8 + g;
                const unsigned short* p = &sm[OFF_BHI + nr * CPITCH + k0 + tg * 2];
                bhi[ni][0] = *(const uint32_t*)p;
                bhi[ni][1] = *(const uint32_t*)(p + 8);
                const unsigned short* q = &sm[OFF_BLO + nr * CPITCH + k0 + tg * 2];
                blo[ni][0] = *(const uint32_t*)q;
                blo[ni][1] = *(const uint32_t*)(q + 8);
            }
#pragma unroll
            for (int mi = 0; mi < 2; mi++)
#pragma unroll
                for (int ni = 0; ni < 4; ni++) {
                    mma16816(acc[mi][ni], ahi[mi], bhi[ni]);
                    mma16816(acc[mi][ni], ahi[mi], blo[ni]);
                    mma16816(acc[mi][ni], alo[mi], bhi[ni]);
                }
        }
        __syncthreads();
    }

#pragma unroll
    for (int mi = 0; mi < 2; mi++) {
        int m = m0 + warp_m * 32 + mi * 16 + g;
        float bs0 = bias[m], bs1 = bias[m + 8];
        size_t row0 = (((size_t)bI * M + m) << 9) + l0;
        size_t row1 = (((size_t)bI * M + m + 8) << 9) + l0;
#pragma unroll
        for (int ni = 0; ni < 4; ni++) {
            int ncol = warp_n * 32 + ni * 8 + tg * 2;
            float2 v0 = make_float2(acc[mi][ni][0] + bs0, acc[mi][ni][1] + bs0);
            float2 v1 = make_float2(acc[mi][ni][2] + bs1, acc[mi][ni][3] + bs1);
            if (res) {
                float2 r0 = *(const float2*)&res[row0 + ncol];
                float2 r1 = *(const float2*)&res[row1 + ncol];
                v0.x += r0.x; v0.y += r0.y; v1.x += r1.x; v1.y += r1.y;
            }
            *(float2*)&Y[row0 + ncol] = v0;
            *(float2*)&Y[row1 + ncol] = v1;
        }
    }
}

// ================= generic tensor-core GEMM: A packed, B hi/lo =================
template<int CM, int NT>
__global__ void __launch_bounds__(256, 2)
gemm_mma(const uint32_t* __restrict__ Apk,
         const unsigned short* __restrict__ Bthi, const unsigned short* __restrict__ Btlo,
         const float* __restrict__ bias, float* __restrict__ C, int M, int N, int K) {
    extern __shared__ unsigned short sm[];
    int tid = threadIdx.x;
    int wid = tid >> 5, lane = tid & 31;
    int g = lane >> 2, tg = lane & 3;
    int warp_m = wid & 1, warp_n = wid >> 1;
    int n0 = blockIdx.x * 128, m0 = blockIdx.y * 64;

    const uint32_t* Ap = Apk + (size_t)m0 * K;
    const unsigned short* Bh = Bthi + (size_t)n0 * K;
    const unsigned short* Bl = Btlo + (size_t)n0 * K;

    float acc[2][4][4];
#pragma unroll
    for (int mi = 0; mi < 2; mi++)
#pragma unroll
        for (int ni = 0; ni < 4; ni++)
#pragma unroll
            for (int r = 0; r < 4; r++) acc[mi][ni][r] = 0.f;

    int fa_m = tid >> 2, fa_k = (tid & 3) * 16;
    int fb_n = tid >> 1, fb_h = (tid & 1) * 32;
    int nchunks = K >> 6;

    for (int c = 0; c < nchunks; c++) {
        int c64 = c << 6;
        {
            const uint32_t* pa = Ap + (size_t)fa_m * K + c64 + fa_k;
            uint4 p0 = *(const uint4*)pa;
            uint4 p1 = *(const uint4*)(pa + 4);
            uint4 p2 = *(const uint4*)(pa + 8);
            uint4 p3 = *(const uint4*)(pa + 12);
            uint4 h0, h1, l0v, l1v;
            h0.x = __byte_perm(p0.x, p0.y, 0x5410); h0.y = __byte_perm(p0.z, p0.w, 0x5410);
            h0.z = __byte_perm(p1.x, p1.y, 0x5410); h0.w = __byte_perm(p1.z, p1.w, 0x5410);
            h1.x = __byte_perm(p2.x, p2.y, 0x5410); h1.y = __byte_perm(p2.z, p2.w, 0x5410);
            h1.z = __byte_perm(p3.x, p3.y, 0x5410); h1.w = __byte_perm(p3.z, p3.w, 0x5410);
            l0v.x = __byte_perm(p0.x, p0.y, 0x7632); l0v.y = __byte_perm(p0.z, p0.w, 0x7632);
            l0v.z = __byte_perm(p1.x, p1.y, 0x7632); l0v.w = __byte_perm(p1.z, p1.w, 0x7632);
            l1v.x = __byte_perm(p2.x, p2.y, 0x7632); l1v.y = __byte_perm(p2.z, p2.w, 0x7632);
            l1v.z = __byte_perm(p3.x, p3.y, 0x7632); l1v.w = __byte_perm(p3.z, p3.w, 0x7632);
            *(uint4*)&sm[OFF_AHI + fa_m * CPITCH + fa_k]     = h0;
            *(uint4*)&sm[OFF_AHI + fa_m * CPITCH + fa_k + 8] = h1;
            *(uint4*)&sm[OFF_ALO + fa_m * CPITCH + fa_k]     = l0v;
            *(uint4*)&sm[OFF_ALO + fa_m * CPITCH + fa_k + 8] = l1v;
        }
        {
            const unsigned short* ph = Bh + (size_t)fb_n * K + c64 + fb_h;
            const unsigned short* pl = Bl + (size_t)fb_n * K + c64 + fb_h;
            unsigned short* dh = &sm[OFF_BHI + fb_n * CPITCH + fb_h];
            unsigned short* dl = &sm[OFF_BLO + fb_n * CPITCH + fb_h];
#pragma unroll
            for (int i = 0; i < 4; i++) {
                *(uint4*)(dh + i * 8) = *(const uint4*)(ph + i * 8);
                *(uint4*)(dl + i * 8) = *(const uint4*)(pl + i * 8);
            }
        }
        __syncthreads();
#pragma unroll
        for (int ks = 0; ks < 4; ks++) {
            int k0 = ks * 16;
            uint32_t ahi[2][4], alo[2][4], bhi[4][2], blo[4][2];
#pragma unroll
            for (int mi = 0; mi < 2; mi++) {
                int r0 = warp_m * 32 + mi * 16 + g;
                const unsigned short* p0 = &sm[OFF_AHI + r0 * CPITCH + k0 + tg * 2];
                const unsigned short* p1 = p0 + 8 * CPITCH;
                ahi[mi][0] = *(const uint32_t*)p0;
                ahi[mi][1] = *(const uint32_t*)p1;
                ahi[mi][2] = *(const uint32_t*)(p0 + 8);
                ahi[mi][3] = *(const uint32_t*)(p1 + 8);
                const unsigned short* q0 = &sm[OFF_ALO + r0 * CPITCH + k0 + tg * 2];
                const unsigned short* q1 = q0 + 8 * CPITCH;
                alo[mi][0] = *(const uint32_t*)q0;
                alo[mi][1] = *(const uint32_t*)q1;
                alo[mi][2] = *(const uint32_t*)(q0 + 8);
                alo[mi][3] = *(const uint32_t*)(q1 + 8);
            }
#pragma unroll
            for (int ni = 0; ni < 4; ni++) {
                int nr = warp_n * 32 + ni * 8 + g;
                const unsigned short* p = &sm[OFF_BHI + nr * CPITCH + k0 + tg * 2];
                bhi[ni][0] = *(const uint32_t*)p;
                bhi[ni][1] = *(const uint32_t*)(p + 8);
                const unsigned short* q = &sm[OFF_BLO + nr * CPITCH + k0 + tg * 2];
                blo[ni][0] = *(const uint32_t*)q;
                blo[ni][1] = *(const uint32_t*)(q + 8);
            }
#pragma unroll
            for (int mi = 0; mi < 2; mi++)
#pragma unroll
                for (int ni = 0; ni < 4; ni++) {
                    mma16816(acc[mi][ni], ahi[mi], bhi[ni]);
                    mma16816(acc[mi][ni], ahi[mi], blo[ni]);
                    mma16816(acc[mi][ni], alo[mi], bhi[ni]);
                    if (NT == 4) mma16816(acc[mi][ni], alo[mi], blo[ni]);
                }
        }
        __syncthreads();
    }

    if (CM == 0) {
#pragma unroll
        for (int mi = 0; mi < 2; mi++) {
            int m = m0 + warp_m * 32 + mi * 16 + g;
#pragma unroll
            for (int ni = 0; ni < 4; ni++) {
                int n = n0 + warp_n * 32 + ni * 8 + tg * 2;
                float b0 = bias ? bias[n] : 0.f;
                float b1 = bias ? bias[n + 1] : 0.f;
                *(float2*)&C[(size_t)m * N + n] =
                    make_float2(acc[mi][ni][0] + b0, acc[mi][ni][1] + b1);
                *(float2*)&C[(size_t)(m + 8) * N + n] =
                    make_float2(acc[mi][ni][2] + b0, acc[mi][ni][3] + b1);
            }
        }
    } else {  // CTRANS
#pragma unroll
        for (int mi = 0; mi < 2; mi++) {
            int m = m0 + warp_m * 32 + mi * 16 + g;
            int bI = m >> 9, l = m & 511;
#pragma unroll
            for (int ni = 0; ni < 4; ni++) {
                int n = n0 + warp_n * 32 + ni * 8 + tg * 2;
                float b0 = bias ? bias[n] : 0.f;
                float b1 = bias ? bias[n + 1] : 0.f;
                C[(((size_t)(bI * N + n)) << 9) + l]           = acc[mi][ni][0] + b0;
                C[(((size_t)(bI * N + n + 1)) << 9) + l]       = acc[mi][ni][1] + b1;
                C[(((size_t)(bI * N + n)) << 9) + l + 8]       = acc[mi][ni][2] + b0;
                C[(((size_t)(bI * N + n + 1)) << 9) + l + 8]   = acc[mi][ni][3] + b1;
            }
        }
    }
}

// ---------------- GroupNorm + GELU: register-resident, shuffle reductions ----------------
// 512 threads, 8 values each; 2 barriers total.
__global__ void gn_gelu_kernel(const float* __restrict__ xin, const float* __restrict__ emb,
                               const float* __restrict__ scale, const float* __restrict__ bias,
                               float* __restrict__ x1_out, uint32_t* __restrict__ hpk) {
    int b = blockIdx.x >> 5;
    int g = blockIdx.x & 31;
    size_t base = ((size_t)b * CC + g * CPG) * LL;
    int tid = threadIdx.x;       // 512
    float v[8];
    float s = 0.f, s2 = 0.f;
#pragma unroll
    for (int i = 0; i < 8; i++) {
        int j = tid + i * 512;
        float t = xin[base + j];
        if (emb) t += emb[base + j];
        v[i] = t;
        s += t;
        s2 = fmaf(t, t, s2);
    }
#pragma unroll
    for (int o = 16; o > 0; o >>= 1) {
        s  += __shfl_xor_sync(0xffffffff, s, o);
        s2 += __shfl_xor_sync(0xffffffff, s2, o);
    }
    __shared__ float ws[16], ws2[16], stats[2];
    int wid = tid >> 5, lane = tid & 31;
    if (lane == 0) { ws[wid] = s; ws2[wid] = s2; }
    __syncthreads();
    if (tid < 32) {
        float a  = (tid < 16) ? ws[tid]  : 0.f;
        float a2 = (tid < 16) ? ws2[tid] : 0.f;
#pragma unroll
        for (int o = 8; o > 0; o >>= 1) {
            a  += __shfl_xor_sync(0xffffffff, a, o);
            a2 += __shfl_xor_sync(0xffffffff, a2, o);
        }
        if (tid == 0) { stats[0] = a; stats[1] = a2; }
    }
    __syncthreads();
    float mean = stats[0] * (1.f / 4096.f);
    float var = stats[1] * (1.f / 4096.f) - mean * mean;
    float rsig = rsqrtf(var + 1e-5f);
#pragma unroll
    for (int i = 0; i < 8; i++) {
        int j = tid + i * 512;
        int c = g * CPG + (j >> 9);
        float t = v[i];
        if (x1_out) x1_out[base + j] = t;
        float nn = (t - mean) * rsig * scale[c] + bias[c];
        hpk[base + j] = pack_bf16(gelu_exact(nn));
    }
}

// ---------------- qkv split ----------------
__global__ void qkv_split_kernel(const float* __restrict__ t, float* __restrict__ Q,
                                 float* __restrict__ K, float* __restrict__ V) {
    int idx = blockIdx.x * 256 + threadIdx.x;
    int d = idx & 31;
    int l = (idx >> 5) & 511;
    int h = (idx >> 14) & 7;
    int b = idx >> 17;
    size_t base = ((size_t)(b * LL + l)) * 768 + (size_t)(d * NH + h) * 3;
    int o = ((b * NH + h) * LL + l) * DH + d;
    Q[o] = t[base];
    K[o] = t[base + 1];
    V[o] = t[base + 2];
}

// ---------------- fused flash attention ----------------
__global__ void fused_attn_kernel(const float* __restrict__ Q, const float* __restrict__ K,
                                  const float* __restrict__ V, float* __restrict__ OCb) {
    int bh = blockIdx.y;
    int q0 = blockIdx.x * 64;
    int b = bh >> 3, h = bh & 7;
    __shared__ float Qs[64][33];
    __shared__ float Ks[64][33];
    __shared__ float Vs[64][33];
    __shared__ float Ps[64][65];
    __shared__ float rowm[64], rowl[64], rowscale[64];
    int tid = threadIdx.x;
    int d = tid & 31, qg = tid >> 5;
    int tx = tid & 15, ty = tid >> 4;
    const float sc = 0.17677669529663687f;

#pragma unroll
    for (int i = 0; i < 8; i++) {
        int idx = tid + i * 256;
        int r = idx >> 5, dd = idx & 31;
        Qs[r][dd] = Q[((size_t)(bh << 9) + q0 + r) * 32 + dd];
    }
    if (tid < 64) { rowm[tid] = -3.4e38f; rowl[tid] = 0.f; }
    float acc[8];
#pragma unroll
    for (int j = 0; j < 8; j++) acc[j] = 0.f;

    for (int k0 = 0; k0 < 512; k0 += 64) {
        __syncthreads();
#pragma unroll
        for (int i = 0; i < 8; i++) {
            int idx = tid + i * 256;
            int r = idx >> 5, dd = idx & 31;
            size_t gsrc = ((size_t)(bh << 9) + k0 + r) * 32 + dd;
            Ks[r][dd] = K[gsrc];
            Vs[r][dd] = V[gsrc];
        }
        __syncthreads();
        {
            float sacc[4][4] = {};
#pragma unroll
            for (int kk = 0; kk < 32; kk++) {
                float a[4], bq[4];
#pragma unroll
                for (int i = 0; i < 4; i++) a[i] = Qs[ty * 4 + i][kk];
#pragma unroll
                for (int j = 0; j < 4; j++) bq[j] = Ks[tx * 4 + j][kk];
#pragma unroll
                for (int i = 0; i < 4; i++)
#pragma unroll
                    for (int j = 0; j < 4; j++) sacc[i][j] = fmaf(a[i], bq[j], sacc[i][j]);
            }
#pragma unroll
            for (int i = 0; i < 4; i++)
#pragma unroll
                for (int j = 0; j < 4; j++)
                    Ps[ty * 4 + i][tx * 4 + j] = sacc[i][j] * sc;
        }
        __syncthreads();
        {
            int r = tid >> 2, sub = tid & 3;
            float mloc = -3.4e38f;
#pragma unroll
            for (int c = 0; c < 16; c++) mloc = fmaxf(mloc, Ps[r][sub * 16 + c]);
            mloc = fmaxf(mloc, __shfl_xor_sync(0xffffffff, mloc, 1));
            mloc = fmaxf(mloc, __shfl_xor_sync(0xffffffff, mloc, 2));
            float mold = rowm[r];
            float mnew = fmaxf(mold, mloc);
            float ssum = 0.f;
#pragma unroll
            for (int c = 0; c < 16; c++) {
                float e = expf(Ps[r][sub * 16 + c] - mnew);
                Ps[r][sub * 16 + c] = e;
                ssum += e;
            }
            ssum += __shfl_xor_sync(0xffffffff, ssum, 1);
            ssum += __shfl_xor_sync(0xffffffff, ssum, 2);
            if (sub == 0) {
                float scl = expf(mold - mnew);
                rowscale[r] = scl;
                rowl[r] = rowl[r] * scl + ssum;
                rowm[r] = mnew;
            }
        }
        __syncthreads();
#pragma unroll
        for (int j = 0; j < 8; j++) acc[j] *= rowscale[qg + j * 8];
#pragma unroll
        for (int kk = 0; kk < 64; kk++) {
            float vv = Vs[kk][d];
#pragma unroll
            for (int j = 0; j < 8; j++) acc[j] = fmaf(Ps[qg + j * 8][kk], vv, acc[j]);
        }
    }
#pragma unroll
    for (int j = 0; j < 8; j++) {
        int q = q0 + qg + j * 8;
        OCb[((size_t)(b << 9) + q) * 256 + d * NH + h] = acc[j] / rowl[qg + j * 8];
    }
}

// ---------------- MoE gating: warp-per-row ----------------
__global__ void gating_kernel(const float* __restrict__ logits, float* __restrict__ raw,
                              float* __restrict__ g1, int* __restrict__ i1,
                              float* __restrict__ g2, int* __restrict__ i2) {
    int warp = (blockIdx.x << 3) + (threadIdx.x >> 5);
    int lane = threadIdx.x & 31;
    const float* p = logits + (size_t)warp * EE;
    float lv[32];
#pragma unroll
    for (int i = 0; i < 32; i++) lv[i] = p[i * 32 + lane];

    float bv = lv[0]; int bi = lane;
#pragma unroll
    for (int i = 1; i < 32; i++)
        if (lv[i] > bv) { bv = lv[i]; bi = i * 32 + lane; }
#pragma unroll
    for (int o = 16; o > 0; o >>= 1) {
        float ov = __shfl_xor_sync(0xffffffff, bv, o);
        int oi = __shfl_xor_sync(0xffffffff, bi, o);
        if (ov > bv || (ov == bv && oi < bi)) { bv = ov; bi = oi; }
    }
    float maxv = bv; int maxi = bi;

    float s = 0.f;
#pragma unroll
    for (int i = 0; i < 32; i++) s += expf(lv[i] - maxv);
#pragma unroll
    for (int o = 16; o > 0; o >>= 1) s += __shfl_xor_sync(0xffffffff, s, o);
    float inv = 1.f / s;
    float* rp = raw + (size_t)warp * EE;
#pragma unroll
    for (int i = 0; i < 32; i++) rp[i * 32 + lane] = expf(lv[i] - maxv) * inv;

    float b2 = -3.4e38f; int b2i = 0;
#pragma unroll
    for (int i = 0; i < 32; i++) {
        int e = i * 32 + lane;
        if (e != maxi && lv[i] > b2) { b2 = lv[i]; b2i = e; }
    }
#pragma unroll
    for (int o = 16; o > 0; o >>= 1) {
        float ov = __shfl_xor_sync(0xffffffff, b2, o);
        int oi = __shfl_xor_sync(0xffffffff, b2i, o);
        if (ov > b2 || (ov == b2 && oi < b2i)) { b2 = ov; b2i = oi; }
    }

    if (lane == 0) {
        float gate1v = inv;
        float gate2v = expf(b2 - maxv) * inv;
        float denom = gate1v + gate2v + 1e-9f;
        g1[warp] = gate1v / denom;
        i1[warp] = maxi;
        g2[warp] = gate2v / denom;
        i2[warp] = b2i;
    }
}

// ---------------- per-(b,e) sum of raw over tokens ----------------
__global__ void rawsum_kernel(const float* __restrict__ raw, float* __restrict__ rawsum) {
    int b = blockIdx.x >> 2;
    int chunk = blockIdx.x & 3;
    int e = chunk * 256 + threadIdx.x;
    const float* p = raw + (size_t)b * NTOK * EE + e;
    float s = 0.f;
    for (int n = 0; n < NTOK; n++) s += p[(size_t)n * EE];
    rawsum[b * EE + e] = s;
}

// ---------------- routing with capacity ----------------
__global__ void routing_kernel(const int* __restrict__ idx1, const float* __restrict__ gate1,
                               const int* __restrict__ idx2, const float* __restrict__ gate2,
                               int* __restrict__ slot_tok, float* __restrict__ slot_gate,
                               float* __restrict__ cnt1_out) {
    int b = blockIdx.x;
    int tid = threadIdx.x;
    __shared__ int cnt[EE];
    __shared__ int mcnt[EE];
    for (int e = tid; e < EE; e += 256) cnt[e] = 0;
    for (int i = tid; i < EE * CAPP; i += 256) {
        slot_tok[b * EE * CAPP + i] = -1;
        slot_gate[b * EE * CAPP + i] = 0.f;
    }
    __syncthreads();
    if (tid == 0) {
        for (int n = 0; n < NTOK; n++) {
            int e = idx1[b * NTOK + n];
            int pcur = cnt[e]++;
            if (pcur < CAPP) {
                slot_tok[(b * EE + e) * CAPP + pcur] = n;
                slot_gate[(b * EE + e) * CAPP + pcur] = gate1[b * NTOK + n];
            }
        }
    }
    __syncthreads();
    for (int e = tid; e < EE; e += 256) {
        cnt1_out[b * EE + e] = (float)cnt[e];
        mcnt[e] = cnt[e] < CAPP ? cnt[e] : CAPP;
        cnt[e] = 0;
    }
    __syncthreads();
    if (tid == 0) {
        for (int n = 0; n < NTOK; n++) {
            int e = idx2[b * NTOK + n];
            int pcur = mcnt[e] + cnt[e];
            cnt[e]++;
            if (pcur < CAPP) {
                slot_tok[(b * EE + e) * CAPP + pcur] = n;
                slot_gate[(b * EE + e) * CAPP + pcur] = gate2[b * NTOK + n];
            }
        }
    }
}

// ---------------- expert FFN (float4 weight staging) ----------------
__global__ void expert_kernel(const float* __restrict__ xm, const float* __restrict__ w1,
                              const float* __restrict__ w2,
                              const int* __restrict__ slot_tok, const float* __restrict__ slot_gate,
                              float* __restrict__ out) {
    int e = blockIdx.x;
    int tid = threadIdx.x;
    extern __shared__ float sw[];
    __shared__ float hsh[32][33];
    __shared__ int stok[32];
    __shared__ float sgate[32];
    __shared__ int s_any;
    if (tid < 32) {
        int b = tid >> 2, c = tid & 3;
        stok[tid]  = slot_tok [(b * EE + e) * CAPP + c];
        sgate[tid] = slot_gate[(b * EE + e) * CAPP + c];
    }
    if (tid == 0) s_any = 0;
    __syncthreads();
    if (tid == 0) {
        int a = 0;
        for (int i = 0; i < 32; i++) a |= (stok[i] >= 0);
        s_any = a;
    }
    __syncthreads();
    if (!s_any) return;
    {
        const float4* w1v = (const float4*)(w1 + (size_t)e * DTOK * HIDD);
        float4* swv = (float4*)sw;
#pragma unroll
        for (int i = 0; i < 16; i++) swv[tid + i * 256] = w1v[tid + i * 256];
    }
    __syncthreads();
    int hid = tid & 31;
#pragma unroll
    for (int pass = 0; pass < 4; pass++) {
        int sidx = pass * 8 + (tid >> 5);
        int tok = stok[sidx];
        float acc = 0.f;
        if (tok >= 0) {
            const float* xr = xm + ((size_t)((sidx >> 2) * NTOK + tok)) * DTOK;
            for (int dd = 0; dd < DTOK; dd++) acc = fmaf(xr[dd], sw[dd * HIDD + hid], acc);
        }
        hsh[sidx][hid] = gelu_exact(acc);
    }
    __syncthreads();
    {
        const float4* w2v = (const float4*)(w2 + (size_t)e * HIDD * DTOK);
        float4* swv = (float4*)sw;
#pragma unroll
        for (int i = 0; i < 16; i++) swv[tid + i * 256] = w2v[tid + i * 256];
    }
    __syncthreads();
#pragma unroll
    for (int i = 0; i < 64; i++) {
        int idx = tid + i * 256;
        int sidx = idx >> 9;
        int dd = idx & 511;
        int tok = stok[sidx];
        float g = sgate[sidx];
        if (tok >= 0 && g != 0.f) {
            float acc = 0.f;
#pragma unroll
            for (int h2 = 0; h2 < HIDD; h2++) acc = fmaf(hsh[sidx][h2], sw[h2 * DTOK + dd], acc);
            atomicAdd(&out[((size_t)((sidx >> 2) * NTOK + tok)) * DTOK + dd], g * acc);
        }
    }
}

// ---------------- aux loss ----------------
__global__ void loss_kernel(const float* __restrict__ rawsum, const float* __restrict__ cnt1,
                            float* __restrict__ out_scalar) {
    __shared__ float red[256];
    int tid = threadIdx.x;
    float s = 0.f;
    for (int i = tid; i < BB * EE; i += 256) s += rawsum[i] * cnt1[i];
    red[tid] = s; __syncthreads();
    for (int o = 128; o > 0; o >>= 1) { if (tid < o) red[tid] += red[tid + o]; __syncthreads(); }
    if (tid == 0) out_scalar[0] = red[0] * 1.953125e-05f;
}

// ---------------- maxpool k=3 s=2 pad=1 ----------------
__global__ void maxpool_kernel(const float* __restrict__ yf, float* __restrict__ out) {
    int idx = blockIdx.x * 256 + threadIdx.x;
    int j = idx & 255;
    int o = (idx >> 8) & 511;
    int b = idx >> 17;
    const float* row = yf + ((size_t)(b * 512 + o)) * 512;
    int l = 2 * j;
    float m = row[l];
    if (l > 0) m = fmaxf(m, row[l - 1]);
    m = fmaxf(m, row[l + 1]);
    out[idx] = m;
}

// ---------------- host orchestration ----------------
extern "C" void kernel_launch(void* const* d_in, const int* in_sizes, int n_in,
                              void* d_out, int out_size) {
    const float* x        = (const float*)d_in[0];
    const float* emb      = (const float*)d_in[1];
    const float* rb1_g1s  = (const float*)d_in[2];
    const float* rb1_g1b  = (const float*)d_in[3];
    const float* rb1_c1w  = (const float*)d_in[4];
    const float* rb1_c1b  = (const float*)d_in[5];
    const float* rb1_g2s  = (const float*)d_in[6];
    const float* rb1_g2b  = (const float*)d_in[7];
    const float* rb1_c2w  = (const float*)d_in[8];
    const float* rb1_c2b  = (const float*)d_in[9];
    const float* rb2_g1s  = (const float*)d_in[10];
    const float* rb2_g1b  = (const float*)d_in[11];
    const float* rb2_c1w  = (const float*)d_in[12];
    const float* rb2_c1b  = (const float*)d_in[13];
    const float* rb2_g2s  = (const float*)d_in[14];
    const float* rb2_g2b  = (const float*)d_in[15];
    const float* rb2_c2w  = (const float*)d_in[16];
    const float* rb2_c2b  = (const float*)d_in[17];
    const float* attn_w1  = (const float*)d_in[18];
    const float* attn_b1  = (const float*)d_in[19];
    const float* attn_w2  = (const float*)d_in[20];
    const float* attn_b2  = (const float*)d_in[21];
    const float* moe_wg   = (const float*)d_in[22];
    const float* moe_w1   = (const float*)d_in[23];
    const float* moe_w2   = (const float*)d_in[24];
    const float* out_w    = (const float*)d_in[25];
    const float* out_b    = (const float*)d_in[26];
    float* out = (float*)d_out;

    float *px1, *pr, *pxa, *pt, *pq, *pk, *pv, *poc, *pxb, *pxm;
    float *plog, *praw, *pg1, *pg2, *prs, *pc1, *psg, *pmo, *pyf;
    int *pi1, *pi2, *pst;
    unsigned short *pwhi, *pwlo;
    uint32_t *phpk;
    cudaGetSymbolAddress((void**)&px1, g_x1);
    cudaGetSymbolAddress((void**)&pr,  g_r);
    cudaGetSymbolAddress((void**)&pxa, g_xa);
    cudaGetSymbolAddress((void**)&pt,  g_t);
    cudaGetSymbolAddress((void**)&pq,  g_q);
    cudaGetSymbolAddress((void**)&pk,  g_k);
    cudaGetSymbolAddress((void**)&pv,  g_v);
    cudaGetSymbolAddress((void**)&poc, g_oc);
    cudaGetSymbolAddress((void**)&pxb, g_xb);
    cudaGetSymbolAddress((void**)&pxm, g_xm);
    cudaGetSymbolAddress((void**)&plog, g_logits);
    cudaGetSymbolAddress((void**)&praw, g_raw);
    cudaGetSymbolAddress((void**)&pg1, g_gate1);
    cudaGetSymbolAddress((void**)&pg2, g_gate2);
    cudaGetSymbolAddress((void**)&pi1, g_i1);
    cudaGetSymbolAddress((void**)&pi2, g_i2);
    cudaGetSymbolAddress((void**)&prs, g_rawsum);
    cudaGetSymbolAddress((void**)&pc1, g_cnt1);
    cudaGetSymbolAddress((void**)&pst, g_slot_tok);
    cudaGetSymbolAddress((void**)&psg, g_slot_gate);
    cudaGetSymbolAddress((void**)&pmo, g_moeout);
    cudaGetSymbolAddress((void**)&pyf, g_yfull);
    cudaGetSymbolAddress((void**)&pwhi, g_whi);
    cudaGetSymbolAddress((void**)&pwlo, g_wlo);
    cudaGetSymbolAddress((void**)&phpk, g_hpk);

    cudaFuncSetAttribute(expert_kernel, cudaFuncAttributeMaxDynamicSharedMemorySize, 65536);
    cudaFuncSetAttribute(conv_mma_kernel, cudaFuncAttributeMaxDynamicSharedMemorySize, MMA_SMEM);
    cudaFuncSetAttribute(gemm_mma<0,3>, cudaFuncAttributeMaxDynamicSharedMemorySize, MMA_SMEM);
    cudaFuncSetAttribute(gemm_mma<2,3>, cudaFuncAttributeMaxDynamicSharedMemorySize, MMA_SMEM);
    cudaFuncSetAttribute(gemm_mma<0,4>, cudaFuncAttributeMaxDynamicSharedMemorySize, MMA_SMEM);

    const int WSZc = WSZ;
    // ---- ONE fused weight-conversion launch ----
    cvt_weights_kernel<<<5376, 256>>>(rb1_c1w, rb1_c2w, rb2_c1w, rb2_c2w, out_w,
                                      attn_w1, attn_w2, moe_wg, pwhi, pwlo);

    // ---- res block 1 ----
    gn_gelu_kernel<<<BB * NG, 512>>>(x, emb, rb1_g1s, rb1_g1b, px1, phpk);
    conv_mma_kernel<<<dim3(32, 4), 256, MMA_SMEM>>>(pwhi, pwlo, phpk, rb1_c1b, nullptr, pr, 256);
    gn_gelu_kernel<<<BB * NG, 512>>>(pr, nullptr, rb1_g2s, rb1_g2b, nullptr, phpk);
    conv_mma_kernel<<<dim3(32, 4), 256, MMA_SMEM>>>(pwhi + WSZc, pwlo + WSZc, phpk, rb1_c2b, px1, pxa, 256);

    // ---- attention ----
    cvtT_x_kernel<<<dim3(16, 8, 8), dim3(32, 8)>>>(pxa, phpk);
    gemm_mma<0,3><<<dim3(6, 64), 256, MMA_SMEM>>>(phpk, pwhi + OFF_WQKVT, pwlo + OFF_WQKVT,
                                                  attn_b1, pt, 4096, 768, 256);
    qkv_split_kernel<<<4096, 256>>>(pt, pq, pk, pv);
    fused_attn_kernel<<<dim3(8, 64), 256>>>(pq, pk, pv, poc);
    cvt_pk_kernel<<<4096, 256>>>(poc, phpk, BB * LL * CC);
    gemm_mma<2,3><<<dim3(2, 64), 256, MMA_SMEM>>>(phpk, pwhi + OFF_W2T, pwlo + OFF_W2T,
                                                  attn_b2, pxb, 4096, 256, 256);

    // ---- res block 2 ----
    gn_gelu_kernel<<<BB * NG, 512>>>(pxb, emb, rb2_g1s, rb2_g1b, px1, phpk);
    conv_mma_kernel<<<dim3(32, 4), 256, MMA_SMEM>>>(pwhi + 2*WSZc, pwlo + 2*WSZc, phpk, rb2_c1b, nullptr, pr, 256);
    gn_gelu_kernel<<<BB * NG, 512>>>(pr, nullptr, rb2_g2s, rb2_g2b, nullptr, phpk);
    conv_mma_kernel<<<dim3(32, 4), 256, MMA_SMEM>>>(pwhi + 3*WSZc, pwlo + 3*WSZc, phpk, rb2_c2b, px1, pxm, 256);

    // ---- MoE ----
    cvt_pk_kernel<<<4096, 256>>>(pxm, phpk, BB * CC * LL);
    gemm_mma<0,4><<<dim3(8, 32), 256, MMA_SMEM>>>(phpk, pwhi + OFF_WGT, pwlo + OFF_WGT,
                                                  nullptr, plog, 2048, 1024, 512);
    gating_kernel<<<256, 256>>>(plog, praw, pg1, pi1, pg2, pi2);
    rawsum_kernel<<<32, 256>>>(praw, prs);
    routing_kernel<<<BB, 256>>>(pi1, pg1, pi2, pg2, pst, psg, pc1);
    cudaMemsetAsync(pmo, 0, sizeof(float) * BB * CC * LL);
    expert_kernel<<<EE, 256, 65536>>>(pxm, moe_w1, moe_w2, pst, psg, pmo);
    loss_kernel<<<1, 256>>>(prs, pc1, out + 2097152);

    // ---- output conv + maxpool ----
    cvt_pk_kernel<<<4096, 256>>>(pmo, phpk, BB * CC * LL);
    conv_mma_kernel<<<dim3(32, 8), 256, MMA_SMEM>>>(pwhi + 4*WSZc, pwlo + 4*WSZc, phpk, out_b, nullptr, pyf, 512);
    maxpool_kernel<<<4096, 256>>>(pyf, out);

    // second output: moe result x (B,C,L)
    cudaMemcpyAsync(out + 1048576, pmo, sizeof(float) * BB * CC * LL, cudaMemcpyDeviceToDevice);
}

// round 17
// speedup vs baseline: 1.1427x; 1.0896x over previous
#include <cuda_runtime.h>
#include <cuda_bf16.h>
#include <math.h>
#include <stdint.h>

// ---------------- problem constants ----------------
#define BB   8
#define CC   256
#define LL   512
#define NG   32
#define CPG  8
#define NH   8
#define DH   32
#define EE   1024
#define HIDD 32
#define CAPP 4
#define NTOK 256
#define DTOK 512
#define QKVSZ (BB*NH*LL*DH)

// ---------------- scratch (device globals; allocation-free) ----------------
__device__ float g_x1[BB*CC*LL];
__device__ float g_r [BB*CC*LL];
__device__ float g_xa[BB*CC*LL];
__device__ float g_t [BB*LL*3*CC];
__device__ uint32_t g_qp[QKVSZ];
__device__ uint32_t g_kp[QKVSZ];
__device__ uint32_t g_vp[QKVSZ];
__device__ float g_xb[BB*CC*LL];
__device__ float g_xm[BB*CC*LL];
__device__ float g_logits[BB*NTOK*EE];
__device__ float g_raw  [BB*NTOK*EE];
__device__ float g_gate1[BB*NTOK];
__device__ float g_gate2[BB*NTOK];
__device__ int   g_i1[BB*NTOK];
__device__ int   g_i2[BB*NTOK];
__device__ float g_rawsum[BB*EE];
__device__ float g_cnt1 [BB*EE];
__device__ int   g_slot_tok [BB*EE*CAPP];
__device__ float g_slot_gate[BB*EE*CAPP];
__device__ float g_moeout[BB*CC*LL];
__device__ float g_yfull[(size_t)BB*2*CC*LL];
#define WSZ 196608
#define OFF_WQKVT (6*WSZ)
#define OFF_W2T   (OFF_WQKVT + 196608)
#define OFF_WGT   (OFF_W2T + 65536)
#define WTOT      (OFF_WGT + 524288)
__device__ unsigned short g_whi[WTOT];
__device__ unsigned short g_wlo[WTOT];
__device__ uint32_t g_hpk[BB*CC*LL];

__device__ __forceinline__ float gelu_exact(float v) {
    return 0.5f * v * (1.0f + erff(v * 0.7071067811865476f));
}
__device__ __forceinline__ void split_bf16(float v, unsigned short& h, unsigned short& l) {
    __nv_bfloat16 hb = __float2bfloat16(v);
    __nv_bfloat16 lb = __float2bfloat16(v - __bfloat162float(hb));
    h = *(unsigned short*)&hb;
    l = *(unsigned short*)&lb;
}
__device__ __forceinline__ uint32_t pack_bf16(float v) {
    unsigned short h, l;
    split_bf16(v, h, l);
    return (uint32_t)h | ((uint32_t)l << 16);
}

// ---------------- float -> packed bf16 hi/lo conversion ----------------
__global__ void cvt_pk_kernel(const float* __restrict__ src, uint32_t* __restrict__ pk, int n) {
    int i = blockIdx.x * 256 + threadIdx.x;
    if (i < n) pk[i] = pack_bf16(src[i]);
}

// ---------------- ONE fused weight conversion kernel ----------------
__global__ void cvt_weights_kernel(const float* __restrict__ w0, const float* __restrict__ w1,
                                   const float* __restrict__ w2, const float* __restrict__ w3,
                                   const float* __restrict__ w4,
                                   const float* __restrict__ tw0, const float* __restrict__ tw1,
                                   const float* __restrict__ tw2,
                                   unsigned short* __restrict__ whi, unsigned short* __restrict__ wlo) {
    __shared__ float tile[32][33];
    int b = blockIdx.x, tid = threadIdx.x;
    if (b < 4608) {
        const float* src;
        size_t off;
        int base;
        if (b < 3072) {
            int s = b / 768;
            src = (s == 0) ? w0 : (s == 1) ? w1 : (s == 2) ? w2 : w3;
            off = (size_t)s * WSZ;
            base = (b - s * 768) * 256;
        } else {
            src = w4; off = (size_t)4 * WSZ; base = (b - 3072) * 256;
        }
        int i = base + tid;
        unsigned short h, l;
        split_bf16(src[i], h, l);
        whi[off + i] = h; wlo[off + i] = l;
    } else {
        int t = b - 4608;
        const float* W; int K, N; size_t off; int tk, tn;
        if (t < 192)      { W = tw0; K = 256; N = 768;  off = OFF_WQKVT; tk = t & 7;  tn = t >> 3; }
        else if (t < 256) { t -= 192; W = tw1; K = 256; N = 256; off = OFF_W2T; tk = t & 7;  tn = t >> 3; }
        else              { t -= 256; W = tw2; K = 512; N = 1024; off = OFF_WGT; tk = t & 15; tn = t >> 4; }
        int x = tid & 31, y = tid >> 5;
        int k0 = tk * 32, n0 = tn * 32;
#pragma unroll
        for (int i = 0; i < 32; i += 8)
            tile[y + i][x] = W[(size_t)(k0 + y + i) * N + n0 + x];
        __syncthreads();
#pragma unroll
        for (int i = 0; i < 32; i += 8) {
            unsigned short h, l;
            split_bf16(tile[x][y + i], h, l);
            size_t o = off + (size_t)(n0 + y + i) * K + k0 + x;
            whi[o] = h; wlo[o] = l;
        }
    }
}

// ---------------- transposed activation cvt: xa(B,C,L) -> A[(b*L+l)][C] packed ----------------
__global__ void cvtT_x_kernel(const float* __restrict__ X, uint32_t* __restrict__ apk) {
    __shared__ float tile[32][33];
    int b = blockIdx.z;
    int l0 = blockIdx.x * 32, c0 = blockIdx.y * 32;
    int x = threadIdx.x, y = threadIdx.y;
#pragma unroll
    for (int i = 0; i < 32; i += 8)
        tile[y + i][x] = X[(((size_t)(b * CC + c0 + y + i)) << 9) + l0 + x];
    __syncthreads();
#pragma unroll
    for (int i = 0; i < 32; i += 8)
        apk[(size_t)(b * LL + l0 + y + i) * CC + c0 + x] = pack_bf16(tile[x][y + i]);
}

// ================= warp-level bf16 MMA (m16n8k16, f32 accum) =================
__device__ __forceinline__ void mma16816(float* c, const uint32_t* a, const uint32_t* b) {
    asm volatile("mma.sync.aligned.m16n8k16.row.col.f32.bf16.bf16.f32 "
        "{%0,%1,%2,%3}, {%4,%5,%6,%7}, {%8,%9}, {%0,%1,%2,%3};"
        : "+f"(c[0]), "+f"(c[1]), "+f"(c[2]), "+f"(c[3])
        : "r"(a[0]), "r"(a[1]), "r"(a[2]), "r"(a[3]), "r"(b[0]), "r"(b[1]));
}

#define CPITCH 72
#define OFF_AHI 0
#define OFF_ALO (64*CPITCH)
#define OFF_BHI (2*64*CPITCH)
#define OFF_BLO (2*64*CPITCH + 128*CPITCH)
#define MMA_SMEM ((2*64*CPITCH + 2*128*CPITCH) * 2)   // 55296 bytes

// ================= tensor-core conv1d(k=3,pad=1); X packed =================
__global__ void __launch_bounds__(256, 2)
conv_mma_kernel(const unsigned short* __restrict__ Whi, const unsigned short* __restrict__ Wlo,
                const uint32_t* __restrict__ Xpk,
                const float* __restrict__ bias, const float* __restrict__ res,
                float* __restrict__ Y, int M) {
    extern __shared__ unsigned short sm[];
    int tid = threadIdx.x;
    int wid = tid >> 5, lane = tid & 31;
    int g = lane >> 2, tg = lane & 3;
    int warp_m = wid & 1, warp_n = wid >> 1;
    int n0 = blockIdx.x * 128, m0 = blockIdx.y * 64;
    int bI = n0 >> 9, l0 = n0 & 511;

    const unsigned short* Wh = Whi + (size_t)m0 * 768;
    const unsigned short* Wl = Wlo + (size_t)m0 * 768;
    const uint32_t* Xp = Xpk + (((size_t)bI * CC) << 9);

    float acc[2][4][4];
#pragma unroll
    for (int mi = 0; mi < 2; mi++)
#pragma unroll
        for (int ni = 0; ni < 4; ni++)
#pragma unroll
            for (int r = 0; r < 4; r++) acc[mi][ni][r] = 0.f;

    int fa_m = tid >> 2, fa_k = (tid & 3) * 16;
    int fb_n = tid >> 1, fb_h = (tid & 1) * 32;

    for (int c = 0; c < 12; c++) {
        int c64 = c * 64;
        {
            const unsigned short* ph = Wh + (size_t)fa_m * 768 + c64 + fa_k;
            const unsigned short* pl = Wl + (size_t)fa_m * 768 + c64 + fa_k;
            *(uint4*)&sm[OFF_AHI + fa_m * CPITCH + fa_k]     = *(const uint4*)ph;
            *(uint4*)&sm[OFF_AHI + fa_m * CPITCH + fa_k + 8] = *(const uint4*)(ph + 8);
            *(uint4*)&sm[OFF_ALO + fa_m * CPITCH + fa_k]     = *(const uint4*)pl;
            *(uint4*)&sm[OFF_ALO + fa_m * CPITCH + fa_k + 8] = *(const uint4*)(pl + 8);
        }
        {
            int kg = c64 + fb_h;
            int ic = kg / 3, t = kg - 3 * ic;
            int l = l0 + fb_n;
            unsigned short* dh = &sm[OFF_BHI + fb_n * CPITCH + fb_h];
            unsigned short* dl = &sm[OFF_BLO + fb_n * CPITCH + fb_h];
#pragma unroll 8
            for (int i = 0; i < 32; i++) {
                int ll = l + t - 1;
                bool ok = ((unsigned)ll < 512u);
                uint32_t v = ok ? Xp[(ic << 9) + ll] : 0u;
                dh[i] = (unsigned short)v;
                dl[i] = (unsigned short)(v >> 16);
                if (++t == 3) { t = 0; ++ic; }
            }
        }
        __syncthreads();
#pragma unroll
        for (int ks = 0; ks < 4; ks++) {
            int k0 = ks * 16;
            uint32_t ahi[2][4], alo[2][4], bhi[4][2], blo[4][2];
#pragma unroll
            for (int mi = 0; mi < 2; mi++) {
                int r0 = warp_m * 32 + mi * 16 + g;
                const unsigned short* p0 = &sm[OFF_AHI + r0 * CPITCH + k0 + tg * 2];
                const unsigned short* p1 = p0 + 8 * CPITCH;
                ahi[mi][0] = *(const uint32_t*)p0;
                ahi[mi][1] = *(const uint32_t*)p1;
                ahi[mi][2] = *(const uint32_t*)(p0 + 8);
                ahi[mi][3] = *(const uint32_t*)(p1 + 8);
                const unsigned short* q0 = &sm[OFF_ALO + r0 * CPITCH + k0 + tg * 2];
                const unsigned short* q1 = q0 + 8 * CPITCH;
                alo[mi][0] = *(const uint32_t*)q0;
                alo[mi][1] = *(const uint32_t*)q1;
                alo[mi][2] = *(const uint32_t*)(q0 + 8);
                alo[mi][3] = *(const uint32_t*)(q1 + 8);
            }
#pragma unroll
            for (int ni = 0; ni < 4; ni++) {
                int nr = warp_n * 32 + ni * 8 + g;
                const unsigned short* p = &sm[OFF_BHI + nr * CPITCH + k0 + tg * 2];
                bhi[ni][0] = *(const uint32_t*)p;
                bhi[ni][1] = *(const uint32_t*)(p + 8);
                const unsigned short* q = &sm[OFF_BLO + nr * CPITCH + k0 + tg * 2];
                blo[ni][0] = *(const uint32_t*)q;
                blo[ni][1] = *(const uint32_t*)(q + 8);
            }
#pragma unroll
            for (int mi = 0; mi < 2; mi++)
#pragma unroll
                for (int ni = 0; ni < 4; ni++) {
                    mma16816(acc[mi][ni], ahi[mi], bhi[ni]);
                    mma16816(acc[mi][ni], ahi[mi], blo[ni]);
                    mma16816(acc[mi][ni], alo[mi], bhi[ni]);
                }
        }
        __syncthreads();
    }

#pragma unroll
    for (int mi = 0; mi < 2; mi++) {
        int m = m0 + warp_m * 32 + mi * 16 + g;
        float bs0 = bias[m], bs1 = bias[m + 8];
        size_t row0 = (((size_t)bI * M + m) << 9) + l0;
        size_t row1 = (((size_t)bI * M + m + 8) << 9) + l0;
#pragma unroll
        for (int ni = 0; ni < 4; ni++) {
            int ncol = warp_n * 32 + ni * 8 + tg * 2;
            float2 v0 = make_float2(acc[mi][ni][0] + bs0, acc[mi][ni][1] + bs0);
            float2 v1 = make_float2(acc[mi][ni][2] + bs1, acc[mi][ni][3] + bs1);
            if (res) {
                float2 r0 = *(const float2*)&res[row0 + ncol];
                float2 r1 = *(const float2*)&res[row1 + ncol];
                v0.x += r0.x; v0.y += r0.y; v1.x += r1.x; v1.y += r1.y;
            }
            *(float2*)&Y[row0 + ncol] = v0;
            *(float2*)&Y[row1 + ncol] = v1;
        }
    }
}

// ================= generic tensor-core GEMM: A packed, B hi/lo =================
template<int CM, int NT>
__global__ void __launch_bounds__(256, 2)
gemm_mma(const uint32_t* __restrict__ Apk,
         const unsigned short* __restrict__ Bthi, const unsigned short* __restrict__ Btlo,
         const float* __restrict__ bias, float* __restrict__ C, int M, int N, int K) {
    extern __shared__ unsigned short sm[];
    int tid = threadIdx.x;
    int wid = tid >> 5, lane = tid & 31;
    int g = lane >> 2, tg = lane & 3;
    int warp_m = wid & 1, warp_n = wid >> 1;
    int n0 = blockIdx.x * 128, m0 = blockIdx.y * 64;

    const uint32_t* Ap = Apk + (size_t)m0 * K;
    const unsigned short* Bh = Bthi + (size_t)n0 * K;
    const unsigned short* Bl = Btlo + (size_t)n0 * K;

    float acc[2][4][4];
#pragma unroll
    for (int mi = 0; mi < 2; mi++)
#pragma unroll
        for (int ni = 0; ni < 4; ni++)
#pragma unroll
            for (int r = 0; r < 4; r++) acc[mi][ni][r] = 0.f;

    int fa_m = tid >> 2, fa_k = (tid & 3) * 16;
    int fb_n = tid >> 1, fb_h = (tid & 1) * 32;
    int nchunks = K >> 6;

    for (int c = 0; c < nchunks; c++) {
        int c64 = c << 6;
        {
            const uint32_t* pa = Ap + (size_t)fa_m * K + c64 + fa_k;
            uint4 p0 = *(const uint4*)pa;
            uint4 p1 = *(const uint4*)(pa + 4);
            uint4 p2 = *(const uint4*)(pa + 8);
            uint4 p3 = *(const uint4*)(pa + 12);
            uint4 h0, h1, l0v, l1v;
            h0.x = __byte_perm(p0.x, p0.y, 0x5410); h0.y = __byte_perm(p0.z, p0.w, 0x5410);
            h0.z = __byte_perm(p1.x, p1.y, 0x5410); h0.w = __byte_perm(p1.z, p1.w, 0x5410);
            h1.x = __byte_perm(p2.x, p2.y, 0x5410); h1.y = __byte_perm(p2.z, p2.w, 0x5410);
            h1.z = __byte_perm(p3.x, p3.y, 0x5410); h1.w = __byte_perm(p3.z, p3.w, 0x5410);
            l0v.x = __byte_perm(p0.x, p0.y, 0x7632); l0v.y = __byte_perm(p0.z, p0.w, 0x7632);
            l0v.z = __byte_perm(p1.x, p1.y, 0x7632); l0v.w = __byte_perm(p1.z, p1.w, 0x7632);
            l1v.x = __byte_perm(p2.x, p2.y, 0x7632); l1v.y = __byte_perm(p2.z, p2.w, 0x7632);
            l1v.z = __byte_perm(p3.x, p3.y, 0x7632); l1v.w = __byte_perm(p3.z, p3.w, 0x7632);
            *(uint4*)&sm[OFF_AHI + fa_m * CPITCH + fa_k]     = h0;
            *(uint4*)&sm[OFF_AHI + fa_m * CPITCH + fa_k + 8] = h1;
            *(uint4*)&sm[OFF_ALO + fa_m * CPITCH + fa_k]     = l0v;
            *(uint4*)&sm[OFF_ALO + fa_m * CPITCH + fa_k + 8] = l1v;
        }
        {
            const unsigned short* ph = Bh + (size_t)fb_n * K + c64 + fb_h;
            const unsigned short* pl = Bl + (size_t)fb_n * K + c64 + fb_h;
            unsigned short* dh = &sm[OFF_BHI + fb_n * CPITCH + fb_h];
            unsigned short* dl = &sm[OFF_BLO + fb_n * CPITCH + fb_h];
#pragma unroll
            for (int i = 0; i < 4; i++) {
                *(uint4*)(dh + i * 8) = *(const uint4*)(ph + i * 8);
                *(uint4*)(dl + i * 8) = *(const uint4*)(pl + i * 8);
            }
        }
        __syncthreads();
#pragma unroll
        for (int ks = 0; ks < 4; ks++) {
            int k0 = ks * 16;
            uint32_t ahi[2][4], alo[2][4], bhi[4][2], blo[4][2];
#pragma unroll
            for (int mi = 0; mi < 2; mi++) {
                int r0 = warp_m * 32 + mi * 16 + g;
                const unsigned short* p0 = &sm[OFF_AHI + r0 * CPITCH + k0 + tg * 2];
                const unsigned short* p1 = p0 + 8 * CPITCH;
                ahi[mi][0] = *(const uint32_t*)p0;
                ahi[mi][1] = *(const uint32_t*)p1;
                ahi[mi][2] = *(const uint32_t*)(p0 + 8);
                ahi[mi][3] = *(const uint32_t*)(p1 + 8);
                const unsigned short* q0 = &sm[OFF_ALO + r0 * CPITCH + k0 + tg * 2];
                const unsigned short* q1 = q0 + 8 * CPITCH;
                alo[mi][0] = *(const uint32_t*)q0;
                alo[mi][1] = *(const uint32_t*)q1;
                alo[mi][2] = *(const uint32_t*)(q0 + 8);
                alo[mi][3] = *(const uint32_t*)(q1 + 8);
            }
#pragma unroll
            for (int ni = 0; ni < 4; ni++) {
                int nr = warp_n * 32 + ni * 8 + g;
                const unsigned short* p = &sm[OFF_BHI + nr * CPITCH + k0 + tg * 2];
                bhi[ni][0] = *(const uint32_t*)p;
                bhi[ni][1] = *(const uint32_t*)(p + 8);
                const unsigned short* q = &sm[OFF_BLO + nr * CPITCH + k0 + tg * 2];
                blo[ni][0] = *(const uint32_t*)q;
                blo[ni][1] = *(const uint32_t*)(q + 8);
            }
#pragma unroll
            for (int mi = 0; mi < 2; mi++)
#pragma unroll
                for (int ni = 0; ni < 4; ni++) {
                    mma16816(acc[mi][ni], ahi[mi], bhi[ni]);
                    mma16816(acc[mi][ni], ahi[mi], blo[ni]);
                    mma16816(acc[mi][ni], alo[mi], bhi[ni]);
                    if (NT == 4) mma16816(acc[mi][ni], alo[mi], blo[ni]);
                }
        }
        __syncthreads();
    }

    if (CM == 0) {
#pragma unroll
        for (int mi = 0; mi < 2; mi++) {
            int m = m0 + warp_m * 32 + mi * 16 + g;
#pragma unroll
            for (int ni = 0; ni < 4; ni++) {
                int n = n0 + warp_n * 32 + ni * 8 + tg * 2;
                float b0 = bias ? bias[n] : 0.f;
                float b1 = bias ? bias[n + 1] : 0.f;
                *(float2*)&C[(size_t)m * N + n] =
                    make_float2(acc[mi][ni][0] + b0, acc[mi][ni][1] + b1);
                *(float2*)&C[(size_t)(m + 8) * N + n] =
                    make_float2(acc[mi][ni][2] + b0, acc[mi][ni][3] + b1);
            }
        }
    } else {  // CTRANS
#pragma unroll
        for (int mi = 0; mi < 2; mi++) {
            int m = m0 + warp_m * 32 + mi * 16 + g;
            int bI = m >> 9, l = m & 511;
#pragma unroll
            for (int ni = 0; ni < 4; ni++) {
                int n = n0 + warp_n * 32 + ni * 8 + tg * 2;
                float b0 = bias ? bias[n] : 0.f;
                float b1 = bias ? bias[n + 1] : 0.f;
                C[(((size_t)(bI * N + n)) << 9) + l]           = acc[mi][ni][0] + b0;
                C[(((size_t)(bI * N + n + 1)) << 9) + l]       = acc[mi][ni][1] + b1;
                C[(((size_t)(bI * N + n)) << 9) + l + 8]       = acc[mi][ni][2] + b0;
                C[(((size_t)(bI * N + n + 1)) << 9) + l + 8]   = acc[mi][ni][3] + b1;
            }
        }
    }
}

// ---------------- GroupNorm + GELU: register-resident, shuffle reductions ----------------
__global__ void gn_gelu_kernel(const float* __restrict__ xin, const float* __restrict__ emb,
                               const float* __restrict__ scale, const float* __restrict__ bias,
                               float* __restrict__ x1_out, uint32_t* __restrict__ hpk) {
    int b = blockIdx.x >> 5;
    int g = blockIdx.x & 31;
    size_t base = ((size_t)b * CC + g * CPG) * LL;
    int tid = threadIdx.x;       // 512
    float v[8];
    float s = 0.f, s2 = 0.f;
#pragma unroll
    for (int i = 0; i < 8; i++) {
        int j = tid + i * 512;
        float t = xin[base + j];
        if (emb) t += emb[base + j];
        v[i] = t;
        s += t;
        s2 = fmaf(t, t, s2);
    }
#pragma unroll
    for (int o = 16; o > 0; o >>= 1) {
        s  += __shfl_xor_sync(0xffffffff, s, o);
        s2 += __shfl_xor_sync(0xffffffff, s2, o);
    }
    __shared__ float ws[16], ws2[16], stats[2];
    int wid = tid >> 5, lane = tid & 31;
    if (lane == 0) { ws[wid] = s; ws2[wid] = s2; }
    __syncthreads();
    if (tid < 32) {
        float a  = (tid < 16) ? ws[tid]  : 0.f;
        float a2 = (tid < 16) ? ws2[tid] : 0.f;
#pragma unroll
        for (int o = 8; o > 0; o >>= 1) {
            a  += __shfl_xor_sync(0xffffffff, a, o);
            a2 += __shfl_xor_sync(0xffffffff, a2, o);
        }
        if (tid == 0) { stats[0] = a; stats[1] = a2; }
    }
    __syncthreads();
    float mean = stats[0] * (1.f / 4096.f);
    float var = stats[1] * (1.f / 4096.f) - mean * mean;
    float rsig = rsqrtf(var + 1e-5f);
#pragma unroll
    for (int i = 0; i < 8; i++) {
        int j = tid + i * 512;
        int c = g * CPG + (j >> 9);
        float t = v[i];
        if (x1_out) x1_out[base + j] = t;
        float nn = (t - mean) * rsig * scale[c] + bias[c];
        hpk[base + j] = pack_bf16(gelu_exact(nn));
    }
}

// ---------------- qkv split -> packed bf16 hi/lo ----------------
__global__ void qkv_split_kernel(const float* __restrict__ t, uint32_t* __restrict__ Q,
                                 uint32_t* __restrict__ K, uint32_t* __restrict__ V) {
    int idx = blockIdx.x * 256 + threadIdx.x;
    int d = idx & 31;
    int l = (idx >> 5) & 511;
    int h = (idx >> 14) & 7;
    int b = idx >> 17;
    size_t base = ((size_t)(b * LL + l)) * 768 + (size_t)(d * NH + h) * 3;
    int o = ((b * NH + h) * LL + l) * DH + d;
    Q[o] = pack_bf16(t[base]);
    K[o] = pack_bf16(t[base + 1]);
    V[o] = pack_bf16(t[base + 2]);
}

// ---------------- flash attention on HMMA (bf16 hi/lo 3-term) ----------------
#define AQP 40     // Q/K smem pitch (ushorts)
#define AVP 66     // V^T smem pitch
#define APP 72     // P smem pitch
#define A_OQH 0
#define A_OQL (A_OQH + 64*AQP)
#define A_OKH (A_OQL + 64*AQP)
#define A_OKL (A_OKH + 64*AQP)
#define A_OVH (A_OKL + 64*AQP)
#define A_OVL (A_OVH + 32*AVP)
#define A_OPH (A_OVL + 32*AVP)
#define A_OPL (A_OPH + 64*APP)
#define A_USTOT (A_OPL + 64*APP)                 // ushorts
#define ATTN_SMEM (A_USTOT*2 + 64*APP*4 + 3*64*4)

__global__ void __launch_bounds__(256, 2)
fused_attn_kernel(const uint32_t* __restrict__ Qp, const uint32_t* __restrict__ Kp,
                  const uint32_t* __restrict__ Vp, uint32_t* __restrict__ Opk) {
    extern __shared__ unsigned short sma[];
    float* Psf = (float*)(sma + A_USTOT);
    float* rowm = Psf + 64 * APP;
    float* rowl = rowm + 64;
    float* rowscale = rowl + 64;

    int bh = blockIdx.y;
    int q0 = blockIdx.x * 64;
    int b = bh >> 3, h = bh & 7;
    int tid = threadIdx.x;
    int wid = tid >> 5, lane = tid & 31;
    int g = lane >> 2, tg = lane & 3;
    int warp_m = wid & 1, warp_n = wid >> 1;
    const float sc = 0.17677669529663687f;

#pragma unroll
    for (int i = 0; i < 8; i++) {
        int idx = tid + i * 256;
        int r = idx >> 5, d = idx & 31;
        uint32_t v = Qp[((size_t)(bh << 9) + q0 + r) * 32 + d];
        sma[A_OQH + r * AQP + d] = (unsigned short)v;
        sma[A_OQL + r * AQP + d] = (unsigned short)(v >> 16);
    }
    if (tid < 64) { rowm[tid] = -3.4e38f; rowl[tid] = 0.f; }

    float acc_o[2][4];
#pragma unroll
    for (int mi = 0; mi < 2; mi++)
#pragma unroll
        for (int r = 0; r < 4; r++) acc_o[mi][r] = 0.f;

    for (int k0g = 0; k0g < 512; k0g += 64) {
        __syncthreads();
#pragma unroll
        for (int i = 0; i < 8; i++) {
            int idx = tid + i * 256;
            int r = idx >> 5, d = idx & 31;
            size_t gsrc = ((size_t)(bh << 9) + k0g + r) * 32 + d;
            uint32_t kv = Kp[gsrc];
            sma[A_OKH + r * AQP + d] = (unsigned short)kv;
            sma[A_OKL + r * AQP + d] = (unsigned short)(kv >> 16);
            uint32_t vv = Vp[gsrc];
            sma[A_OVH + d * AVP + r] = (unsigned short)vv;
            sma[A_OVL + d * AVP + r] = (unsigned short)(vv >> 16);
        }
        __syncthreads();
        {
            float sacc[2][2][4];
#pragma unroll
            for (int mi = 0; mi < 2; mi++)
#pragma unroll
                for (int ni = 0; ni < 2; ni++)
#pragma unroll
                    for (int r = 0; r < 4; r++) sacc[mi][ni][r] = 0.f;
#pragma unroll
            for (int ks = 0; ks < 2; ks++) {
                int k0 = ks * 16;
                uint32_t ahi[2][4], alo[2][4], bhi[2][2], blo[2][2];
#pragma unroll
                for (int mi = 0; mi < 2; mi++) {
                    int r0 = warp_m * 32 + mi * 16 + g;
                    const unsigned short* p0 = &sma[A_OQH + r0 * AQP + k0 + tg * 2];
                    const unsigned short* p1 = p0 + 8 * AQP;
                    ahi[mi][0] = *(const uint32_t*)p0;
                    ahi[mi][1] = *(const uint32_t*)p1;
                    ahi[mi][2] = *(const uint32_t*)(p0 + 8);
                    ahi[mi][3] = *(const uint32_t*)(p1 + 8);
                    const unsigned short* q0p = &sma[A_OQL + r0 * AQP + k0 + tg * 2];
                    const unsigned short* q1p = q0p + 8 * AQP;
                    alo[mi][0] = *(const uint32_t*)q0p;
                    alo[mi][1] = *(const uint32_t*)q1p;
                    alo[mi][2] = *(const uint32_t*)(q0p + 8);
                    alo[mi][3] = *(const uint32_t*)(q1p + 8);
                }
#pragma unroll
                for (int ni = 0; ni < 2; ni++) {
                    int nr = warp_n * 16 + ni * 8 + g;
                    const unsigned short* p = &sma[A_OKH + nr * AQP + k0 + tg * 2];
                    bhi[ni][0] = *(const uint32_t*)p;
                    bhi[ni][1] = *(const uint32_t*)(p + 8);
                    const unsigned short* q = &sma[A_OKL + nr * AQP + k0 + tg * 2];
                    blo[ni][0] = *(const uint32_t*)q;
                    blo[ni][1] = *(const uint32_t*)(q + 8);
                }
#pragma unroll
                for (int mi = 0; mi < 2; mi++)
#pragma unroll
                    for (int ni = 0; ni < 2; ni++) {
                        mma16816(sacc[mi][ni], ahi[mi], bhi[ni]);
                        mma16816(sacc[mi][ni], ahi[mi], blo[ni]);
                        mma16816(sacc[mi][ni], alo[mi], bhi[ni]);
                    }
            }
#pragma unroll
            for (int mi = 0; mi < 2; mi++) {
                int r0 = warp_m * 32 + mi * 16 + g;
#pragma unroll
                for (int ni = 0; ni < 2; ni++) {
                    int col = warp_n * 16 + ni * 8 + tg * 2;
                    Psf[r0 * APP + col]           = sacc[mi][ni][0] * sc;
                    Psf[r0 * APP + col + 1]       = sacc[mi][ni][1] * sc;
                    Psf[(r0 + 8) * APP + col]     = sacc[mi][ni][2] * sc;
                    Psf[(r0 + 8) * APP + col + 1] = sacc[mi][ni][3] * sc;
                }
            }
        }
        __syncthreads();
        {
            int r = tid >> 2, sub = tid & 3;
            float mloc = -3.4e38f;
#pragma unroll
            for (int c = 0; c < 16; c++) mloc = fmaxf(mloc, Psf[r * APP + sub * 16 + c]);
            mloc = fmaxf(mloc, __shfl_xor_sync(0xffffffff, mloc, 1));
            mloc = fmaxf(mloc, __shfl_xor_sync(0xffffffff, mloc, 2));
            float mold = rowm[r];
            float mnew = fmaxf(mold, mloc);
            float ssum = 0.f;
#pragma unroll
            for (int c = 0; c < 16; c++) {
                int col = sub * 16 + c;
                float e = expf(Psf[r * APP + col] - mnew);
                unsigned short hu, lu;
                split_bf16(e, hu, lu);
                sma[A_OPH + r * APP + col] = hu;
                sma[A_OPL + r * APP + col] = lu;
                ssum += e;
            }
            ssum += __shfl_xor_sync(0xffffffff, ssum, 1);
            ssum += __shfl_xor_sync(0xffffffff, ssum, 2);
            if (sub == 0) {
                float scl = expf(mold - mnew);
                rowscale[r] = scl;
                rowl[r] = rowl[r] * scl + ssum;
                rowm[r] = mnew;
            }
        }
        __syncthreads();
        {
#pragma unroll
            for (int mi = 0; mi < 2; mi++) {
                int r0 = warp_m * 32 + mi * 16 + g;
                float s0 = rowscale[r0], s1 = rowscale[r0 + 8];
                acc_o[mi][0] *= s0; acc_o[mi][1] *= s0;
                acc_o[mi][2] *= s1; acc_o[mi][3] *= s1;
            }
#pragma unroll
            for (int ks = 0; ks < 4; ks++) {
                int k0 = ks * 16;
                uint32_t ahi[2][4], alo[2][4], bhi[2], blo[2];
#pragma unroll
                for (int mi = 0; mi < 2; mi++) {
                    int r0 = warp_m * 32 + mi * 16 + g;
                    const unsigned short* p0 = &sma[A_OPH + r0 * APP + k0 + tg * 2];
                    const unsigned short* p1 = p0 + 8 * APP;
                    ahi[mi][0] = *(const uint32_t*)p0;
                    ahi[mi][1] = *(const uint32_t*)p1;
                    ahi[mi][2] = *(const uint32_t*)(p0 + 8);
                    ahi[mi][3] = *(const uint32_t*)(p1 + 8);
                    const unsigned short* q0p = &sma[A_OPL + r0 * APP + k0 + tg * 2];
                    const unsigned short* q1p = q0p + 8 * APP;
                    alo[mi][0] = *(const uint32_t*)q0p;
                    alo[mi][1] = *(const uint32_t*)q1p;
                    alo[mi][2] = *(const uint32_t*)(q0p + 8);
                    alo[mi][3] = *(const uint32_t*)(q1p + 8);
                }
                {
                    int nr = warp_n * 8 + g;
                    const unsigned short* p = &sma[A_OVH + nr * AVP + k0 + tg * 2];
                    bhi[0] = *(const uint32_t*)p;
                    bhi[1] = *(const uint32_t*)(p + 8);
                    const unsigned short* q = &sma[A_OVL + nr * AVP + k0 + tg * 2];
                    blo[0] = *(const uint32_t*)q;
                    blo[1] = *(const uint32_t*)(q + 8);
                }
#pragma unroll
                for (int mi = 0; mi < 2; mi++) {
                    mma16816(acc_o[mi], ahi[mi], bhi);
                    mma16816(acc_o[mi], ahi[mi], blo);
                    mma16816(acc_o[mi], alo[mi], bhi);
                }
            }
        }
    }
#pragma unroll
    for (int mi = 0; mi < 2; mi++) {
        int r0 = warp_m * 32 + mi * 16 + g;
        float inv0 = 1.f / rowl[r0], inv1 = 1.f / rowl[r0 + 8];
        int d0 = warp_n * 8 + tg * 2;
        int q_0 = q0 + r0, q_1 = q0 + r0 + 8;
        size_t a00 = ((size_t)(b << 9) + q_0) * 256 + d0 * NH + h;
        size_t a10 = ((size_t)(b << 9) + q_1) * 256 + d0 * NH + h;
        Opk[a00]          = pack_bf16(acc_o[mi][0] * inv0);
        Opk[a00 + NH]     = pack_bf16(acc_o[mi][1] * inv0);
        Opk[a10]          = pack_bf16(acc_o[mi][2] * inv1);
        Opk[a10 + NH]     = pack_bf16(acc_o[mi][3] * inv1);
    }
}

// ---------------- MoE gating: warp-per-row ----------------
__global__ void gating_kernel(const float* __restrict__ logits, float* __restrict__ raw,
                              float* __restrict__ g1, int* __restrict__ i1,
                              float* __restrict__ g2, int* __restrict__ i2) {
    int warp = (blockIdx.x << 3) + (threadIdx.x >> 5);
    int lane = threadIdx.x & 31;
    const float* p = logits + (size_t)warp * EE;
    float lv[32];
#pragma unroll
    for (int i = 0; i < 32; i++) lv[i] = p[i * 32 + lane];

    float bv = lv[0]; int bi = lane;
#pragma unroll
    for (int i = 1; i < 32; i++)
        if (lv[i] > bv) { bv = lv[i]; bi = i * 32 + lane; }
#pragma unroll
    for (int o = 16; o > 0; o >>= 1) {
        float ov = __shfl_xor_sync(0xffffffff, bv, o);
        int oi = __shfl_xor_sync(0xffffffff, bi, o);
        if (ov > bv || (ov == bv && oi < bi)) { bv = ov; bi = oi; }
    }
    float maxv = bv; int maxi = bi;

    float s = 0.f;
#pragma unroll
    for (int i = 0; i < 32; i++) s += expf(lv[i] - maxv);
#pragma unroll
    for (int o = 16; o > 0; o >>= 1) s += __shfl_xor_sync(0xffffffff, s, o);
    float inv = 1.f / s;
    float* rp = raw + (size_t)warp * EE;
#pragma unroll
    for (int i = 0; i < 32; i++) rp[i * 32 + lane] = expf(lv[i] - maxv) * inv;

    float b2 = -3.4e38f; int b2i = 0;
#pragma unroll
    for (int i = 0; i < 32; i++) {
        int e = i * 32 + lane;
        if (e != maxi && lv[i] > b2) { b2 = lv[i]; b2i = e; }
    }
#pragma unroll
    for (int o = 16; o > 0; o >>= 1) {
        float ov = __shfl_xor_sync(0xffffffff, b2, o);
        int oi = __shfl_xor_sync(0xffffffff, b2i, o);
        if (ov > b2 || (ov == b2 && oi < b2i)) { b2 = ov; b2i = oi; }
    }

    if (lane == 0) {
        float gate1v = inv;
        float gate2v = expf(b2 - maxv) * inv;
        float denom = gate1v + gate2v + 1e-9f;
        g1[warp] = gate1v / denom;
        i1[warp] = maxi;
        g2[warp] = gate2v / denom;
        i2[warp] = b2i;
    }
}

// ---------------- per-(b,e) sum of raw over tokens ----------------
__global__ void rawsum_kernel(const float* __restrict__ raw, float* __restrict__ rawsum) {
    int b = blockIdx.x >> 2;
    int chunk = blockIdx.x & 3;
    int e = chunk * 256 + threadIdx.x;
    const float* p = raw + (size_t)b * NTOK * EE + e;
    float s = 0.f;
    for (int n = 0; n < NTOK; n++) s += p[(size_t)n * EE];
    rawsum[b * EE + e] = s;
}

// ---------------- routing with capacity ----------------
__global__ void routing_kernel(const int* __restrict__ idx1, const float* __restrict__ gate1,
                               const int* __restrict__ idx2, const float* __restrict__ gate2,
                               int* __restrict__ slot_tok, float* __restrict__ slot_gate,
                               float* __restrict__ cnt1_out) {
    int b = blockIdx.x;
    int tid = threadIdx.x;
    __shared__ int cnt[EE];
    __shared__ int mcnt[EE];
    for (int e = tid; e < EE; e += 256) cnt[e] = 0;
    for (int i = tid; i < EE * CAPP; i += 256) {
        slot_tok[b * EE * CAPP + i] = -1;
        slot_gate[b * EE * CAPP + i] = 0.f;
    }
    __syncthreads();
    if (tid == 0) {
        for (int n = 0; n < NTOK; n++) {
            int e = idx1[b * NTOK + n];
            int pcur = cnt[e]++;
            if (pcur < CAPP) {
                slot_tok[(b * EE + e) * CAPP + pcur] = n;
                slot_gate[(b * EE + e) * CAPP + pcur] = gate1[b * NTOK + n];
            }
        }
    }
    __syncthreads();
    for (int e = tid; e < EE; e += 256) {
        cnt1_out[b * EE + e] = (float)cnt[e];
        mcnt[e] = cnt[e] < CAPP ? cnt[e] : CAPP;
        cnt[e] = 0;
    }
    __syncthreads();
    if (tid == 0) {
        for (int n = 0; n < NTOK; n++) {
            int e = idx2[b * NTOK + n];
            int pcur = mcnt[e] + cnt[e];
            cnt[e]++;
            if (pcur < CAPP) {
                slot_tok[(b * EE + e) * CAPP + pcur] = n;
                slot_gate[(b * EE + e) * CAPP + pcur] = gate2[b * NTOK + n];
            }
        }
    }
}

// ---------------- expert FFN (float4 weight staging) ----------------
__global__ void expert_kernel(const float* __restrict__ xm, const float* __restrict__ w1,
                              const float* __restrict__ w2,
                              const int* __restrict__ slot_tok, const float* __restrict__ slot_gate,
                              float* __restrict__ out) {
    int e = blockIdx.x;
    int tid = threadIdx.x;
    extern __shared__ float sw[];
    __shared__ float hsh[32][33];
    __shared__ int stok[32];
    __shared__ float sgate[32];
    __shared__ int s_any;
    if (tid < 32) {
        int b = tid >> 2, c = tid & 3;
        stok[tid]  = slot_tok [(b * EE + e) * CAPP + c];
        sgate[tid] = slot_gate[(b * EE + e) * CAPP + c];
    }
    if (tid == 0) s_any = 0;
    __syncthreads();
    if (tid == 0) {
        int a = 0;
        for (int i = 0; i < 32; i++) a |= (stok[i] >= 0);
        s_any = a;
    }
    __syncthreads();
    if (!s_any) return;
    {
        const float4* w1v = (const float4*)(w1 + (size_t)e * DTOK * HIDD);
        float4* swv = (float4*)sw;
#pragma unroll
        for (int i = 0; i < 16; i++) swv[tid + i * 256] = w1v[tid + i * 256];
    }
    __syncthreads();
    int hid = tid & 31;
#pragma unroll
    for (int pass = 0; pass < 4; pass++) {
        int sidx = pass * 8 + (tid >> 5);
        int tok = stok[sidx];
        float acc = 0.f;
        if (tok >= 0) {
            const float* xr = xm + ((size_t)((sidx >> 2) * NTOK + tok)) * DTOK;
            for (int dd = 0; dd < DTOK; dd++) acc = fmaf(xr[dd], sw[dd * HIDD + hid], acc);
        }
        hsh[sidx][hid] = gelu_exact(acc);
    }
    __syncthreads();
    {
        const float4* w2v = (const float4*)(w2 + (size_t)e * HIDD * DTOK);
        float4* swv = (float4*)sw;
#pragma unroll
        for (int i = 0; i < 16; i++) swv[tid + i * 256] = w2v[tid + i * 256];
    }
    __syncthreads();
#pragma unroll
    for (int i = 0; i < 64; i++) {
        int idx = tid + i * 256;
        int sidx = idx >> 9;
        int dd = idx & 511;
        int tok = stok[sidx];
        float g = sgate[sidx];
        if (tok >= 0 && g != 0.f) {
            float acc = 0.f;
#pragma unroll
            for (int h2 = 0; h2 < HIDD; h2++) acc = fmaf(hsh[sidx][h2], sw[h2 * DTOK + dd], acc);
            atomicAdd(&out[((size_t)((sidx >> 2) * NTOK + tok)) * DTOK + dd], g * acc);
        }
    }
}

// ---------------- aux loss ----------------
__global__ void loss_kernel(const float* __restrict__ rawsum, const float* __restrict__ cnt1,
                            float* __restrict__ out_scalar) {
    __shared__ float red[256];
    int tid = threadIdx.x;
    float s = 0.f;
    for (int i = tid; i < BB * EE; i += 256) s += rawsum[i] * cnt1[i];
    red[tid] = s; __syncthreads();
    for (int o = 128; o > 0; o >>= 1) { if (tid < o) red[tid] += red[tid + o]; __syncthreads(); }
    if (tid == 0) out_scalar[0] = red[0] * 1.953125e-05f;
}

// ---------------- maxpool k=3 s=2 pad=1 ----------------
__global__ void maxpool_kernel(const float* __restrict__ yf, float* __restrict__ out) {
    int idx = blockIdx.x * 256 + threadIdx.x;
    int j = idx & 255;
    int o = (idx >> 8) & 511;
    int b = idx >> 17;
    const float* row = yf + ((size_t)(b * 512 + o)) * 512;
    int l = 2 * j;
    float m = row[l];
    if (l > 0) m = fmaxf(m, row[l - 1]);
    m = fmaxf(m, row[l + 1]);
    out[idx] = m;
}

// ---------------- host orchestration ----------------
extern "C" void kernel_launch(void* const* d_in, const int* in_sizes, int n_in,
                              void* d_out, int out_size) {
    const float* x        = (const float*)d_in[0];
    const float* emb      = (const float*)d_in[1];
    const float* rb1_g1s  = (const float*)d_in[2];
    const float* rb1_g1b  = (const float*)d_in[3];
    const float* rb1_c1w  = (const float*)d_in[4];
    const float* rb1_c1b  = (const float*)d_in[5];
    const float* rb1_g2s  = (const float*)d_in[6];
    const float* rb1_g2b  = (const float*)d_in[7];
    const float* rb1_c2w  = (const float*)d_in[8];
    const float* rb1_c2b  = (const float*)d_in[9];
    const float* rb2_g1s  = (const float*)d_in[10];
    const float* rb2_g1b  = (const float*)d_in[11];
    const float* rb2_c1w  = (const float*)d_in[12];
    const float* rb2_c1b  = (const float*)d_in[13];
    const float* rb2_g2s  = (const float*)d_in[14];
    const float* rb2_g2b  = (const float*)d_in[15];
    const float* rb2_c2w  = (const float*)d_in[16];
    const float* rb2_c2b  = (const float*)d_in[17];
    const float* attn_w1  = (const float*)d_in[18];
    const float* attn_b1  = (const float*)d_in[19];
    const float* attn_w2  = (const float*)d_in[20];
    const float* attn_b2  = (const float*)d_in[21];
    const float* moe_wg   = (const float*)d_in[22];
    const float* moe_w1   = (const float*)d_in[23];
    const float* moe_w2   = (const float*)d_in[24];
    const float* out_w    = (const float*)d_in[25];
    const float* out_b    = (const float*)d_in[26];
    float* out = (float*)d_out;

    float *px1, *pr, *pxa, *pt, *pxb, *pxm;
    float *plog, *praw, *pg1, *pg2, *prs, *pc1, *psg, *pmo, *pyf;
    int *pi1, *pi2, *pst;
    unsigned short *pwhi, *pwlo;
    uint32_t *phpk, *pqp, *pkp, *pvp;
    cudaGetSymbolAddress((void**)&px1, g_x1);
    cudaGetSymbolAddress((void**)&pr,  g_r);
    cudaGetSymbolAddress((void**)&pxa, g_xa);
    cudaGetSymbolAddress((void**)&pt,  g_t);
    cudaGetSymbolAddress((void**)&pqp, g_qp);
    cudaGetSymbolAddress((void**)&pkp, g_kp);
    cudaGetSymbolAddress((void**)&pvp, g_vp);
    cudaGetSymbolAddress((void**)&pxb, g_xb);
    cudaGetSymbolAddress((void**)&pxm, g_xm);
    cudaGetSymbolAddress((void**)&plog, g_logits);
    cudaGetSymbolAddress((void**)&praw, g_raw);
    cudaGetSymbolAddress((void**)&pg1, g_gate1);
    cudaGetSymbolAddress((void**)&pg2, g_gate2);
    cudaGetSymbolAddress((void**)&pi1, g_i1);
    cudaGetSymbolAddress((void**)&pi2, g_i2);
    cudaGetSymbolAddress((void**)&prs, g_rawsum);
    cudaGetSymbolAddress((void**)&pc1, g_cnt1);
    cudaGetSymbolAddress((void**)&pst, g_slot_tok);
    cudaGetSymbolAddress((void**)&psg, g_slot_gate);
    cudaGetSymbolAddress((void**)&pmo, g_moeout);
    cudaGetSymbolAddress((void**)&pyf, g_yfull);
    cudaGetSymbolAddress((void**)&pwhi, g_whi);
    cudaGetSymbolAddress((void**)&pwlo, g_wlo);
    cudaGetSymbolAddress((void**)&phpk, g_hpk);

    cudaFuncSetAttribute(expert_kernel, cudaFuncAttributeMaxDynamicSharedMemorySize, 65536);
    cudaFuncSetAttribute(conv_mma_kernel, cudaFuncAttributeMaxDynamicSharedMemorySize, MMA_SMEM);
    cudaFuncSetAttribute(gemm_mma<0,3>, cudaFuncAttributeMaxDynamicSharedMemorySize, MMA_SMEM);
    cudaFuncSetAttribute(gemm_mma<2,3>, cudaFuncAttributeMaxDynamicSharedMemorySize, MMA_SMEM);
    cudaFuncSetAttribute(gemm_mma<0,4>, cudaFuncAttributeMaxDynamicSharedMemorySize, MMA_SMEM);
    cudaFuncSetAttribute(fused_attn_kernel, cudaFuncAttributeMaxDynamicSharedMemorySize, ATTN_SMEM);

    const int WSZc = WSZ;
    // ---- ONE fused weight-conversion launch ----
    cvt_weights_kernel<<<5376, 256>>>(rb1_c1w, rb1_c2w, rb2_c1w, rb2_c2w, out_w,
                                      attn_w1, attn_w2, moe_wg, pwhi, pwlo);

    // ---- res block 1 ----
    gn_gelu_kernel<<<BB * NG, 512>>>(x, emb, rb1_g1s, rb1_g1b, px1, phpk);
    conv_mma_kernel<<<dim3(32, 4), 256, MMA_SMEM>>>(pwhi, pwlo, phpk, rb1_c1b, nullptr, pr, 256);
    gn_gelu_kernel<<<BB * NG, 512>>>(pr, nullptr, rb1_g2s, rb1_g2b, nullptr, phpk);
    conv_mma_kernel<<<dim3(32, 4), 256, MMA_SMEM>>>(pwhi + WSZc, pwlo + WSZc, phpk, rb1_c2b, px1, pxa, 256);

    // ---- attention (HMMA flash) ----
    cvtT_x_kernel<<<dim3(16, 8, 8), dim3(32, 8)>>>(pxa, phpk);
    gemm_mma<0,3><<<dim3(6, 64), 256, MMA_SMEM>>>(phpk, pwhi + OFF_WQKVT, pwlo + OFF_WQKVT,
                                                  attn_b1, pt, 4096, 768, 256);
    qkv_split_kernel<<<4096, 256>>>(pt, pqp, pkp, pvp);
    fused_attn_kernel<<<dim3(8, 64), 256, ATTN_SMEM>>>(pqp, pkp, pvp, phpk);
    gemm_mma<2,3><<<dim3(2, 64), 256, MMA_SMEM>>>(phpk, pwhi + OFF_W2T, pwlo + OFF_W2T,
                                                  attn_b2, pxb, 4096, 256, 256);

    // ---- res block 2 ----
    gn_gelu_kernel<<<BB * NG, 512>>>(pxb, emb, rb2_g1s, rb2_g1b, px1, phpk);
    conv_mma_kernel<<<dim3(32, 4), 256, MMA_SMEM>>>(pwhi + 2*WSZc, pwlo + 2*WSZc, phpk, rb2_c1b, nullptr, pr, 256);
    gn_gelu_kernel<<<BB * NG, 512>>>(pr, nullptr, rb2_g2s, rb2_g2b, nullptr, phpk);
    conv_mma_kernel<<<dim3(32, 4), 256, MMA_SMEM>>>(pwhi + 3*WSZc, pwlo + 3*WSZc, phpk, rb2_c2b, px1, pxm, 256);

    // ---- MoE ----
    cvt_pk_kernel<<<4096, 256>>>(pxm, phpk, BB * CC * LL);
    gemm_mma<0,4><<<dim3(8, 32), 256, MMA_SMEM>>>(phpk, pwhi + OFF_WGT, pwlo + OFF_WGT,
                                                  nullptr, plog, 2048, 1024, 512);
    gating_kernel<<<256, 256>>>(plog, praw, pg1, pi1, pg2, pi2);
    rawsum_kernel<<<32, 256>>>(praw, prs);
    routing_kernel<<<BB, 256>>>(pi1, pg1, pi2, pg2, pst, psg, pc1);
    cudaMemsetAsync(pmo, 0, sizeof(float) * BB * CC * LL);
    expert_kernel<<<EE, 256, 65536>>>(pxm, moe_w1, moe_w2, pst, psg, pmo);
    loss_kernel<<<1, 256>>>(prs, pc1, out + 2097152);

    // ---- output conv + maxpool ----
    cvt_pk_kernel<<<4096, 256>>>(pmo, phpk, BB * CC * LL);
    conv_mma_kernel<<<dim3(32, 8), 256, MMA_SMEM>>>(pwhi + 4*WSZc, pwlo + 4*WSZc, phpk, out_b, nullptr, pyf, 512);
    maxpool_kernel<<<4096, 256>>>(pyf, out);

    // second output: moe result x (B,C,L)
    cudaMemcpyAsync(out + 1048576, pmo, sizeof(float) * BB * CC * LL, cudaMemcpyDeviceToDevice);
}